// round 6
// baseline (speedup 1.0000x reference)
#include <cuda_runtime.h>
#include <cuda_bf16.h>
#include <math.h>
#include <stdint.h>

// Problem dims
#define Bb 2
#define Tt 1024
#define Cc 2048
#define Hh 16
#define DK 128
#define SC 1024
#define SS 2048
#define KDIM 2048
#define NMAT 4194304ull   // 2048*2048

#define RSQRT_DK 0.08838834764831845f

// HMMA GEMM tiling (128x128 CTA tile, 16 warps 4x4, warp tile 32x32, BK=32)
#define MM_BK 32
#define MM_LDS_B 80                       // bytes per smem row (32 bf16 + 16 pad)
#define MM_MAT_BYTES (128 * MM_LDS_B)     // 10240
#define MM_STAGE_BYTES (4 * MM_MAT_BYTES) // 40960
#define MM_SMEM (2 * MM_STAGE_BYTES)      // 81920
#define MM_KSTEPS (KDIM / MM_BK)          // 64
#define SC_KSTEPS (DK / MM_BK)            // 4

// PV tiling: A = P [128 x 32], B = V [32 x 128] (ldmatrix.trans)
#define PV_LDSV 272                       // 128 bf16 (256B) + 16 pad
#define PV_MATP MM_MAT_BYTES              // 10240
#define PV_MATV (32 * PV_LDSV)            // 8704
#define PV_STAGE (2 * PV_MATP + 2 * PV_MATV)  // 37888
#define PV_SMEM (2 * PV_STAGE)            // 75776

// ---------------------------------------------------------------------------
// Scratch (device globals)
// ---------------------------------------------------------------------------
__device__ float g_scores[(size_t)Bb * Hh * Tt * SC];     // [bh,t,s]
// bf16 hi/lo: 0=x, 1=Wq, 2=Wk, 3=Wv, 4=Wo, 5=cache_k, 6=cache_v
__device__ __nv_bfloat16 g_bh[7 * NMAT];
__device__ __nv_bfloat16 g_bl[7 * NMAT];
__device__ __nv_bfloat16 g_qh[NMAT];                      // Q [bh,t,d] scaled
__device__ __nv_bfloat16 g_ql[NMAT];
__device__ __nv_bfloat16 g_ph[(size_t)Bb * Hh * Tt * SC]; // P [bh,t,s]
__device__ __nv_bfloat16 g_pl[(size_t)Bb * Hh * Tt * SC];
__device__ __nv_bfloat16 g_ah[NMAT];                      // attn [b,t,h,d]
__device__ __nv_bfloat16 g_al[NMAT];

// ---------------------------------------------------------------------------
// PTX helpers
// ---------------------------------------------------------------------------
__device__ __forceinline__ uint32_t smem_u32(const void* p) {
    uint32_t a;
    asm("{ .reg .u64 t; cvta.to.shared.u64 t, %1; cvt.u32.u64 %0, t; }" : "=r"(a) : "l"(p));
    return a;
}
#define CP_ASYNC16(saddr, gaddr) \
    asm volatile("cp.async.cg.shared.global [%0], [%1], 16;" :: "r"(saddr), "l"(gaddr))
#define CP_COMMIT() asm volatile("cp.async.commit_group;" ::: "memory")
#define CP_WAIT(n)  asm volatile("cp.async.wait_group %0;" :: "n"(n) : "memory")

__device__ __forceinline__ void ldm_x4(uint32_t addr, uint32_t* r) {
    asm volatile("ldmatrix.sync.aligned.m8n8.x4.shared.b16 {%0,%1,%2,%3}, [%4];"
        : "=r"(r[0]), "=r"(r[1]), "=r"(r[2]), "=r"(r[3]) : "r"(addr));
}
__device__ __forceinline__ void ldm_x2(uint32_t addr, uint32_t* r) {
    asm volatile("ldmatrix.sync.aligned.m8n8.x2.shared.b16 {%0,%1}, [%2];"
        : "=r"(r[0]), "=r"(r[1]) : "r"(addr));
}
__device__ __forceinline__ void ldm_x2_trans(uint32_t addr, uint32_t* r) {
    asm volatile("ldmatrix.sync.aligned.m8n8.x2.trans.shared.b16 {%0,%1}, [%2];"
        : "=r"(r[0]), "=r"(r[1]) : "r"(addr));
}
__device__ __forceinline__ void mma_bf16(float* d, const uint32_t* a, const uint32_t* b) {
    asm volatile("mma.sync.aligned.m16n8k16.row.col.f32.bf16.bf16.f32 "
        "{%0,%1,%2,%3}, {%4,%5,%6,%7}, {%8,%9}, {%0,%1,%2,%3};"
        : "+f"(d[0]), "+f"(d[1]), "+f"(d[2]), "+f"(d[3])
        : "r"(a[0]), "r"(a[1]), "r"(a[2]), "r"(a[3]), "r"(b[0]), "r"(b[1]));
}

__device__ __forceinline__ void split2_store(float v0, float v1,
                                             __nv_bfloat16* hi, __nv_bfloat16* lo) {
    __nv_bfloat16 h0 = __float2bfloat16(v0);
    __nv_bfloat16 h1 = __float2bfloat16(v1);
    __nv_bfloat16 l0 = __float2bfloat16(v0 - __bfloat162float(h0));
    __nv_bfloat16 l1 = __float2bfloat16(v1 - __bfloat162float(h1));
    *reinterpret_cast<__nv_bfloat162*>(hi) = __halves2bfloat162(h0, h1);
    *reinterpret_cast<__nv_bfloat162*>(lo) = __halves2bfloat162(l0, l1);
}

// ---------------------------------------------------------------------------
// copy caches -> output K/V slots
// ---------------------------------------------------------------------------
__global__ void copy_cache_kernel(const float4* __restrict__ ck,
                                  const float4* __restrict__ cv,
                                  float4* __restrict__ Kout,
                                  float4* __restrict__ Vout) {
    int i = blockIdx.x * blockDim.x + threadIdx.x;
    const int total = Bb * Hh * SC * DK / 4;
    if (i < total) {
        int pos = i & 31;
        int row = i >> 5;
        int s = row & (SC - 1);
        int bh = row >> 10;
        int dst = (((bh * SS) + s) << 5) + pos;
        Kout[dst] = ck[i];
        Vout[dst] = cv[i];
    }
}

// ---------------------------------------------------------------------------
// fp32 -> (bf16 hi, bf16 lo) for 7 matrices
// ---------------------------------------------------------------------------
__device__ __forceinline__ void split4(float4 v, __nv_bfloat162* dh, __nv_bfloat162* dl) {
    __nv_bfloat16 h0 = __float2bfloat16(v.x);
    __nv_bfloat16 h1 = __float2bfloat16(v.y);
    __nv_bfloat16 h2 = __float2bfloat16(v.z);
    __nv_bfloat16 h3 = __float2bfloat16(v.w);
    __nv_bfloat16 l0 = __float2bfloat16(v.x - __bfloat162float(h0));
    __nv_bfloat16 l1 = __float2bfloat16(v.y - __bfloat162float(h1));
    __nv_bfloat16 l2 = __float2bfloat16(v.z - __bfloat162float(h2));
    __nv_bfloat16 l3 = __float2bfloat16(v.w - __bfloat162float(h3));
    dh[0] = __halves2bfloat162(h0, h1);
    dh[1] = __halves2bfloat162(h2, h3);
    dl[0] = __halves2bfloat162(l0, l1);
    dl[1] = __halves2bfloat162(l2, l3);
}

__global__ void convert7_kernel(const float4* __restrict__ x,
                                const float4* __restrict__ wq,
                                const float4* __restrict__ wk,
                                const float4* __restrict__ wv,
                                const float4* __restrict__ wo,
                                const float4* __restrict__ ck,
                                const float4* __restrict__ cv) {
    int id = blockIdx.x * blockDim.x + threadIdx.x;
    const int per = (int)(NMAT / 4);
    int mat = id / per;
    int rem = id - mat * per;
    const float4* srcs[7] = {x, wq, wk, wv, wo, ck, cv};
    float4 v = srcs[mat][rem];
    __nv_bfloat162* dh = reinterpret_cast<__nv_bfloat162*>(g_bh + (size_t)mat * NMAT) + rem * 2;
    __nv_bfloat162* dl = reinterpret_cast<__nv_bfloat162*>(g_bl + (size_t)mat * NMAT) + rem * 2;
    split4(v, dh, dl);
}

// ---------------------------------------------------------------------------
// HMMA bf16x3 GEMM (512 threads, 16 warps 4x4, warp tile 32x32)
// y[m,n] = sum_k A[m,k]*B[n,k], K=2048
// mode 0: A=x, B=W[proj]; Q -> bf16 hi/lo (scaled), K/V -> d_out fp32
// mode 1: A=attn(bf16), B=Wo; -> out fp32
// ---------------------------------------------------------------------------
__global__ __launch_bounds__(512, 1)
void mm_hmma_kernel(int mode, float* __restrict__ Kout, float* __restrict__ Vout,
                    float* __restrict__ out) {
    extern __shared__ char sm[];
    const uint32_t sbu = smem_u32(sm);
    const int tid = threadIdx.x;
    const int wid = tid >> 5, lane = tid & 31;
    const int warp_m = wid >> 2;          // 0..3
    const int warp_n = wid & 3;           // 0..3

    const int proj = blockIdx.z;
    const __nv_bfloat16 *Ah, *Al, *Bh, *Bl;
    if (mode == 0) {
        Ah = g_bh;                        Al = g_bl;
        Bh = g_bh + (size_t)(1 + proj) * NMAT;
        Bl = g_bl + (size_t)(1 + proj) * NMAT;
    } else {
        Ah = g_ah;                        Al = g_al;
        Bh = g_bh + (size_t)4 * NMAT;
        Bl = g_bl + (size_t)4 * NMAT;
    }
    const int m0 = blockIdx.x * 128, n0 = blockIdx.y * 128;

    // cp.async: 2048 16B chunks per stage, 4 per thread
    const __nv_bfloat16* gptr[4];
    uint32_t soff[4];
    {
        const __nv_bfloat16* src4[4] = {
            Ah + (size_t)m0 * KDIM, Al + (size_t)m0 * KDIM,
            Bh + (size_t)n0 * KDIM, Bl + (size_t)n0 * KDIM
        };
#pragma unroll
        for (int j = 0; j < 4; j++) {
            int c = j * 512 + tid;
            int mat = c >> 9;
            int r = (c >> 2) & 127;
            int c16 = c & 3;
            gptr[j] = src4[mat] + (size_t)r * KDIM + c16 * 8;
            soff[j] = (uint32_t)(mat * MM_MAT_BYTES + r * MM_LDS_B + c16 * 16);
        }
    }

    const uint32_t a_row = (uint32_t)(warp_m * 32 + (lane & 15));
    const uint32_t a_kb  = (uint32_t)(((lane >> 4) << 3) * 2);
    const uint32_t b_row = (uint32_t)(warp_n * 32 + (lane & 7));
    const uint32_t b_kb  = (uint32_t)((((lane >> 3) & 1) << 3) * 2);

    float acc[2][4][4];
#pragma unroll
    for (int mi = 0; mi < 2; mi++)
#pragma unroll
        for (int ni = 0; ni < 4; ni++)
#pragma unroll
            for (int q = 0; q < 4; q++) acc[mi][ni][q] = 0.f;

#pragma unroll
    for (int j = 0; j < 4; j++) CP_ASYNC16(sbu + soff[j], gptr[j]);
    CP_COMMIT();

    for (int i = 0; i < MM_KSTEPS; i++) {
        const int s = i & 1;
        if (i + 1 < MM_KSTEPS) {
            const uint32_t sb2 = sbu + ((i + 1) & 1) * MM_STAGE_BYTES;
            const int k0 = (i + 1) * MM_BK;
#pragma unroll
            for (int j = 0; j < 4; j++) CP_ASYNC16(sb2 + soff[j], gptr[j] + k0);
            CP_COMMIT();
            CP_WAIT(1);
        } else {
            CP_WAIT(0);
        }
        __syncthreads();

        const uint32_t stage = sbu + s * MM_STAGE_BYTES;
#pragma unroll
        for (int kk = 0; kk < 2; kk++) {
            const uint32_t kb = (uint32_t)(kk * 32);
            uint32_t bh_f[4][2], bl_f[4][2];
#pragma unroll
            for (int ni = 0; ni < 4; ni++) {
                uint32_t baddr = stage + 2 * MM_MAT_BYTES +
                                 (b_row + ni * 8) * MM_LDS_B + b_kb + kb;
                ldm_x2(baddr, bh_f[ni]);
                ldm_x2(baddr + MM_MAT_BYTES, bl_f[ni]);
            }
#pragma unroll
            for (int mi = 0; mi < 2; mi++) {
                uint32_t ah_f[4], al_f[4];
                uint32_t aaddr = stage + (a_row + mi * 16) * MM_LDS_B + a_kb + kb;
                ldm_x4(aaddr, ah_f);
                ldm_x4(aaddr + MM_MAT_BYTES, al_f);
#pragma unroll
                for (int ni = 0; ni < 4; ni++) {
                    mma_bf16(acc[mi][ni], ah_f, bh_f[ni]);
                    mma_bf16(acc[mi][ni], ah_f, bl_f[ni]);
                    mma_bf16(acc[mi][ni], al_f, bh_f[ni]);
                }
            }
        }
        __syncthreads();
    }

    const int gid = lane >> 2, tc = lane & 3;
#pragma unroll
    for (int mi = 0; mi < 2; mi++) {
#pragma unroll
        for (int ni = 0; ni < 4; ni++) {
            int mrow0 = m0 + warp_m * 32 + mi * 16 + gid;
            int ncol  = n0 + warp_n * 32 + ni * 8 + tc * 2;
#pragma unroll
            for (int half = 0; half < 2; half++) {
                int m = mrow0 + half * 8;
                float v0 = acc[mi][ni][half * 2 + 0];
                float v1 = acc[mi][ni][half * 2 + 1];
                if (mode == 0) {
                    int b = m >> 10, t = m & (Tt - 1);
                    int h = ncol >> 7, d = ncol & (DK - 1);
                    if (proj == 0) {
                        size_t qi = (((size_t)(b * Hh + h) * Tt) + t) * DK + d;
                        split2_store(v0 * RSQRT_DK, v1 * RSQRT_DK, g_qh + qi, g_ql + qi);
                    } else {
                        float* base = (proj == 1) ? Kout : Vout;
                        float* dst = base + (((size_t)(b * Hh + h) * SS) + SC + t) * DK + d;
                        float2 vv; vv.x = v0; vv.y = v1;
                        *reinterpret_cast<float2*>(dst) = vv;
                    }
                } else {
                    float* dst = out + (size_t)m * Cc + ncol;
                    float2 vv; vv.x = v0; vv.y = v1;
                    *reinterpret_cast<float2*>(dst) = vv;
                }
            }
        }
    }
}

// ---------------------------------------------------------------------------
// scores via HMMA bf16x3 (512 threads): scores[bh,t,s] = Q . K, Kdim=128
// ---------------------------------------------------------------------------
__global__ __launch_bounds__(512, 1)
void scores_hmma_kernel() {
    if (blockIdx.y > blockIdx.x) return;
    extern __shared__ char sm[];
    const uint32_t sbu = smem_u32(sm);
    const int tid = threadIdx.x;
    const int wid = tid >> 5, lane = tid & 31;
    const int warp_m = wid >> 2;
    const int warp_n = wid & 3;

    const int bh = blockIdx.z;
    const int m0 = blockIdx.x * 128, n0 = blockIdx.y * 128;

    const __nv_bfloat16* gptr[4];
    uint32_t soff[4];
    {
        const __nv_bfloat16* src4[4] = {
            g_qh + (size_t)bh * Tt * DK + (size_t)m0 * DK,
            g_ql + (size_t)bh * Tt * DK + (size_t)m0 * DK,
            g_bh + (size_t)5 * NMAT + (size_t)bh * SC * DK + (size_t)n0 * DK,
            g_bl + (size_t)5 * NMAT + (size_t)bh * SC * DK + (size_t)n0 * DK
        };
#pragma unroll
        for (int j = 0; j < 4; j++) {
            int c = j * 512 + tid;
            int mat = c >> 9;
            int r = (c >> 2) & 127;
            int c16 = c & 3;
            gptr[j] = src4[mat] + (size_t)r * DK + c16 * 8;
            soff[j] = (uint32_t)(mat * MM_MAT_BYTES + r * MM_LDS_B + c16 * 16);
        }
    }

    const uint32_t a_row = (uint32_t)(warp_m * 32 + (lane & 15));
    const uint32_t a_kb  = (uint32_t)(((lane >> 4) << 3) * 2);
    const uint32_t b_row = (uint32_t)(warp_n * 32 + (lane & 7));
    const uint32_t b_kb  = (uint32_t)((((lane >> 3) & 1) << 3) * 2);

    float acc[2][4][4];
#pragma unroll
    for (int mi = 0; mi < 2; mi++)
#pragma unroll
        for (int ni = 0; ni < 4; ni++)
#pragma unroll
            for (int q = 0; q < 4; q++) acc[mi][ni][q] = 0.f;

#pragma unroll
    for (int j = 0; j < 4; j++) CP_ASYNC16(sbu + soff[j], gptr[j]);
    CP_COMMIT();

    for (int i = 0; i < SC_KSTEPS; i++) {
        const int s = i & 1;
        if (i + 1 < SC_KSTEPS) {
            const uint32_t sb2 = sbu + ((i + 1) & 1) * MM_STAGE_BYTES;
            const int k0 = (i + 1) * MM_BK;
#pragma unroll
            for (int j = 0; j < 4; j++) CP_ASYNC16(sb2 + soff[j], gptr[j] + k0);
            CP_COMMIT();
            CP_WAIT(1);
        } else {
            CP_WAIT(0);
        }
        __syncthreads();

        const uint32_t stage = sbu + s * MM_STAGE_BYTES;
#pragma unroll
        for (int kk = 0; kk < 2; kk++) {
            const uint32_t kb = (uint32_t)(kk * 32);
            uint32_t bh_f[4][2], bl_f[4][2];
#pragma unroll
            for (int ni = 0; ni < 4; ni++) {
                uint32_t baddr = stage + 2 * MM_MAT_BYTES +
                                 (b_row + ni * 8) * MM_LDS_B + b_kb + kb;
                ldm_x2(baddr, bh_f[ni]);
                ldm_x2(baddr + MM_MAT_BYTES, bl_f[ni]);
            }
#pragma unroll
            for (int mi = 0; mi < 2; mi++) {
                uint32_t ah_f[4], al_f[4];
                uint32_t aaddr = stage + (a_row + mi * 16) * MM_LDS_B + a_kb + kb;
                ldm_x4(aaddr, ah_f);
                ldm_x4(aaddr + MM_MAT_BYTES, al_f);
#pragma unroll
                for (int ni = 0; ni < 4; ni++) {
                    mma_bf16(acc[mi][ni], ah_f, bh_f[ni]);
                    mma_bf16(acc[mi][ni], ah_f, bl_f[ni]);
                    mma_bf16(acc[mi][ni], al_f, bh_f[ni]);
                }
            }
        }
        __syncthreads();
    }

    float* outp = g_scores + (size_t)bh * Tt * SC;
    const int gid = lane >> 2, tc = lane & 3;
#pragma unroll
    for (int mi = 0; mi < 2; mi++) {
#pragma unroll
        for (int ni = 0; ni < 4; ni++) {
            int mrow0 = m0 + warp_m * 32 + mi * 16 + gid;
            int ncol  = n0 + warp_n * 32 + ni * 8 + tc * 2;
#pragma unroll
            for (int half = 0; half < 2; half++) {
                int t = mrow0 + half * 8;
                float2 vv;
                vv.x = acc[mi][ni][half * 2 + 0];
                vv.y = acc[mi][ni][half * 2 + 1];
                *reinterpret_cast<float2*>(outp + (size_t)t * SC + ncol) = vv;
            }
        }
    }
}

// ---------------------------------------------------------------------------
// softmax: fp32 scores in, bf16 hi/lo P out (zero tail)
// ---------------------------------------------------------------------------
__global__ __launch_bounds__(256)
void softmax_kernel() {
    __shared__ float sred[8];
    int row = blockIdx.x;
    int t = row & (Tt - 1);
    int len = t + 1;
    const float* p = g_scores + (size_t)row * SC;
    int tid = threadIdx.x;
    int lane = tid & 31, warp = tid >> 5;

    float v[4];
    float m = -1e30f;
#pragma unroll
    for (int j = 0; j < 4; j++) {
        int idx = tid + j * 256;
        if (idx < len) { v[j] = p[idx]; m = fmaxf(m, v[j]); }
    }
#pragma unroll
    for (int o = 16; o; o >>= 1) m = fmaxf(m, __shfl_xor_sync(0xffffffffu, m, o));
    if (lane == 0) sred[warp] = m;
    __syncthreads();
    if (tid < 32) {
        float x = (lane < 8) ? sred[lane] : -1e30f;
#pragma unroll
        for (int o = 4; o; o >>= 1) x = fmaxf(x, __shfl_xor_sync(0xffffffffu, x, o));
        if (lane == 0) sred[0] = x;
    }
    __syncthreads();
    m = sred[0];
    __syncthreads();

    float sum = 0.f;
#pragma unroll
    for (int j = 0; j < 4; j++) {
        int idx = tid + j * 256;
        if (idx < len) { v[j] = __expf(v[j] - m); sum += v[j]; }
    }
#pragma unroll
    for (int o = 16; o; o >>= 1) sum += __shfl_xor_sync(0xffffffffu, sum, o);
    if (lane == 0) sred[warp] = sum;
    __syncthreads();
    if (tid < 32) {
        float x = (lane < 8) ? sred[lane] : 0.f;
#pragma unroll
        for (int o = 4; o; o >>= 1) x += __shfl_xor_sync(0xffffffffu, x, o);
        if (lane == 0) sred[0] = x;
    }
    __syncthreads();
    float inv = 1.f / sred[0];

    size_t base = (size_t)row * SC;
#pragma unroll
    for (int j = 0; j < 4; j++) {
        int idx = tid + j * 256;
        float w = (idx < len) ? v[j] * inv : 0.f;
        __nv_bfloat16 hh = __float2bfloat16(w);
        g_ph[base + idx] = hh;
        g_pl[base + idx] = __float2bfloat16(w - __bfloat162float(hh));
    }
}

// ---------------------------------------------------------------------------
// PV via HMMA bf16x3 (512 threads): attn[bh,t,d] = sum_s P[t,s] V[s,d]
// V native [s,d] via ldmatrix.trans. Causal k-limit. Output bf16 hi/lo.
// ---------------------------------------------------------------------------
__global__ __launch_bounds__(512, 1)
void pv_hmma_kernel() {
    extern __shared__ char sm[];
    const uint32_t sbu = smem_u32(sm);
    const int tid = threadIdx.x;
    const int wid = tid >> 5, lane = tid & 31;
    const int warp_m = wid >> 2;
    const int warp_n = wid & 3;

    const int mt = blockIdx.x;
    const int bh = blockIdx.y;
    const int m0 = mt * 128;
    const int ksteps = (mt + 1) * 4;

    const __nv_bfloat16* Ph = g_ph + (size_t)bh * Tt * SC + (size_t)m0 * SC;
    const __nv_bfloat16* Pl = g_pl + (size_t)bh * Tt * SC + (size_t)m0 * SC;
    const __nv_bfloat16* Vh = g_bh + (size_t)6 * NMAT + (size_t)bh * SC * DK;
    const __nv_bfloat16* Vl = g_bl + (size_t)6 * NMAT + (size_t)bh * SC * DK;

    const __nv_bfloat16* gptr[4];
    int gstep[4];
    uint32_t soff[4];
#pragma unroll
    for (int j = 0; j < 4; j++) {
        int c = j * 512 + tid;
        if (c < 1024) {
            int mat = c >> 9;
            int idx = c & 511;
            int r = idx >> 2, c16 = idx & 3;
            gptr[j] = (mat ? Pl : Ph) + (size_t)r * SC + c16 * 8;
            gstep[j] = MM_BK;
            soff[j] = (uint32_t)(mat * PV_MATP + r * MM_LDS_B + c16 * 16);
        } else {
            int q = c - 1024;
            int mat = q >> 9;
            int idx = q & 511;
            int r = idx >> 4, c16 = idx & 15;
            gptr[j] = (mat ? Vl : Vh) + (size_t)r * DK + c16 * 8;
            gstep[j] = MM_BK * DK;
            soff[j] = (uint32_t)(2 * PV_MATP + mat * PV_MATV + r * PV_LDSV + c16 * 16);
        }
    }

    const uint32_t a_row = (uint32_t)(warp_m * 32 + (lane & 15));
    const uint32_t a_kb  = (uint32_t)(((lane >> 4) << 3) * 2);
    const uint32_t v_row = (uint32_t)(lane & 15);

    float acc[2][4][4];
#pragma unroll
    for (int mi = 0; mi < 2; mi++)
#pragma unroll
        for (int ni = 0; ni < 4; ni++)
#pragma unroll
            for (int q = 0; q < 4; q++) acc[mi][ni][q] = 0.f;

#pragma unroll
    for (int j = 0; j < 4; j++) CP_ASYNC16(sbu + soff[j], gptr[j]);
    CP_COMMIT();

    for (int i = 0; i < ksteps; i++) {
        const int s = i & 1;
        if (i + 1 < ksteps) {
            const uint32_t sb2 = sbu + ((i + 1) & 1) * PV_STAGE;
#pragma unroll
            for (int j = 0; j < 4; j++)
                CP_ASYNC16(sb2 + soff[j], gptr[j] + (size_t)(i + 1) * gstep[j]);
            CP_COMMIT();
            CP_WAIT(1);
        } else {
            CP_WAIT(0);
        }
        __syncthreads();

        const uint32_t stage = sbu + s * PV_STAGE;
        const uint32_t vbase = stage + 2 * PV_MATP;
#pragma unroll
        for (int kk = 0; kk < 2; kk++) {
            uint32_t bh_f[4][2], bl_f[4][2];
#pragma unroll
            for (int ni = 0; ni < 4; ni++) {
                uint32_t ncl = (uint32_t)(warp_n * 32 + ni * 8) * 2;
                uint32_t baddr = vbase + (kk * 16 + v_row) * PV_LDSV + ncl;
                ldm_x2_trans(baddr, bh_f[ni]);
                ldm_x2_trans(baddr + PV_MATV, bl_f[ni]);
            }
#pragma unroll
            for (int mi = 0; mi < 2; mi++) {
                uint32_t ah_f[4], al_f[4];
                uint32_t aaddr = stage + (a_row + mi * 16) * MM_LDS_B + a_kb + (uint32_t)(kk * 32);
                ldm_x4(aaddr, ah_f);
                ldm_x4(aaddr + PV_MATP, al_f);
#pragma unroll
                for (int ni = 0; ni < 4; ni++) {
                    mma_bf16(acc[mi][ni], ah_f, bh_f[ni]);
                    mma_bf16(acc[mi][ni], ah_f, bl_f[ni]);
                    mma_bf16(acc[mi][ni], al_f, bh_f[ni]);
                }
            }
        }
        __syncthreads();
    }

    const int b = bh >> 4, h = bh & (Hh - 1);
    const int gid = lane >> 2, tc = lane & 3;
#pragma unroll
    for (int mi = 0; mi < 2; mi++) {
#pragma unroll
        for (int ni = 0; ni < 4; ni++) {
            int mrow0 = m0 + warp_m * 32 + mi * 16 + gid;
            int d = warp_n * 32 + ni * 8 + tc * 2;
#pragma unroll
            for (int half = 0; half < 2; half++) {
                int t = mrow0 + half * 8;
                float v0 = acc[mi][ni][half * 2 + 0];
                float v1 = acc[mi][ni][half * 2 + 1];
                size_t idx = (((size_t)(b * Tt + t) * Hh) + h) * DK + d;
                split2_store(v0, v1, g_ah + idx, g_al + idx);
            }
        }
    }
}

// ---------------------------------------------------------------------------
extern "C" void kernel_launch(void* const* d_in, const int* in_sizes, int n_in,
                              void* d_out, int out_size) {
    const float* x  = (const float*)d_in[0];
    const float* ck = (const float*)d_in[1];
    const float* cv = (const float*)d_in[2];
    const float* Wq = (const float*)d_in[3];
    const float* Wk = (const float*)d_in[4];
    const float* Wv = (const float*)d_in[5];
    const float* Wo = (const float*)d_in[6];

    float* out  = (float*)d_out;
    float* Kout = out + (size_t)Bb * Tt * Cc;
    float* Vout = Kout + (size_t)Bb * Hh * SS * DK;

    cudaFuncSetAttribute(mm_hmma_kernel, cudaFuncAttributeMaxDynamicSharedMemorySize, MM_SMEM);
    cudaFuncSetAttribute(scores_hmma_kernel, cudaFuncAttributeMaxDynamicSharedMemorySize, MM_SMEM);
    cudaFuncSetAttribute(pv_hmma_kernel, cudaFuncAttributeMaxDynamicSharedMemorySize, PV_SMEM);

    copy_cache_kernel<<<4096, 256>>>((const float4*)ck, (const float4*)cv,
                                     (float4*)Kout, (float4*)Vout);
    convert7_kernel<<<28672, 256>>>((const float4*)x, (const float4*)Wq,
                                    (const float4*)Wk, (const float4*)Wv,
                                    (const float4*)Wo, (const float4*)ck,
                                    (const float4*)cv);
    mm_hmma_kernel<<<dim3(16, 16, 3), 512, MM_SMEM>>>(0, Kout, Vout, out);
    scores_hmma_kernel<<<dim3(8, 8, 32), 512, MM_SMEM>>>();
    softmax_kernel<<<Bb * Hh * Tt, 256>>>();
    pv_hmma_kernel<<<dim3(8, 32), 512, PV_SMEM>>>();
    mm_hmma_kernel<<<dim3(16, 16, 1), 512, MM_SMEM>>>(1, Kout, Vout, out);
}

// round 7
// speedup vs baseline: 1.0002x; 1.0002x over previous
#include <cuda_runtime.h>
#include <cuda_bf16.h>
#include <math.h>
#include <stdint.h>

// Problem dims
#define Bb 2
#define Tt 1024
#define Cc 2048
#define Hh 16
#define DK 128
#define SC 1024
#define SS 2048
#define KDIM 2048
#define NMAT 4194304ull   // 2048*2048

#define RSQRT_DK 0.08838834764831845f

// HMMA GEMM tiling (128x128 CTA tile, 16 warps 4x4, warp tile 32x32, BK=32)
#define MM_BK 32
#define MM_LDS_B 80                       // bytes per smem row (32 bf16 + 16 pad)
#define MM_MAT_BYTES (128 * MM_LDS_B)     // 10240
#define MM_STAGE_BYTES (4 * MM_MAT_BYTES) // 40960
#define MM_SMEM (2 * MM_STAGE_BYTES)      // 81920
#define MM_KSTEPS (KDIM / MM_BK)          // 64
#define SC_KSTEPS (DK / MM_BK)            // 4

// PV tiling: A = P [128 x 32], B = V [32 x 128] (ldmatrix.trans)
#define PV_LDSV 272                       // 128 bf16 (256B) + 16 pad
#define PV_MATP MM_MAT_BYTES              // 10240
#define PV_MATV (32 * PV_LDSV)            // 8704
#define PV_STAGE (2 * PV_MATP + 2 * PV_MATV)  // 37888
#define PV_SMEM (2 * PV_STAGE)            // 75776

// ---------------------------------------------------------------------------
// Scratch (device globals)
// ---------------------------------------------------------------------------
__device__ float g_scores[(size_t)Bb * Hh * Tt * SC];     // [bh,t,s]
// bf16 hi/lo: 0=x, 1=Wq, 2=Wk, 3=Wv, 4=Wo, 5=cache_k, 6=cache_v
__device__ __nv_bfloat16 g_bh[7 * NMAT];
__device__ __nv_bfloat16 g_bl[7 * NMAT];
__device__ __nv_bfloat16 g_qh[NMAT];                      // Q [bh,t,d] scaled
__device__ __nv_bfloat16 g_ql[NMAT];
__device__ __nv_bfloat16 g_ph[(size_t)Bb * Hh * Tt * SC]; // P [bh,t,s]
__device__ __nv_bfloat16 g_pl[(size_t)Bb * Hh * Tt * SC];
__device__ __nv_bfloat16 g_ah[NMAT];                      // attn [b,t,h,d]
__device__ __nv_bfloat16 g_al[NMAT];

// ---------------------------------------------------------------------------
// PTX helpers
// ---------------------------------------------------------------------------
__device__ __forceinline__ uint32_t smem_u32(const void* p) {
    uint32_t a;
    asm("{ .reg .u64 t; cvta.to.shared.u64 t, %1; cvt.u32.u64 %0, t; }" : "=r"(a) : "l"(p));
    return a;
}
#define CP_ASYNC16(saddr, gaddr) \
    asm volatile("cp.async.cg.shared.global [%0], [%1], 16;" :: "r"(saddr), "l"(gaddr))
#define CP_COMMIT() asm volatile("cp.async.commit_group;" ::: "memory")
#define CP_WAIT(n)  asm volatile("cp.async.wait_group %0;" :: "n"(n) : "memory")

__device__ __forceinline__ void ldm_x4(uint32_t addr, uint32_t* r) {
    asm volatile("ldmatrix.sync.aligned.m8n8.x4.shared.b16 {%0,%1,%2,%3}, [%4];"
        : "=r"(r[0]), "=r"(r[1]), "=r"(r[2]), "=r"(r[3]) : "r"(addr));
}
__device__ __forceinline__ void ldm_x2(uint32_t addr, uint32_t* r) {
    asm volatile("ldmatrix.sync.aligned.m8n8.x2.shared.b16 {%0,%1}, [%2];"
        : "=r"(r[0]), "=r"(r[1]) : "r"(addr));
}
__device__ __forceinline__ void ldm_x2_trans(uint32_t addr, uint32_t* r) {
    asm volatile("ldmatrix.sync.aligned.m8n8.x2.trans.shared.b16 {%0,%1}, [%2];"
        : "=r"(r[0]), "=r"(r[1]) : "r"(addr));
}
__device__ __forceinline__ void mma_bf16(float* d, const uint32_t* a, const uint32_t* b) {
    asm volatile("mma.sync.aligned.m16n8k16.row.col.f32.bf16.bf16.f32 "
        "{%0,%1,%2,%3}, {%4,%5,%6,%7}, {%8,%9}, {%0,%1,%2,%3};"
        : "+f"(d[0]), "+f"(d[1]), "+f"(d[2]), "+f"(d[3])
        : "r"(a[0]), "r"(a[1]), "r"(a[2]), "r"(a[3]), "r"(b[0]), "r"(b[1]));
}

__device__ __forceinline__ void split2_store(float v0, float v1,
                                             __nv_bfloat16* hi, __nv_bfloat16* lo) {
    __nv_bfloat16 h0 = __float2bfloat16(v0);
    __nv_bfloat16 h1 = __float2bfloat16(v1);
    __nv_bfloat16 l0 = __float2bfloat16(v0 - __bfloat162float(h0));
    __nv_bfloat16 l1 = __float2bfloat16(v1 - __bfloat162float(h1));
    *reinterpret_cast<__nv_bfloat162*>(hi) = __halves2bfloat162(h0, h1);
    *reinterpret_cast<__nv_bfloat162*>(lo) = __halves2bfloat162(l0, l1);
}

// Term-major MMA block: all fragments loaded, 3 passes over 2x4 accumulators.
// Consecutive MMAs hit different accumulators (dep distance 8).
__device__ __forceinline__ void mma_block_x3(float acc[2][4][4],
                                             uint32_t ah_f[2][4], uint32_t al_f[2][4],
                                             uint32_t bh_f[4][2], uint32_t bl_f[4][2]) {
#pragma unroll
    for (int mi = 0; mi < 2; mi++)
#pragma unroll
        for (int ni = 0; ni < 4; ni++)
            mma_bf16(acc[mi][ni], ah_f[mi], bh_f[ni]);
#pragma unroll
    for (int mi = 0; mi < 2; mi++)
#pragma unroll
        for (int ni = 0; ni < 4; ni++)
            mma_bf16(acc[mi][ni], ah_f[mi], bl_f[ni]);
#pragma unroll
    for (int mi = 0; mi < 2; mi++)
#pragma unroll
        for (int ni = 0; ni < 4; ni++)
            mma_bf16(acc[mi][ni], al_f[mi], bh_f[ni]);
}

// ---------------------------------------------------------------------------
// copy caches -> output K/V slots
// ---------------------------------------------------------------------------
__global__ void copy_cache_kernel(const float4* __restrict__ ck,
                                  const float4* __restrict__ cv,
                                  float4* __restrict__ Kout,
                                  float4* __restrict__ Vout) {
    int i = blockIdx.x * blockDim.x + threadIdx.x;
    const int total = Bb * Hh * SC * DK / 4;
    if (i < total) {
        int pos = i & 31;
        int row = i >> 5;
        int s = row & (SC - 1);
        int bh = row >> 10;
        int dst = (((bh * SS) + s) << 5) + pos;
        Kout[dst] = ck[i];
        Vout[dst] = cv[i];
    }
}

// ---------------------------------------------------------------------------
// fp32 -> (bf16 hi, bf16 lo) for 7 matrices
// ---------------------------------------------------------------------------
__device__ __forceinline__ void split4(float4 v, __nv_bfloat162* dh, __nv_bfloat162* dl) {
    __nv_bfloat16 h0 = __float2bfloat16(v.x);
    __nv_bfloat16 h1 = __float2bfloat16(v.y);
    __nv_bfloat16 h2 = __float2bfloat16(v.z);
    __nv_bfloat16 h3 = __float2bfloat16(v.w);
    __nv_bfloat16 l0 = __float2bfloat16(v.x - __bfloat162float(h0));
    __nv_bfloat16 l1 = __float2bfloat16(v.y - __bfloat162float(h1));
    __nv_bfloat16 l2 = __float2bfloat16(v.z - __bfloat162float(h2));
    __nv_bfloat16 l3 = __float2bfloat16(v.w - __bfloat162float(h3));
    dh[0] = __halves2bfloat162(h0, h1);
    dh[1] = __halves2bfloat162(h2, h3);
    dl[0] = __halves2bfloat162(l0, l1);
    dl[1] = __halves2bfloat162(l2, l3);
}

__global__ void convert7_kernel(const float4* __restrict__ x,
                                const float4* __restrict__ wq,
                                const float4* __restrict__ wk,
                                const float4* __restrict__ wv,
                                const float4* __restrict__ wo,
                                const float4* __restrict__ ck,
                                const float4* __restrict__ cv) {
    int id = blockIdx.x * blockDim.x + threadIdx.x;
    const int per = (int)(NMAT / 4);
    int mat = id / per;
    int rem = id - mat * per;
    const float4* srcs[7] = {x, wq, wk, wv, wo, ck, cv};
    float4 v = srcs[mat][rem];
    __nv_bfloat162* dh = reinterpret_cast<__nv_bfloat162*>(g_bh + (size_t)mat * NMAT) + rem * 2;
    __nv_bfloat162* dl = reinterpret_cast<__nv_bfloat162*>(g_bl + (size_t)mat * NMAT) + rem * 2;
    split4(v, dh, dl);
}

// ---------------------------------------------------------------------------
// HMMA bf16x3 GEMM (512 threads, 16 warps 4x4, warp tile 32x32)
// ---------------------------------------------------------------------------
__global__ __launch_bounds__(512, 1)
void mm_hmma_kernel(int mode, float* __restrict__ Kout, float* __restrict__ Vout,
                    float* __restrict__ out) {
    extern __shared__ char sm[];
    const uint32_t sbu = smem_u32(sm);
    const int tid = threadIdx.x;
    const int wid = tid >> 5, lane = tid & 31;
    const int warp_m = wid >> 2;
    const int warp_n = wid & 3;

    const int proj = blockIdx.z;
    const __nv_bfloat16 *Ah, *Al, *Bh, *Bl;
    if (mode == 0) {
        Ah = g_bh;                        Al = g_bl;
        Bh = g_bh + (size_t)(1 + proj) * NMAT;
        Bl = g_bl + (size_t)(1 + proj) * NMAT;
    } else {
        Ah = g_ah;                        Al = g_al;
        Bh = g_bh + (size_t)4 * NMAT;
        Bl = g_bl + (size_t)4 * NMAT;
    }
    const int m0 = blockIdx.x * 128, n0 = blockIdx.y * 128;

    const __nv_bfloat16* gptr[4];
    uint32_t soff[4];
    {
        const __nv_bfloat16* src4[4] = {
            Ah + (size_t)m0 * KDIM, Al + (size_t)m0 * KDIM,
            Bh + (size_t)n0 * KDIM, Bl + (size_t)n0 * KDIM
        };
#pragma unroll
        for (int j = 0; j < 4; j++) {
            int c = j * 512 + tid;
            int mat = c >> 9;
            int r = (c >> 2) & 127;
            int c16 = c & 3;
            gptr[j] = src4[mat] + (size_t)r * KDIM + c16 * 8;
            soff[j] = (uint32_t)(mat * MM_MAT_BYTES + r * MM_LDS_B + c16 * 16);
        }
    }

    const uint32_t a_row = (uint32_t)(warp_m * 32 + (lane & 15));
    const uint32_t a_kb  = (uint32_t)(((lane >> 4) << 3) * 2);
    const uint32_t b_row = (uint32_t)(warp_n * 32 + (lane & 7));
    const uint32_t b_kb  = (uint32_t)((((lane >> 3) & 1) << 3) * 2);

    float acc[2][4][4];
#pragma unroll
    for (int mi = 0; mi < 2; mi++)
#pragma unroll
        for (int ni = 0; ni < 4; ni++)
#pragma unroll
            for (int q = 0; q < 4; q++) acc[mi][ni][q] = 0.f;

#pragma unroll
    for (int j = 0; j < 4; j++) CP_ASYNC16(sbu + soff[j], gptr[j]);
    CP_COMMIT();

    for (int i = 0; i < MM_KSTEPS; i++) {
        const int s = i & 1;
        if (i + 1 < MM_KSTEPS) {
            const uint32_t sb2 = sbu + ((i + 1) & 1) * MM_STAGE_BYTES;
            const int k0 = (i + 1) * MM_BK;
#pragma unroll
            for (int j = 0; j < 4; j++) CP_ASYNC16(sb2 + soff[j], gptr[j] + k0);
            CP_COMMIT();
            CP_WAIT(1);
        } else {
            CP_WAIT(0);
        }
        __syncthreads();

        const uint32_t stage = sbu + s * MM_STAGE_BYTES;
#pragma unroll
        for (int kk = 0; kk < 2; kk++) {
            const uint32_t kb = (uint32_t)(kk * 32);
            uint32_t ah_f[2][4], al_f[2][4], bh_f[4][2], bl_f[4][2];
#pragma unroll
            for (int ni = 0; ni < 4; ni++) {
                uint32_t baddr = stage + 2 * MM_MAT_BYTES +
                                 (b_row + ni * 8) * MM_LDS_B + b_kb + kb;
                ldm_x2(baddr, bh_f[ni]);
                ldm_x2(baddr + MM_MAT_BYTES, bl_f[ni]);
            }
#pragma unroll
            for (int mi = 0; mi < 2; mi++) {
                uint32_t aaddr = stage + (a_row + mi * 16) * MM_LDS_B + a_kb + kb;
                ldm_x4(aaddr, ah_f[mi]);
                ldm_x4(aaddr + MM_MAT_BYTES, al_f[mi]);
            }
            mma_block_x3(acc, ah_f, al_f, bh_f, bl_f);
        }
        __syncthreads();
    }

    const int gid = lane >> 2, tc = lane & 3;
#pragma unroll
    for (int mi = 0; mi < 2; mi++) {
#pragma unroll
        for (int ni = 0; ni < 4; ni++) {
            int mrow0 = m0 + warp_m * 32 + mi * 16 + gid;
            int ncol  = n0 + warp_n * 32 + ni * 8 + tc * 2;
#pragma unroll
            for (int half = 0; half < 2; half++) {
                int m = mrow0 + half * 8;
                float v0 = acc[mi][ni][half * 2 + 0];
                float v1 = acc[mi][ni][half * 2 + 1];
                if (mode == 0) {
                    int b = m >> 10, t = m & (Tt - 1);
                    int h = ncol >> 7, d = ncol & (DK - 1);
                    if (proj == 0) {
                        size_t qi = (((size_t)(b * Hh + h) * Tt) + t) * DK + d;
                        split2_store(v0 * RSQRT_DK, v1 * RSQRT_DK, g_qh + qi, g_ql + qi);
                    } else {
                        float* base = (proj == 1) ? Kout : Vout;
                        float* dst = base + (((size_t)(b * Hh + h) * SS) + SC + t) * DK + d;
                        float2 vv; vv.x = v0; vv.y = v1;
                        *reinterpret_cast<float2*>(dst) = vv;
                    }
                } else {
                    float* dst = out + (size_t)m * Cc + ncol;
                    float2 vv; vv.x = v0; vv.y = v1;
                    *reinterpret_cast<float2*>(dst) = vv;
                }
            }
        }
    }
}

// ---------------------------------------------------------------------------
// scores via HMMA bf16x3 (512 threads): scores[bh,t,s] = Q . K, Kdim=128
// ---------------------------------------------------------------------------
__global__ __launch_bounds__(512, 1)
void scores_hmma_kernel() {
    if (blockIdx.y > blockIdx.x) return;
    extern __shared__ char sm[];
    const uint32_t sbu = smem_u32(sm);
    const int tid = threadIdx.x;
    const int wid = tid >> 5, lane = tid & 31;
    const int warp_m = wid >> 2;
    const int warp_n = wid & 3;

    const int bh = blockIdx.z;
    const int m0 = blockIdx.x * 128, n0 = blockIdx.y * 128;

    const __nv_bfloat16* gptr[4];
    uint32_t soff[4];
    {
        const __nv_bfloat16* src4[4] = {
            g_qh + (size_t)bh * Tt * DK + (size_t)m0 * DK,
            g_ql + (size_t)bh * Tt * DK + (size_t)m0 * DK,
            g_bh + (size_t)5 * NMAT + (size_t)bh * SC * DK + (size_t)n0 * DK,
            g_bl + (size_t)5 * NMAT + (size_t)bh * SC * DK + (size_t)n0 * DK
        };
#pragma unroll
        for (int j = 0; j < 4; j++) {
            int c = j * 512 + tid;
            int mat = c >> 9;
            int r = (c >> 2) & 127;
            int c16 = c & 3;
            gptr[j] = src4[mat] + (size_t)r * DK + c16 * 8;
            soff[j] = (uint32_t)(mat * MM_MAT_BYTES + r * MM_LDS_B + c16 * 16);
        }
    }

    const uint32_t a_row = (uint32_t)(warp_m * 32 + (lane & 15));
    const uint32_t a_kb  = (uint32_t)(((lane >> 4) << 3) * 2);
    const uint32_t b_row = (uint32_t)(warp_n * 32 + (lane & 7));
    const uint32_t b_kb  = (uint32_t)((((lane >> 3) & 1) << 3) * 2);

    float acc[2][4][4];
#pragma unroll
    for (int mi = 0; mi < 2; mi++)
#pragma unroll
        for (int ni = 0; ni < 4; ni++)
#pragma unroll
            for (int q = 0; q < 4; q++) acc[mi][ni][q] = 0.f;

#pragma unroll
    for (int j = 0; j < 4; j++) CP_ASYNC16(sbu + soff[j], gptr[j]);
    CP_COMMIT();

    for (int i = 0; i < SC_KSTEPS; i++) {
        const int s = i & 1;
        if (i + 1 < SC_KSTEPS) {
            const uint32_t sb2 = sbu + ((i + 1) & 1) * MM_STAGE_BYTES;
            const int k0 = (i + 1) * MM_BK;
#pragma unroll
            for (int j = 0; j < 4; j++) CP_ASYNC16(sb2 + soff[j], gptr[j] + k0);
            CP_COMMIT();
            CP_WAIT(1);
        } else {
            CP_WAIT(0);
        }
        __syncthreads();

        const uint32_t stage = sbu + s * MM_STAGE_BYTES;
#pragma unroll
        for (int kk = 0; kk < 2; kk++) {
            const uint32_t kb = (uint32_t)(kk * 32);
            uint32_t ah_f[2][4], al_f[2][4], bh_f[4][2], bl_f[4][2];
#pragma unroll
            for (int ni = 0; ni < 4; ni++) {
                uint32_t baddr = stage + 2 * MM_MAT_BYTES +
                                 (b_row + ni * 8) * MM_LDS_B + b_kb + kb;
                ldm_x2(baddr, bh_f[ni]);
                ldm_x2(baddr + MM_MAT_BYTES, bl_f[ni]);
            }
#pragma unroll
            for (int mi = 0; mi < 2; mi++) {
                uint32_t aaddr = stage + (a_row + mi * 16) * MM_LDS_B + a_kb + kb;
                ldm_x4(aaddr, ah_f[mi]);
                ldm_x4(aaddr + MM_MAT_BYTES, al_f[mi]);
            }
            mma_block_x3(acc, ah_f, al_f, bh_f, bl_f);
        }
        __syncthreads();
    }

    float* outp = g_scores + (size_t)bh * Tt * SC;
    const int gid = lane >> 2, tc = lane & 3;
#pragma unroll
    for (int mi = 0; mi < 2; mi++) {
#pragma unroll
        for (int ni = 0; ni < 4; ni++) {
            int mrow0 = m0 + warp_m * 32 + mi * 16 + gid;
            int ncol  = n0 + warp_n * 32 + ni * 8 + tc * 2;
#pragma unroll
            for (int half = 0; half < 2; half++) {
                int t = mrow0 + half * 8;
                float2 vv;
                vv.x = acc[mi][ni][half * 2 + 0];
                vv.y = acc[mi][ni][half * 2 + 1];
                *reinterpret_cast<float2*>(outp + (size_t)t * SC + ncol) = vv;
            }
        }
    }
}

// ---------------------------------------------------------------------------
// softmax: fp32 scores in, bf16 hi/lo P out (zero tail)
// ---------------------------------------------------------------------------
__global__ __launch_bounds__(256)
void softmax_kernel() {
    __shared__ float sred[8];
    int row = blockIdx.x;
    int t = row & (Tt - 1);
    int len = t + 1;
    const float* p = g_scores + (size_t)row * SC;
    int tid = threadIdx.x;
    int lane = tid & 31, warp = tid >> 5;

    float v[4];
    float m = -1e30f;
#pragma unroll
    for (int j = 0; j < 4; j++) {
        int idx = tid + j * 256;
        if (idx < len) { v[j] = p[idx]; m = fmaxf(m, v[j]); }
    }
#pragma unroll
    for (int o = 16; o; o >>= 1) m = fmaxf(m, __shfl_xor_sync(0xffffffffu, m, o));
    if (lane == 0) sred[warp] = m;
    __syncthreads();
    if (tid < 32) {
        float x = (lane < 8) ? sred[lane] : -1e30f;
#pragma unroll
        for (int o = 4; o; o >>= 1) x = fmaxf(x, __shfl_xor_sync(0xffffffffu, x, o));
        if (lane == 0) sred[0] = x;
    }
    __syncthreads();
    m = sred[0];
    __syncthreads();

    float sum = 0.f;
#pragma unroll
    for (int j = 0; j < 4; j++) {
        int idx = tid + j * 256;
        if (idx < len) { v[j] = __expf(v[j] - m); sum += v[j]; }
    }
#pragma unroll
    for (int o = 16; o; o >>= 1) sum += __shfl_xor_sync(0xffffffffu, sum, o);
    if (lane == 0) sred[warp] = sum;
    __syncthreads();
    if (tid < 32) {
        float x = (lane < 8) ? sred[lane] : 0.f;
#pragma unroll
        for (int o = 4; o; o >>= 1) x += __shfl_xor_sync(0xffffffffu, x, o);
        if (lane == 0) sred[0] = x;
    }
    __syncthreads();
    float inv = 1.f / sred[0];

    size_t base = (size_t)row * SC;
#pragma unroll
    for (int j = 0; j < 4; j++) {
        int idx = tid + j * 256;
        float w = (idx < len) ? v[j] * inv : 0.f;
        __nv_bfloat16 hh = __float2bfloat16(w);
        g_ph[base + idx] = hh;
        g_pl[base + idx] = __float2bfloat16(w - __bfloat162float(hh));
    }
}

// ---------------------------------------------------------------------------
// PV via HMMA bf16x3 (512 threads): attn[bh,t,d] = sum_s P[t,s] V[s,d]
// ---------------------------------------------------------------------------
__global__ __launch_bounds__(512, 1)
void pv_hmma_kernel() {
    extern __shared__ char sm[];
    const uint32_t sbu = smem_u32(sm);
    const int tid = threadIdx.x;
    const int wid = tid >> 5, lane = tid & 31;
    const int warp_m = wid >> 2;
    const int warp_n = wid & 3;

    const int mt = blockIdx.x;
    const int bh = blockIdx.y;
    const int m0 = mt * 128;
    const int ksteps = (mt + 1) * 4;

    const __nv_bfloat16* Ph = g_ph + (size_t)bh * Tt * SC + (size_t)m0 * SC;
    const __nv_bfloat16* Pl = g_pl + (size_t)bh * Tt * SC + (size_t)m0 * SC;
    const __nv_bfloat16* Vh = g_bh + (size_t)6 * NMAT + (size_t)bh * SC * DK;
    const __nv_bfloat16* Vl = g_bl + (size_t)6 * NMAT + (size_t)bh * SC * DK;

    const __nv_bfloat16* gptr[4];
    int gstep[4];
    uint32_t soff[4];
#pragma unroll
    for (int j = 0; j < 4; j++) {
        int c = j * 512 + tid;
        if (c < 1024) {
            int mat = c >> 9;
            int idx = c & 511;
            int r = idx >> 2, c16 = idx & 3;
            gptr[j] = (mat ? Pl : Ph) + (size_t)r * SC + c16 * 8;
            gstep[j] = MM_BK;
            soff[j] = (uint32_t)(mat * PV_MATP + r * MM_LDS_B + c16 * 16);
        } else {
            int q = c - 1024;
            int mat = q >> 9;
            int idx = q & 511;
            int r = idx >> 4, c16 = idx & 15;
            gptr[j] = (mat ? Vl : Vh) + (size_t)r * DK + c16 * 8;
            gstep[j] = MM_BK * DK;
            soff[j] = (uint32_t)(2 * PV_MATP + mat * PV_MATV + r * PV_LDSV + c16 * 16);
        }
    }

    const uint32_t a_row = (uint32_t)(warp_m * 32 + (lane & 15));
    const uint32_t a_kb  = (uint32_t)(((lane >> 4) << 3) * 2);
    const uint32_t v_row = (uint32_t)(lane & 15);

    float acc[2][4][4];
#pragma unroll
    for (int mi = 0; mi < 2; mi++)
#pragma unroll
        for (int ni = 0; ni < 4; ni++)
#pragma unroll
            for (int q = 0; q < 4; q++) acc[mi][ni][q] = 0.f;

#pragma unroll
    for (int j = 0; j < 4; j++) CP_ASYNC16(sbu + soff[j], gptr[j]);
    CP_COMMIT();

    for (int i = 0; i < ksteps; i++) {
        const int s = i & 1;
        if (i + 1 < ksteps) {
            const uint32_t sb2 = sbu + ((i + 1) & 1) * PV_STAGE;
#pragma unroll
            for (int j = 0; j < 4; j++)
                CP_ASYNC16(sb2 + soff[j], gptr[j] + (size_t)(i + 1) * gstep[j]);
            CP_COMMIT();
            CP_WAIT(1);
        } else {
            CP_WAIT(0);
        }
        __syncthreads();

        const uint32_t stage = sbu + s * PV_STAGE;
        const uint32_t vbase = stage + 2 * PV_MATP;
#pragma unroll
        for (int kk = 0; kk < 2; kk++) {
            uint32_t ah_f[2][4], al_f[2][4], bh_f[4][2], bl_f[4][2];
#pragma unroll
            for (int ni = 0; ni < 4; ni++) {
                uint32_t ncl = (uint32_t)(warp_n * 32 + ni * 8) * 2;
                uint32_t baddr = vbase + (kk * 16 + v_row) * PV_LDSV + ncl;
                ldm_x2_trans(baddr, bh_f[ni]);
                ldm_x2_trans(baddr + PV_MATV, bl_f[ni]);
            }
#pragma unroll
            for (int mi = 0; mi < 2; mi++) {
                uint32_t aaddr = stage + (a_row + mi * 16) * MM_LDS_B + a_kb + (uint32_t)(kk * 32);
                ldm_x4(aaddr, ah_f[mi]);
                ldm_x4(aaddr + PV_MATP, al_f[mi]);
            }
            mma_block_x3(acc, ah_f, al_f, bh_f, bl_f);
        }
        __syncthreads();
    }

    const int b = bh >> 4, h = bh & (Hh - 1);
    const int gid = lane >> 2, tc = lane & 3;
#pragma unroll
    for (int mi = 0; mi < 2; mi++) {
#pragma unroll
        for (int ni = 0; ni < 4; ni++) {
            int mrow0 = m0 + warp_m * 32 + mi * 16 + gid;
            int d = warp_n * 32 + ni * 8 + tc * 2;
#pragma unroll
            for (int half = 0; half < 2; half++) {
                int t = mrow0 + half * 8;
                float v0 = acc[mi][ni][half * 2 + 0];
                float v1 = acc[mi][ni][half * 2 + 1];
                size_t idx = (((size_t)(b * Tt + t) * Hh) + h) * DK + d;
                split2_store(v0, v1, g_ah + idx, g_al + idx);
            }
        }
    }
}

// ---------------------------------------------------------------------------
extern "C" void kernel_launch(void* const* d_in, const int* in_sizes, int n_in,
                              void* d_out, int out_size) {
    const float* x  = (const float*)d_in[0];
    const float* ck = (const float*)d_in[1];
    const float* cv = (const float*)d_in[2];
    const float* Wq = (const float*)d_in[3];
    const float* Wk = (const float*)d_in[4];
    const float* Wv = (const float*)d_in[5];
    const float* Wo = (const float*)d_in[6];

    float* out  = (float*)d_out;
    float* Kout = out + (size_t)Bb * Tt * Cc;
    float* Vout = Kout + (size_t)Bb * Hh * SS * DK;

    cudaFuncSetAttribute(mm_hmma_kernel, cudaFuncAttributeMaxDynamicSharedMemorySize, MM_SMEM);
    cudaFuncSetAttribute(scores_hmma_kernel, cudaFuncAttributeMaxDynamicSharedMemorySize, MM_SMEM);
    cudaFuncSetAttribute(pv_hmma_kernel, cudaFuncAttributeMaxDynamicSharedMemorySize, PV_SMEM);

    copy_cache_kernel<<<4096, 256>>>((const float4*)ck, (const float4*)cv,
                                     (float4*)Kout, (float4*)Vout);
    convert7_kernel<<<28672, 256>>>((const float4*)x, (const float4*)Wq,
                                    (const float4*)Wk, (const float4*)Wv,
                                    (const float4*)Wo, (const float4*)ck,
                                    (const float4*)cv);
    mm_hmma_kernel<<<dim3(16, 16, 3), 512, MM_SMEM>>>(0, Kout, Vout, out);
    scores_hmma_kernel<<<dim3(8, 8, 32), 512, MM_SMEM>>>();
    softmax_kernel<<<Bb * Hh * Tt, 256>>>();
    pv_hmma_kernel<<<dim3(8, 32), 512, PV_SMEM>>>();
    mm_hmma_kernel<<<dim3(16, 16, 1), 512, MM_SMEM>>>(1, Kout, Vout, out);
}

// round 8
// speedup vs baseline: 1.2998x; 1.2996x over previous
#include <cuda_runtime.h>
#include <cuda_fp16.h>
#include <math.h>
#include <stdint.h>

// Problem dims
#define Bb 2
#define Tt 1024
#define Cc 2048
#define Hh 16
#define DK 128
#define SC 1024
#define SS 2048
#define KDIM 2048
#define NMAT 4194304ull   // 2048*2048

#define RSQRT_DK 0.08838834764831845f

// HMMA GEMM tiling (128x128 CTA tile, 16 warps 4x4, warp tile 32x32, BK=32)
#define MM_BK 32
#define MM_LDS_B 80                       // bytes per smem row (32 fp16 + 16 pad)
#define MM_MAT_BYTES (128 * MM_LDS_B)     // 10240
#define MM_STAGE_BYTES (3 * MM_MAT_BYTES) // 30720 (Ah, Al, B)
#define MM_SMEM (2 * MM_STAGE_BYTES)      // 61440
#define MM_KSTEPS (KDIM / MM_BK)          // 64
#define SC_KSTEPS (DK / MM_BK)            // 4

// PV tiling: A = P [128 x 32] (hi+lo), B = V [32 x 128] single (ldmatrix.trans)
#define PV_LDSV 272                       // 128 fp16 (256B) + 16 pad
#define PV_MATP MM_MAT_BYTES              // 10240
#define PV_MATV (32 * PV_LDSV)            // 8704
#define PV_STAGE (2 * PV_MATP + PV_MATV)  // 29184
#define PV_SMEM (2 * PV_STAGE)            // 58368

// ---------------------------------------------------------------------------
// Scratch (device globals)
// ---------------------------------------------------------------------------
__device__ float g_scores[(size_t)Bb * Hh * Tt * SC];     // [bh,t,s]
__device__ __half g_xh[NMAT];                             // x hi
__device__ __half g_xl[NMAT];                             // x lo
__device__ __half g_w4[4 * NMAT];                         // Wq,Wk,Wv,Wo single fp16
__device__ __half g_kc[NMAT];                             // cache_k single fp16
__device__ __half g_vc[NMAT];                             // cache_v single fp16
__device__ __half g_qh[NMAT];                             // Q hi [bh,t,d] scaled
__device__ __half g_ql[NMAT];                             // Q lo
__device__ __half g_ph[(size_t)Bb * Hh * Tt * SC];        // P hi [bh,t,s]
__device__ __half g_pl[(size_t)Bb * Hh * Tt * SC];        // P lo
__device__ __half g_ah[NMAT];                             // attn hi [b,t,h,d]
__device__ __half g_al[NMAT];                             // attn lo

// ---------------------------------------------------------------------------
// PTX helpers
// ---------------------------------------------------------------------------
__device__ __forceinline__ uint32_t smem_u32(const void* p) {
    uint32_t a;
    asm("{ .reg .u64 t; cvta.to.shared.u64 t, %1; cvt.u32.u64 %0, t; }" : "=r"(a) : "l"(p));
    return a;
}
#define CP_ASYNC16(saddr, gaddr) \
    asm volatile("cp.async.cg.shared.global [%0], [%1], 16;" :: "r"(saddr), "l"(gaddr))
#define CP_COMMIT() asm volatile("cp.async.commit_group;" ::: "memory")
#define CP_WAIT(n)  asm volatile("cp.async.wait_group %0;" :: "n"(n) : "memory")

__device__ __forceinline__ void ldm_x4(uint32_t addr, uint32_t* r) {
    asm volatile("ldmatrix.sync.aligned.m8n8.x4.shared.b16 {%0,%1,%2,%3}, [%4];"
        : "=r"(r[0]), "=r"(r[1]), "=r"(r[2]), "=r"(r[3]) : "r"(addr));
}
__device__ __forceinline__ void ldm_x2(uint32_t addr, uint32_t* r) {
    asm volatile("ldmatrix.sync.aligned.m8n8.x2.shared.b16 {%0,%1}, [%2];"
        : "=r"(r[0]), "=r"(r[1]) : "r"(addr));
}
__device__ __forceinline__ void ldm_x2_trans(uint32_t addr, uint32_t* r) {
    asm volatile("ldmatrix.sync.aligned.m8n8.x2.trans.shared.b16 {%0,%1}, [%2];"
        : "=r"(r[0]), "=r"(r[1]) : "r"(addr));
}
__device__ __forceinline__ void mma_f16(float* d, const uint32_t* a, const uint32_t* b) {
    asm volatile("mma.sync.aligned.m16n8k16.row.col.f32.f16.f16.f32 "
        "{%0,%1,%2,%3}, {%4,%5,%6,%7}, {%8,%9}, {%0,%1,%2,%3};"
        : "+f"(d[0]), "+f"(d[1]), "+f"(d[2]), "+f"(d[3])
        : "r"(a[0]), "r"(a[1]), "r"(a[2]), "r"(a[3]), "r"(b[0]), "r"(b[1]));
}

__device__ __forceinline__ void split2h_store(float v0, float v1,
                                              __half* hi, __half* lo) {
    __half h0 = __float2half(v0);
    __half h1 = __float2half(v1);
    __half l0 = __float2half(v0 - __half2float(h0));
    __half l1 = __float2half(v1 - __half2float(h1));
    *reinterpret_cast<__half2*>(hi) = __halves2half2(h0, h1);
    *reinterpret_cast<__half2*>(lo) = __halves2half2(l0, l1);
}

// fp16x2 MMA block: 2 passes (AhB, AlB) over 2x4 accumulators
__device__ __forceinline__ void mma_block_x2(float acc[2][4][4],
                                             uint32_t ah_f[2][4], uint32_t al_f[2][4],
                                             uint32_t b_f[4][2]) {
#pragma unroll
    for (int mi = 0; mi < 2; mi++)
#pragma unroll
        for (int ni = 0; ni < 4; ni++)
            mma_f16(acc[mi][ni], ah_f[mi], b_f[ni]);
#pragma unroll
    for (int mi = 0; mi < 2; mi++)
#pragma unroll
        for (int ni = 0; ni < 4; ni++)
            mma_f16(acc[mi][ni], al_f[mi], b_f[ni]);
}

// ---------------------------------------------------------------------------
// copy caches -> output K/V slots
// ---------------------------------------------------------------------------
__global__ void copy_cache_kernel(const float4* __restrict__ ck,
                                  const float4* __restrict__ cv,
                                  float4* __restrict__ Kout,
                                  float4* __restrict__ Vout) {
    int i = blockIdx.x * blockDim.x + threadIdx.x;
    const int total = Bb * Hh * SC * DK / 4;
    if (i < total) {
        int pos = i & 31;
        int row = i >> 5;
        int s = row & (SC - 1);
        int bh = row >> 10;
        int dst = (((bh * SS) + s) << 5) + pos;
        Kout[dst] = ck[i];
        Vout[dst] = cv[i];
    }
}

// ---------------------------------------------------------------------------
// conversions: x -> fp16 hi/lo; Wq,Wk,Wv,Wo,cache_k,cache_v -> single fp16
// ---------------------------------------------------------------------------
__global__ void convert7_kernel(const float4* __restrict__ x,
                                const float4* __restrict__ wq,
                                const float4* __restrict__ wk,
                                const float4* __restrict__ wv,
                                const float4* __restrict__ wo,
                                const float4* __restrict__ ck,
                                const float4* __restrict__ cv) {
    int id = blockIdx.x * blockDim.x + threadIdx.x;
    const int per = (int)(NMAT / 4);
    int mat = id / per;
    int rem = id - mat * per;
    const float4* srcs[7] = {x, wq, wk, wv, wo, ck, cv};
    float4 v = srcs[mat][rem];
    if (mat == 0) {
        __half h0 = __float2half(v.x), h1 = __float2half(v.y);
        __half h2 = __float2half(v.z), h3 = __float2half(v.w);
        __half2* dh = reinterpret_cast<__half2*>(g_xh) + rem * 2;
        __half2* dl = reinterpret_cast<__half2*>(g_xl) + rem * 2;
        dh[0] = __halves2half2(h0, h1);
        dh[1] = __halves2half2(h2, h3);
        dl[0] = __halves2half2(__float2half(v.x - __half2float(h0)),
                               __float2half(v.y - __half2float(h1)));
        dl[1] = __halves2half2(__float2half(v.z - __half2float(h2)),
                               __float2half(v.w - __half2float(h3)));
    } else {
        __half* base;
        if (mat <= 4)      base = g_w4 + (size_t)(mat - 1) * NMAT;
        else if (mat == 5) base = g_kc;
        else               base = g_vc;
        __half2* d = reinterpret_cast<__half2*>(base) + rem * 2;
        d[0] = __halves2half2(__float2half(v.x), __float2half(v.y));
        d[1] = __halves2half2(__float2half(v.z), __float2half(v.w));
    }
}

// ---------------------------------------------------------------------------
// HMMA fp16x2 GEMM (512 threads, 16 warps 4x4, warp tile 32x32)
// y[m,n] = sum_k A[m,k]*B[n,k], K=2048
// mode 0: A=x(hi/lo), B=W[proj]; Q -> fp16 hi/lo (scaled), K/V -> d_out fp32
// mode 1: A=attn(hi/lo), B=Wo; -> out fp32
// ---------------------------------------------------------------------------
__global__ __launch_bounds__(512, 1)
void mm_hmma_kernel(int mode, float* __restrict__ Kout, float* __restrict__ Vout,
                    float* __restrict__ out) {
    extern __shared__ char sm[];
    const uint32_t sbu = smem_u32(sm);
    const int tid = threadIdx.x;
    const int wid = tid >> 5, lane = tid & 31;
    const int warp_m = wid >> 2;
    const int warp_n = wid & 3;

    const int proj = blockIdx.z;
    const __half *Ah, *Al, *Bs;
    if (mode == 0) {
        Ah = g_xh;  Al = g_xl;
        Bs = g_w4 + (size_t)proj * NMAT;
    } else {
        Ah = g_ah;  Al = g_al;
        Bs = g_w4 + (size_t)3 * NMAT;
    }
    const int m0 = blockIdx.x * 128, n0 = blockIdx.y * 128;

    // cp.async: 1536 16B chunks per stage, 3 per thread
    const __half* gptr[3];
    uint32_t soff[3];
    {
        const __half* src3[3] = {
            Ah + (size_t)m0 * KDIM, Al + (size_t)m0 * KDIM, Bs + (size_t)n0 * KDIM
        };
#pragma unroll
        for (int j = 0; j < 3; j++) {
            int c = j * 512 + tid;
            int mat = c >> 9;
            int r = (c >> 2) & 127;
            int c16 = c & 3;
            gptr[j] = src3[mat] + (size_t)r * KDIM + c16 * 8;
            soff[j] = (uint32_t)(mat * MM_MAT_BYTES + r * MM_LDS_B + c16 * 16);
        }
    }

    const uint32_t a_row = (uint32_t)(warp_m * 32 + (lane & 15));
    const uint32_t a_kb  = (uint32_t)(((lane >> 4) << 3) * 2);
    const uint32_t b_row = (uint32_t)(warp_n * 32 + (lane & 7));
    const uint32_t b_kb  = (uint32_t)((((lane >> 3) & 1) << 3) * 2);

    float acc[2][4][4];
#pragma unroll
    for (int mi = 0; mi < 2; mi++)
#pragma unroll
        for (int ni = 0; ni < 4; ni++)
#pragma unroll
            for (int q = 0; q < 4; q++) acc[mi][ni][q] = 0.f;

#pragma unroll
    for (int j = 0; j < 3; j++) CP_ASYNC16(sbu + soff[j], gptr[j]);
    CP_COMMIT();

    for (int i = 0; i < MM_KSTEPS; i++) {
        const int s = i & 1;
        if (i + 1 < MM_KSTEPS) {
            const uint32_t sb2 = sbu + ((i + 1) & 1) * MM_STAGE_BYTES;
            const int k0 = (i + 1) * MM_BK;
#pragma unroll
            for (int j = 0; j < 3; j++) CP_ASYNC16(sb2 + soff[j], gptr[j] + k0);
            CP_COMMIT();
            CP_WAIT(1);
        } else {
            CP_WAIT(0);
        }
        __syncthreads();

        const uint32_t stage = sbu + s * MM_STAGE_BYTES;
#pragma unroll
        for (int kk = 0; kk < 2; kk++) {
            const uint32_t kb = (uint32_t)(kk * 32);
            uint32_t ah_f[2][4], al_f[2][4], b_f[4][2];
#pragma unroll
            for (int ni = 0; ni < 4; ni++) {
                uint32_t baddr = stage + 2 * MM_MAT_BYTES +
                                 (b_row + ni * 8) * MM_LDS_B + b_kb + kb;
                ldm_x2(baddr, b_f[ni]);
            }
#pragma unroll
            for (int mi = 0; mi < 2; mi++) {
                uint32_t aaddr = stage + (a_row + mi * 16) * MM_LDS_B + a_kb + kb;
                ldm_x4(aaddr, ah_f[mi]);
                ldm_x4(aaddr + MM_MAT_BYTES, al_f[mi]);
            }
            mma_block_x2(acc, ah_f, al_f, b_f);
        }
        __syncthreads();
    }

    const int gid = lane >> 2, tc = lane & 3;
#pragma unroll
    for (int mi = 0; mi < 2; mi++) {
#pragma unroll
        for (int ni = 0; ni < 4; ni++) {
            int mrow0 = m0 + warp_m * 32 + mi * 16 + gid;
            int ncol  = n0 + warp_n * 32 + ni * 8 + tc * 2;
#pragma unroll
            for (int half = 0; half < 2; half++) {
                int m = mrow0 + half * 8;
                float v0 = acc[mi][ni][half * 2 + 0];
                float v1 = acc[mi][ni][half * 2 + 1];
                if (mode == 0) {
                    int b = m >> 10, t = m & (Tt - 1);
                    int h = ncol >> 7, d = ncol & (DK - 1);
                    if (proj == 0) {
                        size_t qi = (((size_t)(b * Hh + h) * Tt) + t) * DK + d;
                        split2h_store(v0 * RSQRT_DK, v1 * RSQRT_DK, g_qh + qi, g_ql + qi);
                    } else {
                        float* base = (proj == 1) ? Kout : Vout;
                        float* dst = base + (((size_t)(b * Hh + h) * SS) + SC + t) * DK + d;
                        float2 vv; vv.x = v0; vv.y = v1;
                        *reinterpret_cast<float2*>(dst) = vv;
                    }
                } else {
                    float* dst = out + (size_t)m * Cc + ncol;
                    float2 vv; vv.x = v0; vv.y = v1;
                    *reinterpret_cast<float2*>(dst) = vv;
                }
            }
        }
    }
}

// ---------------------------------------------------------------------------
// scores via HMMA fp16x2 (512 threads): scores[bh,t,s] = Q . K, Kdim=128
// ---------------------------------------------------------------------------
__global__ __launch_bounds__(512, 1)
void scores_hmma_kernel() {
    if (blockIdx.y > blockIdx.x) return;
    extern __shared__ char sm[];
    const uint32_t sbu = smem_u32(sm);
    const int tid = threadIdx.x;
    const int wid = tid >> 5, lane = tid & 31;
    const int warp_m = wid >> 2;
    const int warp_n = wid & 3;

    const int bh = blockIdx.z;
    const int m0 = blockIdx.x * 128, n0 = blockIdx.y * 128;

    const __half* gptr[3];
    uint32_t soff[3];
    {
        const __half* src3[3] = {
            g_qh + (size_t)bh * Tt * DK + (size_t)m0 * DK,
            g_ql + (size_t)bh * Tt * DK + (size_t)m0 * DK,
            g_kc + (size_t)bh * SC * DK + (size_t)n0 * DK
        };
#pragma unroll
        for (int j = 0; j < 3; j++) {
            int c = j * 512 + tid;
            int mat = c >> 9;
            int r = (c >> 2) & 127;
            int c16 = c & 3;
            gptr[j] = src3[mat] + (size_t)r * DK + c16 * 8;
            soff[j] = (uint32_t)(mat * MM_MAT_BYTES + r * MM_LDS_B + c16 * 16);
        }
    }

    const uint32_t a_row = (uint32_t)(warp_m * 32 + (lane & 15));
    const uint32_t a_kb  = (uint32_t)(((lane >> 4) << 3) * 2);
    const uint32_t b_row = (uint32_t)(warp_n * 32 + (lane & 7));
    const uint32_t b_kb  = (uint32_t)((((lane >> 3) & 1) << 3) * 2);

    float acc[2][4][4];
#pragma unroll
    for (int mi = 0; mi < 2; mi++)
#pragma unroll
        for (int ni = 0; ni < 4; ni++)
#pragma unroll
            for (int q = 0; q < 4; q++) acc[mi][ni][q] = 0.f;

#pragma unroll
    for (int j = 0; j < 3; j++) CP_ASYNC16(sbu + soff[j], gptr[j]);
    CP_COMMIT();

    for (int i = 0; i < SC_KSTEPS; i++) {
        const int s = i & 1;
        if (i + 1 < SC_KSTEPS) {
            const uint32_t sb2 = sbu + ((i + 1) & 1) * MM_STAGE_BYTES;
            const int k0 = (i + 1) * MM_BK;
#pragma unroll
            for (int j = 0; j < 3; j++) CP_ASYNC16(sb2 + soff[j], gptr[j] + k0);
            CP_COMMIT();
            CP_WAIT(1);
        } else {
            CP_WAIT(0);
        }
        __syncthreads();

        const uint32_t stage = sbu + s * MM_STAGE_BYTES;
#pragma unroll
        for (int kk = 0; kk < 2; kk++) {
            const uint32_t kb = (uint32_t)(kk * 32);
            uint32_t ah_f[2][4], al_f[2][4], b_f[4][2];
#pragma unroll
            for (int ni = 0; ni < 4; ni++) {
                uint32_t baddr = stage + 2 * MM_MAT_BYTES +
                                 (b_row + ni * 8) * MM_LDS_B + b_kb + kb;
                ldm_x2(baddr, b_f[ni]);
            }
#pragma unroll
            for (int mi = 0; mi < 2; mi++) {
                uint32_t aaddr = stage + (a_row + mi * 16) * MM_LDS_B + a_kb + kb;
                ldm_x4(aaddr, ah_f[mi]);
                ldm_x4(aaddr + MM_MAT_BYTES, al_f[mi]);
            }
            mma_block_x2(acc, ah_f, al_f, b_f);
        }
        __syncthreads();
    }

    float* outp = g_scores + (size_t)bh * Tt * SC;
    const int gid = lane >> 2, tc = lane & 3;
#pragma unroll
    for (int mi = 0; mi < 2; mi++) {
#pragma unroll
        for (int ni = 0; ni < 4; ni++) {
            int mrow0 = m0 + warp_m * 32 + mi * 16 + gid;
            int ncol  = n0 + warp_n * 32 + ni * 8 + tc * 2;
#pragma unroll
            for (int half = 0; half < 2; half++) {
                int t = mrow0 + half * 8;
                float2 vv;
                vv.x = acc[mi][ni][half * 2 + 0];
                vv.y = acc[mi][ni][half * 2 + 1];
                *reinterpret_cast<float2*>(outp + (size_t)t * SC + ncol) = vv;
            }
        }
    }
}

// ---------------------------------------------------------------------------
// softmax: fp32 scores in, fp16 hi/lo P out (zero tail)
// ---------------------------------------------------------------------------
__global__ __launch_bounds__(256)
void softmax_kernel() {
    __shared__ float sred[8];
    int row = blockIdx.x;
    int t = row & (Tt - 1);
    int len = t + 1;
    const float* p = g_scores + (size_t)row * SC;
    int tid = threadIdx.x;
    int lane = tid & 31, warp = tid >> 5;

    float v[4];
    float m = -1e30f;
#pragma unroll
    for (int j = 0; j < 4; j++) {
        int idx = tid + j * 256;
        if (idx < len) { v[j] = p[idx]; m = fmaxf(m, v[j]); }
    }
#pragma unroll
    for (int o = 16; o; o >>= 1) m = fmaxf(m, __shfl_xor_sync(0xffffffffu, m, o));
    if (lane == 0) sred[warp] = m;
    __syncthreads();
    if (tid < 32) {
        float x = (lane < 8) ? sred[lane] : -1e30f;
#pragma unroll
        for (int o = 4; o; o >>= 1) x = fmaxf(x, __shfl_xor_sync(0xffffffffu, x, o));
        if (lane == 0) sred[0] = x;
    }
    __syncthreads();
    m = sred[0];
    __syncthreads();

    float sum = 0.f;
#pragma unroll
    for (int j = 0; j < 4; j++) {
        int idx = tid + j * 256;
        if (idx < len) { v[j] = __expf(v[j] - m); sum += v[j]; }
    }
#pragma unroll
    for (int o = 16; o; o >>= 1) sum += __shfl_xor_sync(0xffffffffu, sum, o);
    if (lane == 0) sred[warp] = sum;
    __syncthreads();
    if (tid < 32) {
        float x = (lane < 8) ? sred[lane] : 0.f;
#pragma unroll
        for (int o = 4; o; o >>= 1) x += __shfl_xor_sync(0xffffffffu, x, o);
        if (lane == 0) sred[0] = x;
    }
    __syncthreads();
    float inv = 1.f / sred[0];

    size_t base = (size_t)row * SC;
#pragma unroll
    for (int j = 0; j < 4; j++) {
        int idx = tid + j * 256;
        float w = (idx < len) ? v[j] * inv : 0.f;
        __half hh = __float2half(w);
        g_ph[base + idx] = hh;
        g_pl[base + idx] = __float2half(w - __half2float(hh));
    }
}

// ---------------------------------------------------------------------------
// PV via HMMA fp16x2 (512 threads): attn[bh,t,d] = sum_s P[t,s] V[s,d]
// V native [s,d] via ldmatrix.trans (single fp16). Causal k-limit.
// ---------------------------------------------------------------------------
__global__ __launch_bounds__(512, 1)
void pv_hmma_kernel() {
    extern __shared__ char sm[];
    const uint32_t sbu = smem_u32(sm);
    const int tid = threadIdx.x;
    const int wid = tid >> 5, lane = tid & 31;
    const int warp_m = wid >> 2;
    const int warp_n = wid & 3;

    const int mt = blockIdx.x;
    const int bh = blockIdx.y;
    const int m0 = mt * 128;
    const int ksteps = (mt + 1) * 4;

    const __half* Ph = g_ph + (size_t)bh * Tt * SC + (size_t)m0 * SC;
    const __half* Pl = g_pl + (size_t)bh * Tt * SC + (size_t)m0 * SC;
    const __half* Vs = g_vc + (size_t)bh * SC * DK;

    const __half* gptr[3];
    int gstep[3];
    uint32_t soff[3];
#pragma unroll
    for (int j = 0; j < 3; j++) {
        int c = j * 512 + tid;
        if (c < 1024) {
            int mat = c >> 9;
            int idx = c & 511;
            int r = idx >> 2, c16 = idx & 3;
            gptr[j] = (mat ? Pl : Ph) + (size_t)r * SC + c16 * 8;
            gstep[j] = MM_BK;
            soff[j] = (uint32_t)(mat * PV_MATP + r * MM_LDS_B + c16 * 16);
        } else {
            int idx = c - 1024;                 // 0..511
            int r = idx >> 4, c16 = idx & 15;
            gptr[j] = Vs + (size_t)r * DK + c16 * 8;
            gstep[j] = MM_BK * DK;
            soff[j] = (uint32_t)(2 * PV_MATP + r * PV_LDSV + c16 * 16);
        }
    }

    const uint32_t a_row = (uint32_t)(warp_m * 32 + (lane & 15));
    const uint32_t a_kb  = (uint32_t)(((lane >> 4) << 3) * 2);
    const uint32_t v_row = (uint32_t)(lane & 15);

    float acc[2][4][4];
#pragma unroll
    for (int mi = 0; mi < 2; mi++)
#pragma unroll
        for (int ni = 0; ni < 4; ni++)
#pragma unroll
            for (int q = 0; q < 4; q++) acc[mi][ni][q] = 0.f;

#pragma unroll
    for (int j = 0; j < 3; j++) CP_ASYNC16(sbu + soff[j], gptr[j]);
    CP_COMMIT();

    for (int i = 0; i < ksteps; i++) {
        const int s = i & 1;
        if (i + 1 < ksteps) {
            const uint32_t sb2 = sbu + ((i + 1) & 1) * PV_STAGE;
#pragma unroll
            for (int j = 0; j < 3; j++)
                CP_ASYNC16(sb2 + soff[j], gptr[j] + (size_t)(i + 1) * gstep[j]);
            CP_COMMIT();
            CP_WAIT(1);
        } else {
            CP_WAIT(0);
        }
        __syncthreads();

        const uint32_t stage = sbu + s * PV_STAGE;
        const uint32_t vbase = stage + 2 * PV_MATP;
#pragma unroll
        for (int kk = 0; kk < 2; kk++) {
            uint32_t ah_f[2][4], al_f[2][4], b_f[4][2];
#pragma unroll
            for (int ni = 0; ni < 4; ni++) {
                uint32_t ncl = (uint32_t)(warp_n * 32 + ni * 8) * 2;
                uint32_t baddr = vbase + (kk * 16 + v_row) * PV_LDSV + ncl;
                ldm_x2_trans(baddr, b_f[ni]);
            }
#pragma unroll
            for (int mi = 0; mi < 2; mi++) {
                uint32_t aaddr = stage + (a_row + mi * 16) * MM_LDS_B + a_kb + (uint32_t)(kk * 32);
                ldm_x4(aaddr, ah_f[mi]);
                ldm_x4(aaddr + PV_MATP, al_f[mi]);
            }
            mma_block_x2(acc, ah_f, al_f, b_f);
        }
        __syncthreads();
    }

    const int b = bh >> 4, h = bh & (Hh - 1);
    const int gid = lane >> 2, tc = lane & 3;
#pragma unroll
    for (int mi = 0; mi < 2; mi++) {
#pragma unroll
        for (int ni = 0; ni < 4; ni++) {
            int mrow0 = m0 + warp_m * 32 + mi * 16 + gid;
            int d = warp_n * 32 + ni * 8 + tc * 2;
#pragma unroll
            for (int half = 0; half < 2; half++) {
                int t = mrow0 + half * 8;
                float v0 = acc[mi][ni][half * 2 + 0];
                float v1 = acc[mi][ni][half * 2 + 1];
                size_t idx = (((size_t)(b * Tt + t) * Hh) + h) * DK + d;
                split2h_store(v0, v1, g_ah + idx, g_al + idx);
            }
        }
    }
}

// ---------------------------------------------------------------------------
extern "C" void kernel_launch(void* const* d_in, const int* in_sizes, int n_in,
                              void* d_out, int out_size) {
    const float* x  = (const float*)d_in[0];
    const float* ck = (const float*)d_in[1];
    const float* cv = (const float*)d_in[2];
    const float* Wq = (const float*)d_in[3];
    const float* Wk = (const float*)d_in[4];
    const float* Wv = (const float*)d_in[5];
    const float* Wo = (const float*)d_in[6];

    float* out  = (float*)d_out;
    float* Kout = out + (size_t)Bb * Tt * Cc;
    float* Vout = Kout + (size_t)Bb * Hh * SS * DK;

    cudaFuncSetAttribute(mm_hmma_kernel, cudaFuncAttributeMaxDynamicSharedMemorySize, MM_SMEM);
    cudaFuncSetAttribute(scores_hmma_kernel, cudaFuncAttributeMaxDynamicSharedMemorySize, MM_SMEM);
    cudaFuncSetAttribute(pv_hmma_kernel, cudaFuncAttributeMaxDynamicSharedMemorySize, PV_SMEM);

    copy_cache_kernel<<<4096, 256>>>((const float4*)ck, (const float4*)cv,
                                     (float4*)Kout, (float4*)Vout);
    convert7_kernel<<<28672, 256>>>((const float4*)x, (const float4*)Wq,
                                    (const float4*)Wk, (const float4*)Wv,
                                    (const float4*)Wo, (const float4*)ck,
                                    (const float4*)cv);
    mm_hmma_kernel<<<dim3(16, 16, 3), 512, MM_SMEM>>>(0, Kout, Vout, out);
    scores_hmma_kernel<<<dim3(8, 8, 32), 512, MM_SMEM>>>();
    softmax_kernel<<<Bb * Hh * Tt, 256>>>();
    pv_hmma_kernel<<<dim3(8, 32), 512, PV_SMEM>>>();
    mm_hmma_kernel<<<dim3(16, 16, 1), 512, MM_SMEM>>>(1, Kout, Vout, out);
}

// round 9
// speedup vs baseline: 1.3106x; 1.0083x over previous
#include <cuda_runtime.h>
#include <cuda_fp16.h>
#include <math.h>
#include <stdint.h>

// Problem dims
#define Bb 2
#define Tt 1024
#define Cc 2048
#define Hh 16
#define DK 128
#define SC 1024
#define SS 2048
#define KDIM 2048
#define NMAT 4194304ull   // 2048*2048

#define RSQRT_DK 0.08838834764831845f

// HMMA GEMM tiling: CTA tile 128(M) x 64(N) x 32(K), 256 threads, 8 warps 4x2,
// warp tile 32x32. 2 CTAs/SM.
#define MM_BK 32
#define MM_LDS_B 80                        // bytes per smem row (32 fp16 + 16 pad)
#define MM_MATA 10240                      // 128 rows * 80
#define MM_MATB 5120                       // 64 rows * 80
#define MM_STAGE (2 * MM_MATA + MM_MATB)   // 25600 (Ah, Al, B)
#define MM_SMEM (2 * MM_STAGE)             // 51200
#define MM_KSTEPS (KDIM / MM_BK)           // 64
#define SC_KSTEPS (DK / MM_BK)             // 4

// PV tiling: A = P [128 x 32] hi/lo, B = V [32 k-rows x 64 d-cols] (trans)
#define PV_LDSV 144                        // 64 fp16 (128B) + 16 pad
#define PV_MATP MM_MATA                    // 10240
#define PV_MATV (32 * PV_LDSV)             // 4608
#define PV_STAGE (2 * PV_MATP + PV_MATV)   // 25088
#define PV_SMEM (2 * PV_STAGE)             // 50176

// ---------------------------------------------------------------------------
// Scratch (device globals)
// ---------------------------------------------------------------------------
__device__ float g_scores[(size_t)Bb * Hh * Tt * SC];     // [bh,t,s]
__device__ __half g_xh[NMAT];                             // x hi
__device__ __half g_xl[NMAT];                             // x lo
__device__ __half g_w4[4 * NMAT];                         // Wq,Wk,Wv,Wo fp16
__device__ __half g_kc[NMAT];                             // cache_k fp16
__device__ __half g_vc[NMAT];                             // cache_v fp16
__device__ __half g_qh[NMAT];                             // Q hi [bh,t,d] scaled
__device__ __half g_ql[NMAT];                             // Q lo
__device__ __half g_ph[(size_t)Bb * Hh * Tt * SC];        // P hi [bh,t,s]
__device__ __half g_pl[(size_t)Bb * Hh * Tt * SC];        // P lo
__device__ __half g_ah[NMAT];                             // attn hi [b,t,h,d]
__device__ __half g_al[NMAT];                             // attn lo

// ---------------------------------------------------------------------------
// PTX helpers
// ---------------------------------------------------------------------------
__device__ __forceinline__ uint32_t smem_u32(const void* p) {
    uint32_t a;
    asm("{ .reg .u64 t; cvta.to.shared.u64 t, %1; cvt.u32.u64 %0, t; }" : "=r"(a) : "l"(p));
    return a;
}
#define CP_ASYNC16(saddr, gaddr) \
    asm volatile("cp.async.cg.shared.global [%0], [%1], 16;" :: "r"(saddr), "l"(gaddr))
#define CP_COMMIT() asm volatile("cp.async.commit_group;" ::: "memory")
#define CP_WAIT(n)  asm volatile("cp.async.wait_group %0;" :: "n"(n) : "memory")

__device__ __forceinline__ void ldm_x4(uint32_t addr, uint32_t* r) {
    asm volatile("ldmatrix.sync.aligned.m8n8.x4.shared.b16 {%0,%1,%2,%3}, [%4];"
        : "=r"(r[0]), "=r"(r[1]), "=r"(r[2]), "=r"(r[3]) : "r"(addr));
}
__device__ __forceinline__ void ldm_x2(uint32_t addr, uint32_t* r) {
    asm volatile("ldmatrix.sync.aligned.m8n8.x2.shared.b16 {%0,%1}, [%2];"
        : "=r"(r[0]), "=r"(r[1]) : "r"(addr));
}
__device__ __forceinline__ void ldm_x2_trans(uint32_t addr, uint32_t* r) {
    asm volatile("ldmatrix.sync.aligned.m8n8.x2.trans.shared.b16 {%0,%1}, [%2];"
        : "=r"(r[0]), "=r"(r[1]) : "r"(addr));
}
__device__ __forceinline__ void mma_f16(float* d, const uint32_t* a, const uint32_t* b) {
    asm volatile("mma.sync.aligned.m16n8k16.row.col.f32.f16.f16.f32 "
        "{%0,%1,%2,%3}, {%4,%5,%6,%7}, {%8,%9}, {%0,%1,%2,%3};"
        : "+f"(d[0]), "+f"(d[1]), "+f"(d[2]), "+f"(d[3])
        : "r"(a[0]), "r"(a[1]), "r"(a[2]), "r"(a[3]), "r"(b[0]), "r"(b[1]));
}

__device__ __forceinline__ void split2h_store(float v0, float v1,
                                              __half* hi, __half* lo) {
    __half h0 = __float2half(v0);
    __half h1 = __float2half(v1);
    __half l0 = __float2half(v0 - __half2float(h0));
    __half l1 = __float2half(v1 - __half2float(h1));
    *reinterpret_cast<__half2*>(hi) = __halves2half2(h0, h1);
    *reinterpret_cast<__half2*>(lo) = __halves2half2(l0, l1);
}

// fp16x2 MMA block: 2 passes (AhB, AlB) over 2x4 accumulators
__device__ __forceinline__ void mma_block_x2(float acc[2][4][4],
                                             uint32_t ah_f[2][4], uint32_t al_f[2][4],
                                             uint32_t b_f[4][2]) {
#pragma unroll
    for (int mi = 0; mi < 2; mi++)
#pragma unroll
        for (int ni = 0; ni < 4; ni++)
            mma_f16(acc[mi][ni], ah_f[mi], b_f[ni]);
#pragma unroll
    for (int mi = 0; mi < 2; mi++)
#pragma unroll
        for (int ni = 0; ni < 4; ni++)
            mma_f16(acc[mi][ni], al_f[mi], b_f[ni]);
}

// ---------------------------------------------------------------------------
// conversions (fused with cache copy): x -> fp16 hi/lo; W* -> fp16;
// ck/cv -> fp16 AND fp32 copy into output K/V slots
// ---------------------------------------------------------------------------
__global__ void convert7_kernel(const float4* __restrict__ x,
                                const float4* __restrict__ wq,
                                const float4* __restrict__ wk,
                                const float4* __restrict__ wv,
                                const float4* __restrict__ wo,
                                const float4* __restrict__ ck,
                                const float4* __restrict__ cv,
                                float4* __restrict__ Kout,
                                float4* __restrict__ Vout) {
    int id = blockIdx.x * blockDim.x + threadIdx.x;
    const int per = (int)(NMAT / 4);
    int mat = id / per;
    int rem = id - mat * per;
    const float4* srcs[7] = {x, wq, wk, wv, wo, ck, cv};
    float4 v = srcs[mat][rem];
    if (mat == 0) {
        __half h0 = __float2half(v.x), h1 = __float2half(v.y);
        __half h2 = __float2half(v.z), h3 = __float2half(v.w);
        __half2* dh = reinterpret_cast<__half2*>(g_xh) + rem * 2;
        __half2* dl = reinterpret_cast<__half2*>(g_xl) + rem * 2;
        dh[0] = __halves2half2(h0, h1);
        dh[1] = __halves2half2(h2, h3);
        dl[0] = __halves2half2(__float2half(v.x - __half2float(h0)),
                               __float2half(v.y - __half2float(h1)));
        dl[1] = __halves2half2(__float2half(v.z - __half2float(h2)),
                               __float2half(v.w - __half2float(h3)));
    } else {
        __half* base;
        if (mat <= 4)      base = g_w4 + (size_t)(mat - 1) * NMAT;
        else if (mat == 5) base = g_kc;
        else               base = g_vc;
        __half2* d = reinterpret_cast<__half2*>(base) + rem * 2;
        d[0] = __halves2half2(__float2half(v.x), __float2half(v.y));
        d[1] = __halves2half2(__float2half(v.z), __float2half(v.w));
        if (mat >= 5) {
            // fused cache -> output copy
            int pos = rem & 31;
            int row = rem >> 5;
            int s = row & (SC - 1);
            int bh = row >> 10;
            int dst = (((bh * SS) + s) << 5) + pos;
            ((mat == 5) ? Kout : Vout)[dst] = v;
        }
    }
}

// ---------------------------------------------------------------------------
// HMMA fp16x2 GEMM (256 threads, 8 warps 4x2, CTA tile 128x64, 2 CTAs/SM)
// mode 0: A=x(hi/lo), B=W[proj]; Q -> fp16 hi/lo (scaled), K/V -> d_out fp32
// mode 1: A=attn(hi/lo), B=Wo; -> out fp32
// ---------------------------------------------------------------------------
__global__ __launch_bounds__(256, 2)
void mm_hmma_kernel(int mode, float* __restrict__ Kout, float* __restrict__ Vout,
                    float* __restrict__ out) {
    extern __shared__ char sm[];
    const uint32_t sbu = smem_u32(sm);
    const int tid = threadIdx.x;
    const int wid = tid >> 5, lane = tid & 31;
    const int warp_m = wid >> 1;          // 0..3
    const int warp_n = wid & 1;           // 0..1

    const int proj = blockIdx.z;
    const __half *Ah, *Al, *Bs;
    if (mode == 0) {
        Ah = g_xh;  Al = g_xl;
        Bs = g_w4 + (size_t)proj * NMAT;
    } else {
        Ah = g_ah;  Al = g_al;
        Bs = g_w4 + (size_t)3 * NMAT;
    }
    const int m0 = blockIdx.x * 128, n0 = blockIdx.y * 64;

    // cp.async: 1280 16B chunks per stage, 5 per thread
    const __half* gptr[5];
    uint32_t soff[5];
#pragma unroll
    for (int j = 0; j < 5; j++) {
        int c = j * 256 + tid;
        if (c < 1024) {
            int mat = c >> 9;
            int idx = c & 511;
            int r = idx >> 2, c16 = idx & 3;
            gptr[j] = (mat ? Al : Ah) + (size_t)(m0 + r) * KDIM + c16 * 8;
            soff[j] = (uint32_t)(mat * MM_MATA + r * MM_LDS_B + c16 * 16);
        } else {
            int idx = c - 1024;            // 0..255
            int r = idx >> 2, c16 = idx & 3;
            gptr[j] = Bs + (size_t)(n0 + r) * KDIM + c16 * 8;
            soff[j] = (uint32_t)(2 * MM_MATA + r * MM_LDS_B + c16 * 16);
        }
    }

    const uint32_t a_row = (uint32_t)(warp_m * 32 + (lane & 15));
    const uint32_t a_kb  = (uint32_t)(((lane >> 4) << 3) * 2);
    const uint32_t b_row = (uint32_t)(warp_n * 32 + (lane & 7));
    const uint32_t b_kb  = (uint32_t)((((lane >> 3) & 1) << 3) * 2);

    float acc[2][4][4];
#pragma unroll
    for (int mi = 0; mi < 2; mi++)
#pragma unroll
        for (int ni = 0; ni < 4; ni++)
#pragma unroll
            for (int q = 0; q < 4; q++) acc[mi][ni][q] = 0.f;

#pragma unroll
    for (int j = 0; j < 5; j++) CP_ASYNC16(sbu + soff[j], gptr[j]);
    CP_COMMIT();

    for (int i = 0; i < MM_KSTEPS; i++) {
        const int s = i & 1;
        if (i + 1 < MM_KSTEPS) {
            const uint32_t sb2 = sbu + ((i + 1) & 1) * MM_STAGE;
            const int k0 = (i + 1) * MM_BK;
#pragma unroll
            for (int j = 0; j < 5; j++) CP_ASYNC16(sb2 + soff[j], gptr[j] + k0);
            CP_COMMIT();
            CP_WAIT(1);
        } else {
            CP_WAIT(0);
        }
        __syncthreads();

        const uint32_t stage = sbu + s * MM_STAGE;
#pragma unroll
        for (int kk = 0; kk < 2; kk++) {
            const uint32_t kb = (uint32_t)(kk * 32);
            uint32_t ah_f[2][4], al_f[2][4], b_f[4][2];
#pragma unroll
            for (int ni = 0; ni < 4; ni++) {
                uint32_t baddr = stage + 2 * MM_MATA +
                                 (b_row + ni * 8) * MM_LDS_B + b_kb + kb;
                ldm_x2(baddr, b_f[ni]);
            }
#pragma unroll
            for (int mi = 0; mi < 2; mi++) {
                uint32_t aaddr = stage + (a_row + mi * 16) * MM_LDS_B + a_kb + kb;
                ldm_x4(aaddr, ah_f[mi]);
                ldm_x4(aaddr + MM_MATA, al_f[mi]);
            }
            mma_block_x2(acc, ah_f, al_f, b_f);
        }
        __syncthreads();
    }

    const int gid = lane >> 2, tc = lane & 3;
#pragma unroll
    for (int mi = 0; mi < 2; mi++) {
#pragma unroll
        for (int ni = 0; ni < 4; ni++) {
            int mrow0 = m0 + warp_m * 32 + mi * 16 + gid;
            int ncol  = n0 + warp_n * 32 + ni * 8 + tc * 2;
#pragma unroll
            for (int half = 0; half < 2; half++) {
                int m = mrow0 + half * 8;
                float v0 = acc[mi][ni][half * 2 + 0];
                float v1 = acc[mi][ni][half * 2 + 1];
                if (mode == 0) {
                    int b = m >> 10, t = m & (Tt - 1);
                    int h = ncol >> 7, d = ncol & (DK - 1);
                    if (proj == 0) {
                        size_t qi = (((size_t)(b * Hh + h) * Tt) + t) * DK + d;
                        split2h_store(v0 * RSQRT_DK, v1 * RSQRT_DK, g_qh + qi, g_ql + qi);
                    } else {
                        float* base = (proj == 1) ? Kout : Vout;
                        float* dst = base + (((size_t)(b * Hh + h) * SS) + SC + t) * DK + d;
                        float2 vv; vv.x = v0; vv.y = v1;
                        *reinterpret_cast<float2*>(dst) = vv;
                    }
                } else {
                    float* dst = out + (size_t)m * Cc + ncol;
                    float2 vv; vv.x = v0; vv.y = v1;
                    *reinterpret_cast<float2*>(dst) = vv;
                }
            }
        }
    }
}

// ---------------------------------------------------------------------------
// scores via HMMA fp16x2 (256 threads, CTA tile 128x64): Q . K, Kdim=128
// ---------------------------------------------------------------------------
__global__ __launch_bounds__(256, 2)
void scores_hmma_kernel() {
    if ((blockIdx.y >> 1) > blockIdx.x) return;   // fully-masked tile
    extern __shared__ char sm[];
    const uint32_t sbu = smem_u32(sm);
    const int tid = threadIdx.x;
    const int wid = tid >> 5, lane = tid & 31;
    const int warp_m = wid >> 1;
    const int warp_n = wid & 1;

    const int bh = blockIdx.z;
    const int m0 = blockIdx.x * 128, n0 = blockIdx.y * 64;

    const __half* Qh = g_qh + (size_t)bh * Tt * DK;
    const __half* Ql = g_ql + (size_t)bh * Tt * DK;
    const __half* Ks = g_kc + (size_t)bh * SC * DK;

    const __half* gptr[5];
    uint32_t soff[5];
#pragma unroll
    for (int j = 0; j < 5; j++) {
        int c = j * 256 + tid;
        if (c < 1024) {
            int mat = c >> 9;
            int idx = c & 511;
            int r = idx >> 2, c16 = idx & 3;
            gptr[j] = (mat ? Ql : Qh) + (size_t)(m0 + r) * DK + c16 * 8;
            soff[j] = (uint32_t)(mat * MM_MATA + r * MM_LDS_B + c16 * 16);
        } else {
            int idx = c - 1024;
            int r = idx >> 2, c16 = idx & 3;
            gptr[j] = Ks + (size_t)(n0 + r) * DK + c16 * 8;
            soff[j] = (uint32_t)(2 * MM_MATA + r * MM_LDS_B + c16 * 16);
        }
    }

    const uint32_t a_row = (uint32_t)(warp_m * 32 + (lane & 15));
    const uint32_t a_kb  = (uint32_t)(((lane >> 4) << 3) * 2);
    const uint32_t b_row = (uint32_t)(warp_n * 32 + (lane & 7));
    const uint32_t b_kb  = (uint32_t)((((lane >> 3) & 1) << 3) * 2);

    float acc[2][4][4];
#pragma unroll
    for (int mi = 0; mi < 2; mi++)
#pragma unroll
        for (int ni = 0; ni < 4; ni++)
#pragma unroll
            for (int q = 0; q < 4; q++) acc[mi][ni][q] = 0.f;

#pragma unroll
    for (int j = 0; j < 5; j++) CP_ASYNC16(sbu + soff[j], gptr[j]);
    CP_COMMIT();

    for (int i = 0; i < SC_KSTEPS; i++) {
        const int s = i & 1;
        if (i + 1 < SC_KSTEPS) {
            const uint32_t sb2 = sbu + ((i + 1) & 1) * MM_STAGE;
            const int k0 = (i + 1) * MM_BK;
#pragma unroll
            for (int j = 0; j < 5; j++) CP_ASYNC16(sb2 + soff[j], gptr[j] + k0);
            CP_COMMIT();
            CP_WAIT(1);
        } else {
            CP_WAIT(0);
        }
        __syncthreads();

        const uint32_t stage = sbu + s * MM_STAGE;
#pragma unroll
        for (int kk = 0; kk < 2; kk++) {
            const uint32_t kb = (uint32_t)(kk * 32);
            uint32_t ah_f[2][4], al_f[2][4], b_f[4][2];
#pragma unroll
            for (int ni = 0; ni < 4; ni++) {
                uint32_t baddr = stage + 2 * MM_MATA +
                                 (b_row + ni * 8) * MM_LDS_B + b_kb + kb;
                ldm_x2(baddr, b_f[ni]);
            }
#pragma unroll
            for (int mi = 0; mi < 2; mi++) {
                uint32_t aaddr = stage + (a_row + mi * 16) * MM_LDS_B + a_kb + kb;
                ldm_x4(aaddr, ah_f[mi]);
                ldm_x4(aaddr + MM_MATA, al_f[mi]);
            }
            mma_block_x2(acc, ah_f, al_f, b_f);
        }
        __syncthreads();
    }

    float* outp = g_scores + (size_t)bh * Tt * SC;
    const int gid = lane >> 2, tc = lane & 3;
#pragma unroll
    for (int mi = 0; mi < 2; mi++) {
#pragma unroll
        for (int ni = 0; ni < 4; ni++) {
            int mrow0 = m0 + warp_m * 32 + mi * 16 + gid;
            int ncol  = n0 + warp_n * 32 + ni * 8 + tc * 2;
#pragma unroll
            for (int half = 0; half < 2; half++) {
                int t = mrow0 + half * 8;
                float2 vv;
                vv.x = acc[mi][ni][half * 2 + 0];
                vv.y = acc[mi][ni][half * 2 + 1];
                *reinterpret_cast<float2*>(outp + (size_t)t * SC + ncol) = vv;
            }
        }
    }
}

// ---------------------------------------------------------------------------
// softmax: fp32 scores in, fp16 hi/lo P out (zero tail)
// ---------------------------------------------------------------------------
__global__ __launch_bounds__(256)
void softmax_kernel() {
    __shared__ float sred[8];
    int row = blockIdx.x;
    int t = row & (Tt - 1);
    int len = t + 1;
    const float* p = g_scores + (size_t)row * SC;
    int tid = threadIdx.x;
    int lane = tid & 31, warp = tid >> 5;

    float v[4];
    float m = -1e30f;
#pragma unroll
    for (int j = 0; j < 4; j++) {
        int idx = tid + j * 256;
        if (idx < len) { v[j] = p[idx]; m = fmaxf(m, v[j]); }
    }
#pragma unroll
    for (int o = 16; o; o >>= 1) m = fmaxf(m, __shfl_xor_sync(0xffffffffu, m, o));
    if (lane == 0) sred[warp] = m;
    __syncthreads();
    if (tid < 32) {
        float x = (lane < 8) ? sred[lane] : -1e30f;
#pragma unroll
        for (int o = 4; o; o >>= 1) x = fmaxf(x, __shfl_xor_sync(0xffffffffu, x, o));
        if (lane == 0) sred[0] = x;
    }
    __syncthreads();
    m = sred[0];
    __syncthreads();

    float sum = 0.f;
#pragma unroll
    for (int j = 0; j < 4; j++) {
        int idx = tid + j * 256;
        if (idx < len) { v[j] = __expf(v[j] - m); sum += v[j]; }
    }
#pragma unroll
    for (int o = 16; o; o >>= 1) sum += __shfl_xor_sync(0xffffffffu, sum, o);
    if (lane == 0) sred[warp] = sum;
    __syncthreads();
    if (tid < 32) {
        float x = (lane < 8) ? sred[lane] : 0.f;
#pragma unroll
        for (int o = 4; o; o >>= 1) x += __shfl_xor_sync(0xffffffffu, x, o);
        if (lane == 0) sred[0] = x;
    }
    __syncthreads();
    float inv = 1.f / sred[0];

    size_t base = (size_t)row * SC;
#pragma unroll
    for (int j = 0; j < 4; j++) {
        int idx = tid + j * 256;
        float w = (idx < len) ? v[j] * inv : 0.f;
        __half hh = __float2half(w);
        g_ph[base + idx] = hh;
        g_pl[base + idx] = __float2half(w - __half2float(hh));
    }
}

// ---------------------------------------------------------------------------
// PV via HMMA fp16x2 (256 threads, CTA 128x64): attn = P @ V, causal k-limit
// V native [s,d] via ldmatrix.trans (single fp16)
// ---------------------------------------------------------------------------
__global__ __launch_bounds__(256, 2)
void pv_hmma_kernel() {
    extern __shared__ char sm[];
    const uint32_t sbu = smem_u32(sm);
    const int tid = threadIdx.x;
    const int wid = tid >> 5, lane = tid & 31;
    const int warp_m = wid >> 1;
    const int warp_n = wid & 1;

    const int mt = blockIdx.x;
    const int n0 = blockIdx.y * 64;       // d-tile
    const int bh = blockIdx.z;
    const int m0 = mt * 128;
    const int ksteps = (mt + 1) * 4;

    const __half* Ph = g_ph + (size_t)bh * Tt * SC + (size_t)m0 * SC;
    const __half* Pl = g_pl + (size_t)bh * Tt * SC + (size_t)m0 * SC;
    const __half* Vs = g_vc + (size_t)bh * SC * DK;

    const __half* gptr[5];
    int gstep[5];
    uint32_t soff[5];
#pragma unroll
    for (int j = 0; j < 5; j++) {
        int c = j * 256 + tid;
        if (c < 1024) {
            int mat = c >> 9;
            int idx = c & 511;
            int r = idx >> 2, c16 = idx & 3;
            gptr[j] = (mat ? Pl : Ph) + (size_t)r * SC + c16 * 8;
            gstep[j] = MM_BK;
            soff[j] = (uint32_t)(mat * PV_MATP + r * MM_LDS_B + c16 * 16);
        } else {
            int idx = c - 1024;            // 0..255
            int r = idx >> 3, c8 = idx & 7;
            gptr[j] = Vs + (size_t)r * DK + n0 + c8 * 8;
            gstep[j] = MM_BK * DK;
            soff[j] = (uint32_t)(2 * PV_MATP + r * PV_LDSV + c8 * 16);
        }
    }

    const uint32_t a_row = (uint32_t)(warp_m * 32 + (lane & 15));
    const uint32_t a_kb  = (uint32_t)(((lane >> 4) << 3) * 2);
    const uint32_t v_row = (uint32_t)(lane & 15);

    float acc[2][4][4];
#pragma unroll
    for (int mi = 0; mi < 2; mi++)
#pragma unroll
        for (int ni = 0; ni < 4; ni++)
#pragma unroll
            for (int q = 0; q < 4; q++) acc[mi][ni][q] = 0.f;

#pragma unroll
    for (int j = 0; j < 5; j++) CP_ASYNC16(sbu + soff[j], gptr[j]);
    CP_COMMIT();

    for (int i = 0; i < ksteps; i++) {
        const int s = i & 1;
        if (i + 1 < ksteps) {
            const uint32_t sb2 = sbu + ((i + 1) & 1) * PV_STAGE;
#pragma unroll
            for (int j = 0; j < 5; j++)
                CP_ASYNC16(sb2 + soff[j], gptr[j] + (size_t)(i + 1) * gstep[j]);
            CP_COMMIT();
            CP_WAIT(1);
        } else {
            CP_WAIT(0);
        }
        __syncthreads();

        const uint32_t stage = sbu + s * PV_STAGE;
        const uint32_t vbase = stage + 2 * PV_MATP;
#pragma unroll
        for (int kk = 0; kk < 2; kk++) {
            uint32_t ah_f[2][4], al_f[2][4], b_f[4][2];
#pragma unroll
            for (int ni = 0; ni < 4; ni++) {
                uint32_t ncl = (uint32_t)(warp_n * 32 + ni * 8) * 2;
                uint32_t baddr = vbase + (kk * 16 + v_row) * PV_LDSV + ncl;
                ldm_x2_trans(baddr, b_f[ni]);
            }
#pragma unroll
            for (int mi = 0; mi < 2; mi++) {
                uint32_t aaddr = stage + (a_row + mi * 16) * MM_LDS_B + a_kb + (uint32_t)(kk * 32);
                ldm_x4(aaddr, ah_f[mi]);
                ldm_x4(aaddr + PV_MATP, al_f[mi]);
            }
            mma_block_x2(acc, ah_f, al_f, b_f);
        }
        __syncthreads();
    }

    const int b = bh >> 4, h = bh & (Hh - 1);
    const int gid = lane >> 2, tc = lane & 3;
#pragma unroll
    for (int mi = 0; mi < 2; mi++) {
#pragma unroll
        for (int ni = 0; ni < 4; ni++) {
            int mrow0 = m0 + warp_m * 32 + mi * 16 + gid;
            int d = n0 + warp_n * 32 + ni * 8 + tc * 2;
#pragma unroll
            for (int half = 0; half < 2; half++) {
                int t = mrow0 + half * 8;
                float v0 = acc[mi][ni][half * 2 + 0];
                float v1 = acc[mi][ni][half * 2 + 1];
                size_t idx = (((size_t)(b * Tt + t) * Hh) + h) * DK + d;
                split2h_store(v0, v1, g_ah + idx, g_al + idx);
            }
        }
    }
}

// ---------------------------------------------------------------------------
extern "C" void kernel_launch(void* const* d_in, const int* in_sizes, int n_in,
                              void* d_out, int out_size) {
    const float* x  = (const float*)d_in[0];
    const float* ck = (const float*)d_in[1];
    const float* cv = (const float*)d_in[2];
    const float* Wq = (const float*)d_in[3];
    const float* Wk = (const float*)d_in[4];
    const float* Wv = (const float*)d_in[5];
    const float* Wo = (const float*)d_in[6];

    float* out  = (float*)d_out;
    float* Kout = out + (size_t)Bb * Tt * Cc;
    float* Vout = Kout + (size_t)Bb * Hh * SS * DK;

    cudaFuncSetAttribute(mm_hmma_kernel, cudaFuncAttributeMaxDynamicSharedMemorySize, MM_SMEM);
    cudaFuncSetAttribute(scores_hmma_kernel, cudaFuncAttributeMaxDynamicSharedMemorySize, MM_SMEM);
    cudaFuncSetAttribute(pv_hmma_kernel, cudaFuncAttributeMaxDynamicSharedMemorySize, PV_SMEM);

    convert7_kernel<<<28672, 256>>>((const float4*)x, (const float4*)Wq,
                                    (const float4*)Wk, (const float4*)Wv,
                                    (const float4*)Wo, (const float4*)ck,
                                    (const float4*)cv,
                                    (float4*)Kout, (float4*)Vout);
    mm_hmma_kernel<<<dim3(16, 32, 3), 256, MM_SMEM>>>(0, Kout, Vout, out);
    scores_hmma_kernel<<<dim3(8, 16, 32), 256, MM_SMEM>>>();
    softmax_kernel<<<Bb * Hh * Tt, 256>>>();
    pv_hmma_kernel<<<dim3(8, 2, 32), 256, PV_SMEM>>>();
    mm_hmma_kernel<<<dim3(16, 32, 1), 256, MM_SMEM>>>(1, Kout, Vout, out);
}

// round 10
// speedup vs baseline: 1.9998x; 1.5259x over previous
#include <cuda_runtime.h>
#include <cuda_fp16.h>
#include <math.h>
#include <stdint.h>

// Problem dims
#define Bb 2
#define Tt 1024
#define Cc 2048
#define Hh 16
#define DK 128
#define SC 1024
#define SS 2048
#define KDIM 2048
#define NMAT 4194304ull   // 2048*2048

#define RSQRT_DK 0.08838834764831845f

// HMMA GEMM tiling: CTA tile 128(M) x 64(N) x 32(K), 256 threads, 8 warps 4x2,
// warp tile 32x32, single-pass fp16.
#define MM_BK 32
#define MM_LDS_B 80                        // bytes per smem row (32 fp16 + 16 pad)
#define MM_MATA 10240                      // 128 rows * 80
#define MM_MATB 5120                       // 64 rows * 80
#define MM_STAGE (MM_MATA + MM_MATB)       // 15360 (A, B)
#define MM_SMEM (2 * MM_STAGE)             // 30720
#define MM_KSTEPS (KDIM / MM_BK)           // 64
#define SC_KSTEPS (DK / MM_BK)             // 4

// PV tiling: A = P [128 x 32], B = V [32 k-rows x 64 d-cols] (trans)
#define PV_LDSV 144                        // 64 fp16 (128B) + 16 pad
#define PV_MATP MM_MATA                    // 10240
#define PV_MATV (32 * PV_LDSV)             // 4608
#define PV_STAGE (PV_MATP + PV_MATV)       // 14848
#define PV_SMEM (2 * PV_STAGE)             // 29696

// ---------------------------------------------------------------------------
// Scratch (device globals)
// ---------------------------------------------------------------------------
__device__ float g_scores[(size_t)Bb * Hh * Tt * SC];     // [bh,t,s]
__device__ __half g_xh[NMAT];                             // x fp16
__device__ __half g_w4[4 * NMAT];                         // Wq,Wk,Wv,Wo fp16
__device__ __half g_kc[NMAT];                             // cache_k fp16
__device__ __half g_vc[NMAT];                             // cache_v fp16
__device__ __half g_qh[NMAT];                             // Q fp16 [bh,t,d] scaled
__device__ __half g_ph[(size_t)Bb * Hh * Tt * SC];        // P fp16 [bh,t,s]
__device__ __half g_ah[NMAT];                             // attn fp16 [b,t,h,d]

// ---------------------------------------------------------------------------
// PTX helpers
// ---------------------------------------------------------------------------
__device__ __forceinline__ uint32_t smem_u32(const void* p) {
    uint32_t a;
    asm("{ .reg .u64 t; cvta.to.shared.u64 t, %1; cvt.u32.u64 %0, t; }" : "=r"(a) : "l"(p));
    return a;
}
#define CP_ASYNC16(saddr, gaddr) \
    asm volatile("cp.async.cg.shared.global [%0], [%1], 16;" :: "r"(saddr), "l"(gaddr))
#define CP_COMMIT() asm volatile("cp.async.commit_group;" ::: "memory")
#define CP_WAIT(n)  asm volatile("cp.async.wait_group %0;" :: "n"(n) : "memory")

__device__ __forceinline__ void ldm_x4(uint32_t addr, uint32_t* r) {
    asm volatile("ldmatrix.sync.aligned.m8n8.x4.shared.b16 {%0,%1,%2,%3}, [%4];"
        : "=r"(r[0]), "=r"(r[1]), "=r"(r[2]), "=r"(r[3]) : "r"(addr));
}
__device__ __forceinline__ void ldm_x2(uint32_t addr, uint32_t* r) {
    asm volatile("ldmatrix.sync.aligned.m8n8.x2.shared.b16 {%0,%1}, [%2];"
        : "=r"(r[0]), "=r"(r[1]) : "r"(addr));
}
__device__ __forceinline__ void ldm_x2_trans(uint32_t addr, uint32_t* r) {
    asm volatile("ldmatrix.sync.aligned.m8n8.x2.trans.shared.b16 {%0,%1}, [%2];"
        : "=r"(r[0]), "=r"(r[1]) : "r"(addr));
}
__device__ __forceinline__ void mma_f16(float* d, const uint32_t* a, const uint32_t* b) {
    asm volatile("mma.sync.aligned.m16n8k16.row.col.f32.f16.f16.f32 "
        "{%0,%1,%2,%3}, {%4,%5,%6,%7}, {%8,%9}, {%0,%1,%2,%3};"
        : "+f"(d[0]), "+f"(d[1]), "+f"(d[2]), "+f"(d[3])
        : "r"(a[0]), "r"(a[1]), "r"(a[2]), "r"(a[3]), "r"(b[0]), "r"(b[1]));
}

// single-pass MMA block over 2x4 accumulators
__device__ __forceinline__ void mma_block(float acc[2][4][4],
                                          uint32_t a_f[2][4], uint32_t b_f[4][2]) {
#pragma unroll
    for (int mi = 0; mi < 2; mi++)
#pragma unroll
        for (int ni = 0; ni < 4; ni++)
            mma_f16(acc[mi][ni], a_f[mi], b_f[ni]);
}

// ---------------------------------------------------------------------------
// conversions (fused with cache copy): all 7 matrices -> single fp16;
// ck/cv additionally copied fp32 into output K/V slots
// ---------------------------------------------------------------------------
__global__ void convert7_kernel(const float4* __restrict__ x,
                                const float4* __restrict__ wq,
                                const float4* __restrict__ wk,
                                const float4* __restrict__ wv,
                                const float4* __restrict__ wo,
                                const float4* __restrict__ ck,
                                const float4* __restrict__ cv,
                                float4* __restrict__ Kout,
                                float4* __restrict__ Vout) {
    int id = blockIdx.x * blockDim.x + threadIdx.x;
    const int per = (int)(NMAT / 4);
    int mat = id / per;
    int rem = id - mat * per;
    const float4* srcs[7] = {x, wq, wk, wv, wo, ck, cv};
    float4 v = srcs[mat][rem];
    __half* base;
    if (mat == 0)      base = g_xh;
    else if (mat <= 4) base = g_w4 + (size_t)(mat - 1) * NMAT;
    else if (mat == 5) base = g_kc;
    else               base = g_vc;
    __half2* d = reinterpret_cast<__half2*>(base) + rem * 2;
    d[0] = __halves2half2(__float2half(v.x), __float2half(v.y));
    d[1] = __halves2half2(__float2half(v.z), __float2half(v.w));
    if (mat >= 5) {
        int pos = rem & 31;
        int row = rem >> 5;
        int s = row & (SC - 1);
        int bh = row >> 10;
        int dst = (((bh * SS) + s) << 5) + pos;
        ((mat == 5) ? Kout : Vout)[dst] = v;
    }
}

// ---------------------------------------------------------------------------
// HMMA fp16 GEMM (256 threads, 8 warps 4x2, CTA tile 128x64)
// mode 0: A=x, B=W[proj]; Q -> fp16 (scaled), K/V -> d_out fp32
// mode 1: A=attn, B=Wo; -> out fp32
// ---------------------------------------------------------------------------
__global__ __launch_bounds__(256, 2)
void mm_hmma_kernel(int mode, float* __restrict__ Kout, float* __restrict__ Vout,
                    float* __restrict__ out) {
    extern __shared__ char sm[];
    const uint32_t sbu = smem_u32(sm);
    const int tid = threadIdx.x;
    const int wid = tid >> 5, lane = tid & 31;
    const int warp_m = wid >> 1;          // 0..3
    const int warp_n = wid & 1;           // 0..1

    const int proj = blockIdx.z;
    const __half *As, *Bs;
    if (mode == 0) {
        As = g_xh;
        Bs = g_w4 + (size_t)proj * NMAT;
    } else {
        As = g_ah;
        Bs = g_w4 + (size_t)3 * NMAT;
    }
    const int m0 = blockIdx.x * 128, n0 = blockIdx.y * 64;

    // cp.async: 768 16B chunks per stage, 3 per thread
    const __half* gptr[3];
    uint32_t soff[3];
#pragma unroll
    for (int j = 0; j < 3; j++) {
        int c = j * 256 + tid;
        if (c < 512) {
            int r = c >> 2, c16 = c & 3;
            gptr[j] = As + (size_t)(m0 + r) * KDIM + c16 * 8;
            soff[j] = (uint32_t)(r * MM_LDS_B + c16 * 16);
        } else {
            int idx = c - 512;             // 0..255
            int r = idx >> 2, c16 = idx & 3;
            gptr[j] = Bs + (size_t)(n0 + r) * KDIM + c16 * 8;
            soff[j] = (uint32_t)(MM_MATA + r * MM_LDS_B + c16 * 16);
        }
    }

    const uint32_t a_row = (uint32_t)(warp_m * 32 + (lane & 15));
    const uint32_t a_kb  = (uint32_t)(((lane >> 4) << 3) * 2);
    const uint32_t b_row = (uint32_t)(warp_n * 32 + (lane & 7));
    const uint32_t b_kb  = (uint32_t)((((lane >> 3) & 1) << 3) * 2);

    float acc[2][4][4];
#pragma unroll
    for (int mi = 0; mi < 2; mi++)
#pragma unroll
        for (int ni = 0; ni < 4; ni++)
#pragma unroll
            for (int q = 0; q < 4; q++) acc[mi][ni][q] = 0.f;

#pragma unroll
    for (int j = 0; j < 3; j++) CP_ASYNC16(sbu + soff[j], gptr[j]);
    CP_COMMIT();

    for (int i = 0; i < MM_KSTEPS; i++) {
        const int s = i & 1;
        if (i + 1 < MM_KSTEPS) {
            const uint32_t sb2 = sbu + ((i + 1) & 1) * MM_STAGE;
            const int k0 = (i + 1) * MM_BK;
#pragma unroll
            for (int j = 0; j < 3; j++) CP_ASYNC16(sb2 + soff[j], gptr[j] + k0);
            CP_COMMIT();
            CP_WAIT(1);
        } else {
            CP_WAIT(0);
        }
        __syncthreads();

        const uint32_t stage = sbu + s * MM_STAGE;
#pragma unroll
        for (int kk = 0; kk < 2; kk++) {
            const uint32_t kb = (uint32_t)(kk * 32);
            uint32_t a_f[2][4], b_f[4][2];
#pragma unroll
            for (int ni = 0; ni < 4; ni++) {
                uint32_t baddr = stage + MM_MATA +
                                 (b_row + ni * 8) * MM_LDS_B + b_kb + kb;
                ldm_x2(baddr, b_f[ni]);
            }
#pragma unroll
            for (int mi = 0; mi < 2; mi++) {
                uint32_t aaddr = stage + (a_row + mi * 16) * MM_LDS_B + a_kb + kb;
                ldm_x4(aaddr, a_f[mi]);
            }
            mma_block(acc, a_f, b_f);
        }
        __syncthreads();
    }

    const int gid = lane >> 2, tc = lane & 3;
#pragma unroll
    for (int mi = 0; mi < 2; mi++) {
#pragma unroll
        for (int ni = 0; ni < 4; ni++) {
            int mrow0 = m0 + warp_m * 32 + mi * 16 + gid;
            int ncol  = n0 + warp_n * 32 + ni * 8 + tc * 2;
#pragma unroll
            for (int half = 0; half < 2; half++) {
                int m = mrow0 + half * 8;
                float v0 = acc[mi][ni][half * 2 + 0];
                float v1 = acc[mi][ni][half * 2 + 1];
                if (mode == 0) {
                    int b = m >> 10, t = m & (Tt - 1);
                    int h = ncol >> 7, d = ncol & (DK - 1);
                    if (proj == 0) {
                        size_t qi = (((size_t)(b * Hh + h) * Tt) + t) * DK + d;
                        *reinterpret_cast<__half2*>(g_qh + qi) =
                            __halves2half2(__float2half(v0 * RSQRT_DK),
                                           __float2half(v1 * RSQRT_DK));
                    } else {
                        float* base = (proj == 1) ? Kout : Vout;
                        float* dst = base + (((size_t)(b * Hh + h) * SS) + SC + t) * DK + d;
                        float2 vv; vv.x = v0; vv.y = v1;
                        *reinterpret_cast<float2*>(dst) = vv;
                    }
                } else {
                    float* dst = out + (size_t)m * Cc + ncol;
                    float2 vv; vv.x = v0; vv.y = v1;
                    *reinterpret_cast<float2*>(dst) = vv;
                }
            }
        }
    }
}

// ---------------------------------------------------------------------------
// scores via HMMA fp16 (256 threads, CTA tile 128x64): Q . K, Kdim=128
// ---------------------------------------------------------------------------
__global__ __launch_bounds__(256, 2)
void scores_hmma_kernel() {
    if ((blockIdx.y >> 1) > blockIdx.x) return;   // fully-masked tile
    extern __shared__ char sm[];
    const uint32_t sbu = smem_u32(sm);
    const int tid = threadIdx.x;
    const int wid = tid >> 5, lane = tid & 31;
    const int warp_m = wid >> 1;
    const int warp_n = wid & 1;

    const int bh = blockIdx.z;
    const int m0 = blockIdx.x * 128, n0 = blockIdx.y * 64;

    const __half* Qs = g_qh + (size_t)bh * Tt * DK;
    const __half* Ks = g_kc + (size_t)bh * SC * DK;

    const __half* gptr[3];
    uint32_t soff[3];
#pragma unroll
    for (int j = 0; j < 3; j++) {
        int c = j * 256 + tid;
        if (c < 512) {
            int r = c >> 2, c16 = c & 3;
            gptr[j] = Qs + (size_t)(m0 + r) * DK + c16 * 8;
            soff[j] = (uint32_t)(r * MM_LDS_B + c16 * 16);
        } else {
            int idx = c - 512;
            int r = idx >> 2, c16 = idx & 3;
            gptr[j] = Ks + (size_t)(n0 + r) * DK + c16 * 8;
            soff[j] = (uint32_t)(MM_MATA + r * MM_LDS_B + c16 * 16);
        }
    }

    const uint32_t a_row = (uint32_t)(warp_m * 32 + (lane & 15));
    const uint32_t a_kb  = (uint32_t)(((lane >> 4) << 3) * 2);
    const uint32_t b_row = (uint32_t)(warp_n * 32 + (lane & 7));
    const uint32_t b_kb  = (uint32_t)((((lane >> 3) & 1) << 3) * 2);

    float acc[2][4][4];
#pragma unroll
    for (int mi = 0; mi < 2; mi++)
#pragma unroll
        for (int ni = 0; ni < 4; ni++)
#pragma unroll
            for (int q = 0; q < 4; q++) acc[mi][ni][q] = 0.f;

#pragma unroll
    for (int j = 0; j < 3; j++) CP_ASYNC16(sbu + soff[j], gptr[j]);
    CP_COMMIT();

    for (int i = 0; i < SC_KSTEPS; i++) {
        const int s = i & 1;
        if (i + 1 < SC_KSTEPS) {
            const uint32_t sb2 = sbu + ((i + 1) & 1) * MM_STAGE;
            const int k0 = (i + 1) * MM_BK;
#pragma unroll
            for (int j = 0; j < 3; j++) CP_ASYNC16(sb2 + soff[j], gptr[j] + k0);
            CP_COMMIT();
            CP_WAIT(1);
        } else {
            CP_WAIT(0);
        }
        __syncthreads();

        const uint32_t stage = sbu + s * MM_STAGE;
#pragma unroll
        for (int kk = 0; kk < 2; kk++) {
            const uint32_t kb = (uint32_t)(kk * 32);
            uint32_t a_f[2][4], b_f[4][2];
#pragma unroll
            for (int ni = 0; ni < 4; ni++) {
                uint32_t baddr = stage + MM_MATA +
                                 (b_row + ni * 8) * MM_LDS_B + b_kb + kb;
                ldm_x2(baddr, b_f[ni]);
            }
#pragma unroll
            for (int mi = 0; mi < 2; mi++) {
                uint32_t aaddr = stage + (a_row + mi * 16) * MM_LDS_B + a_kb + kb;
                ldm_x4(aaddr, a_f[mi]);
            }
            mma_block(acc, a_f, b_f);
        }
        __syncthreads();
    }

    float* outp = g_scores + (size_t)bh * Tt * SC;
    const int gid = lane >> 2, tc = lane & 3;
#pragma unroll
    for (int mi = 0; mi < 2; mi++) {
#pragma unroll
        for (int ni = 0; ni < 4; ni++) {
            int mrow0 = m0 + warp_m * 32 + mi * 16 + gid;
            int ncol  = n0 + warp_n * 32 + ni * 8 + tc * 2;
#pragma unroll
            for (int half = 0; half < 2; half++) {
                int t = mrow0 + half * 8;
                float2 vv;
                vv.x = acc[mi][ni][half * 2 + 0];
                vv.y = acc[mi][ni][half * 2 + 1];
                *reinterpret_cast<float2*>(outp + (size_t)t * SC + ncol) = vv;
            }
        }
    }
}

// ---------------------------------------------------------------------------
// softmax: fp32 scores in, fp16 P out (zero tail)
// ---------------------------------------------------------------------------
__global__ __launch_bounds__(256)
void softmax_kernel() {
    __shared__ float sred[8];
    int row = blockIdx.x;
    int t = row & (Tt - 1);
    int len = t + 1;
    const float* p = g_scores + (size_t)row * SC;
    int tid = threadIdx.x;
    int lane = tid & 31, warp = tid >> 5;

    float v[4];
    float m = -1e30f;
#pragma unroll
    for (int j = 0; j < 4; j++) {
        int idx = tid + j * 256;
        if (idx < len) { v[j] = p[idx]; m = fmaxf(m, v[j]); }
    }
#pragma unroll
    for (int o = 16; o; o >>= 1) m = fmaxf(m, __shfl_xor_sync(0xffffffffu, m, o));
    if (lane == 0) sred[warp] = m;
    __syncthreads();
    if (tid < 32) {
        float x = (lane < 8) ? sred[lane] : -1e30f;
#pragma unroll
        for (int o = 4; o; o >>= 1) x = fmaxf(x, __shfl_xor_sync(0xffffffffu, x, o));
        if (lane == 0) sred[0] = x;
    }
    __syncthreads();
    m = sred[0];
    __syncthreads();

    float sum = 0.f;
#pragma unroll
    for (int j = 0; j < 4; j++) {
        int idx = tid + j * 256;
        if (idx < len) { v[j] = __expf(v[j] - m); sum += v[j]; }
    }
#pragma unroll
    for (int o = 16; o; o >>= 1) sum += __shfl_xor_sync(0xffffffffu, sum, o);
    if (lane == 0) sred[warp] = sum;
    __syncthreads();
    if (tid < 32) {
        float x = (lane < 8) ? sred[lane] : 0.f;
#pragma unroll
        for (int o = 4; o; o >>= 1) x += __shfl_xor_sync(0xffffffffu, x, o);
        if (lane == 0) sred[0] = x;
    }
    __syncthreads();
    float inv = 1.f / sred[0];

    size_t base = (size_t)row * SC;
#pragma unroll
    for (int j = 0; j < 4; j++) {
        int idx = tid + j * 256;
        float w = (idx < len) ? v[j] * inv : 0.f;
        g_ph[base + idx] = __float2half(w);
    }
}

// ---------------------------------------------------------------------------
// PV via HMMA fp16 (256 threads, CTA 128x64): attn = P @ V, causal k-limit
// V native [s,d] via ldmatrix.trans
// ---------------------------------------------------------------------------
__global__ __launch_bounds__(256, 2)
void pv_hmma_kernel() {
    extern __shared__ char sm[];
    const uint32_t sbu = smem_u32(sm);
    const int tid = threadIdx.x;
    const int wid = tid >> 5, lane = tid & 31;
    const int warp_m = wid >> 1;
    const int warp_n = wid & 1;

    const int mt = blockIdx.x;
    const int n0 = blockIdx.y * 64;       // d-tile
    const int bh = blockIdx.z;
    const int m0 = mt * 128;
    const int ksteps = (mt + 1) * 4;

    const __half* Ps = g_ph + (size_t)bh * Tt * SC + (size_t)m0 * SC;
    const __half* Vs = g_vc + (size_t)bh * SC * DK;

    const __half* gptr[3];
    int gstep[3];
    uint32_t soff[3];
#pragma unroll
    for (int j = 0; j < 3; j++) {
        int c = j * 256 + tid;
        if (c < 512) {
            int r = c >> 2, c16 = c & 3;
            gptr[j] = Ps + (size_t)r * SC + c16 * 8;
            gstep[j] = MM_BK;
            soff[j] = (uint32_t)(r * MM_LDS_B + c16 * 16);
        } else {
            int idx = c - 512;             // 0..255
            int r = idx >> 3, c8 = idx & 7;
            gptr[j] = Vs + (size_t)r * DK + n0 + c8 * 8;
            gstep[j] = MM_BK * DK;
            soff[j] = (uint32_t)(PV_MATP + r * PV_LDSV + c8 * 16);
        }
    }

    const uint32_t a_row = (uint32_t)(warp_m * 32 + (lane & 15));
    const uint32_t a_kb  = (uint32_t)(((lane >> 4) << 3) * 2);
    const uint32_t v_row = (uint32_t)(lane & 15);

    float acc[2][4][4];
#pragma unroll
    for (int mi = 0; mi < 2; mi++)
#pragma unroll
        for (int ni = 0; ni < 4; ni++)
#pragma unroll
            for (int q = 0; q < 4; q++) acc[mi][ni][q] = 0.f;

#pragma unroll
    for (int j = 0; j < 3; j++) CP_ASYNC16(sbu + soff[j], gptr[j]);
    CP_COMMIT();

    for (int i = 0; i < ksteps; i++) {
        const int s = i & 1;
        if (i + 1 < ksteps) {
            const uint32_t sb2 = sbu + ((i + 1) & 1) * PV_STAGE;
#pragma unroll
            for (int j = 0; j < 3; j++)
                CP_ASYNC16(sb2 + soff[j], gptr[j] + (size_t)(i + 1) * gstep[j]);
            CP_COMMIT();
            CP_WAIT(1);
        } else {
            CP_WAIT(0);
        }
        __syncthreads();

        const uint32_t stage = sbu + s * PV_STAGE;
        const uint32_t vbase = stage + PV_MATP;
#pragma unroll
        for (int kk = 0; kk < 2; kk++) {
            uint32_t a_f[2][4], b_f[4][2];
#pragma unroll
            for (int ni = 0; ni < 4; ni++) {
                uint32_t ncl = (uint32_t)(warp_n * 32 + ni * 8) * 2;
                uint32_t baddr = vbase + (kk * 16 + v_row) * PV_LDSV + ncl;
                ldm_x2_trans(baddr, b_f[ni]);
            }
#pragma unroll
            for (int mi = 0; mi < 2; mi++) {
                uint32_t aaddr = stage + (a_row + mi * 16) * MM_LDS_B + a_kb + (uint32_t)(kk * 32);
                ldm_x4(aaddr, a_f[mi]);
            }
            mma_block(acc, a_f, b_f);
        }
        __syncthreads();
    }

    const int b = bh >> 4, h = bh & (Hh - 1);
    const int gid = lane >> 2, tc = lane & 3;
#pragma unroll
    for (int mi = 0; mi < 2; mi++) {
#pragma unroll
        for (int ni = 0; ni < 4; ni++) {
            int mrow0 = m0 + warp_m * 32 + mi * 16 + gid;
            int d = n0 + warp_n * 32 + ni * 8 + tc * 2;
#pragma unroll
            for (int half = 0; half < 2; half++) {
                int t = mrow0 + half * 8;
                float v0 = acc[mi][ni][half * 2 + 0];
                float v1 = acc[mi][ni][half * 2 + 1];
                size_t idx = (((size_t)(b * Tt + t) * Hh) + h) * DK + d;
                *reinterpret_cast<__half2*>(g_ah + idx) =
                    __halves2half2(__float2half(v0), __float2half(v1));
            }
        }
    }
}

// ---------------------------------------------------------------------------
extern "C" void kernel_launch(void* const* d_in, const int* in_sizes, int n_in,
                              void* d_out, int out_size) {
    const float* x  = (const float*)d_in[0];
    const float* ck = (const float*)d_in[1];
    const float* cv = (const float*)d_in[2];
    const float* Wq = (const float*)d_in[3];
    const float* Wk = (const float*)d_in[4];
    const float* Wv = (const float*)d_in[5];
    const float* Wo = (const float*)d_in[6];

    float* out  = (float*)d_out;
    float* Kout = out + (size_t)Bb * Tt * Cc;
    float* Vout = Kout + (size_t)Bb * Hh * SS * DK;

    cudaFuncSetAttribute(mm_hmma_kernel, cudaFuncAttributeMaxDynamicSharedMemorySize, MM_SMEM);
    cudaFuncSetAttribute(scores_hmma_kernel, cudaFuncAttributeMaxDynamicSharedMemorySize, MM_SMEM);
    cudaFuncSetAttribute(pv_hmma_kernel, cudaFuncAttributeMaxDynamicSharedMemorySize, PV_SMEM);

    convert7_kernel<<<28672, 256>>>((const float4*)x, (const float4*)Wq,
                                    (const float4*)Wk, (const float4*)Wv,
                                    (const float4*)Wo, (const float4*)ck,
                                    (const float4*)cv,
                                    (float4*)Kout, (float4*)Vout);
    mm_hmma_kernel<<<dim3(16, 32, 3), 256, MM_SMEM>>>(0, Kout, Vout, out);
    scores_hmma_kernel<<<dim3(8, 16, 32), 256, MM_SMEM>>>();
    softmax_kernel<<<Bb * Hh * Tt, 256>>>();
    pv_hmma_kernel<<<dim3(8, 2, 32), 256, PV_SMEM>>>();
    mm_hmma_kernel<<<dim3(16, 32, 1), 256, MM_SMEM>>>(1, Kout, Vout, out);
}

// round 11
// speedup vs baseline: 2.2605x; 1.1304x over previous
#include <cuda_runtime.h>
#include <cuda_fp16.h>
#include <math.h>
#include <stdint.h>

// Problem dims
#define Bb 2
#define Tt 1024
#define Cc 2048
#define Hh 16
#define DK 128
#define SC 1024
#define SS 2048
#define KDIM 2048
#define NMAT 4194304ull   // 2048*2048

#define RSQRT_DK 0.08838834764831845f

// HMMA GEMM tiling: CTA tile 128(M) x 64(N) x 32(K), 256 threads, 8 warps 4x2
#define MM_BK 32
#define MM_LDS_B 80                        // bytes per smem row (32 fp16 + 16 pad)
#define MM_MATA 10240                      // 128 rows * 80
#define MM_MATB 5120                       // 64 rows * 80
#define MM_STAGE (MM_MATA + MM_MATB)       // 15360 (A, B)
#define MM_SMEM (2 * MM_STAGE)             // 30720
#define MM_KSTEPS (KDIM / MM_BK)           // 64

// Flash-attention kernel tiling: m-tile 128, s-tile 64, d=128, 8 warps (16 rows each)
#define FA_LDQ 272                         // 128 fp16 = 256B + 16 pad
#define FA_LDK 272
#define FA_QBYTES (128 * FA_LDQ)           // 34816
#define FA_KBYTES (64 * FA_LDK)            // 17408
#define FA_KV_STAGE (2 * FA_KBYTES)        // 34816 (K then V)
#define FA_SMEM (FA_QBYTES + 2 * FA_KV_STAGE)  // 104448

// ---------------------------------------------------------------------------
// Scratch (device globals)
// ---------------------------------------------------------------------------
__device__ __half g_xh[NMAT];                             // x fp16
__device__ __half g_w4[4 * NMAT];                         // Wq,Wk,Wv,Wo fp16
__device__ __half g_kc[NMAT];                             // cache_k fp16
__device__ __half g_vc[NMAT];                             // cache_v fp16
__device__ __half g_qh[NMAT];                             // Q fp16 [bh,t,d] scaled
__device__ __half g_ah[NMAT];                             // attn fp16 [b,t,h,d]

// ---------------------------------------------------------------------------
// PTX helpers
// ---------------------------------------------------------------------------
__device__ __forceinline__ uint32_t smem_u32(const void* p) {
    uint32_t a;
    asm("{ .reg .u64 t; cvta.to.shared.u64 t, %1; cvt.u32.u64 %0, t; }" : "=r"(a) : "l"(p));
    return a;
}
#define CP_ASYNC16(saddr, gaddr) \
    asm volatile("cp.async.cg.shared.global [%0], [%1], 16;" :: "r"(saddr), "l"(gaddr))
#define CP_COMMIT() asm volatile("cp.async.commit_group;" ::: "memory")
#define CP_WAIT(n)  asm volatile("cp.async.wait_group %0;" :: "n"(n) : "memory")

__device__ __forceinline__ void ldm_x4(uint32_t addr, uint32_t* r) {
    asm volatile("ldmatrix.sync.aligned.m8n8.x4.shared.b16 {%0,%1,%2,%3}, [%4];"
        : "=r"(r[0]), "=r"(r[1]), "=r"(r[2]), "=r"(r[3]) : "r"(addr));
}
__device__ __forceinline__ void ldm_x2(uint32_t addr, uint32_t* r) {
    asm volatile("ldmatrix.sync.aligned.m8n8.x2.shared.b16 {%0,%1}, [%2];"
        : "=r"(r[0]), "=r"(r[1]) : "r"(addr));
}
__device__ __forceinline__ void ldm_x2_trans(uint32_t addr, uint32_t* r) {
    asm volatile("ldmatrix.sync.aligned.m8n8.x2.trans.shared.b16 {%0,%1}, [%2];"
        : "=r"(r[0]), "=r"(r[1]) : "r"(addr));
}
__device__ __forceinline__ void mma_f16(float* d, const uint32_t* a, const uint32_t* b) {
    asm volatile("mma.sync.aligned.m16n8k16.row.col.f32.f16.f16.f32 "
        "{%0,%1,%2,%3}, {%4,%5,%6,%7}, {%8,%9}, {%0,%1,%2,%3};"
        : "+f"(d[0]), "+f"(d[1]), "+f"(d[2]), "+f"(d[3])
        : "r"(a[0]), "r"(a[1]), "r"(a[2]), "r"(a[3]), "r"(b[0]), "r"(b[1]));
}
__device__ __forceinline__ uint32_t pack2h(float a, float b) {
    __half2 h = __floats2half2_rn(a, b);
    return *reinterpret_cast<uint32_t*>(&h);
}

// single-pass MMA block over 2x4 accumulators (mm kernel)
__device__ __forceinline__ void mma_block(float acc[2][4][4],
                                          uint32_t a_f[2][4], uint32_t b_f[4][2]) {
#pragma unroll
    for (int mi = 0; mi < 2; mi++)
#pragma unroll
        for (int ni = 0; ni < 4; ni++)
            mma_f16(acc[mi][ni], a_f[mi], b_f[ni]);
}

// ---------------------------------------------------------------------------
// conversions (fused with cache copy): all 7 matrices -> fp16;
// ck/cv also copied fp32 into output K/V slots
// ---------------------------------------------------------------------------
__global__ void convert7_kernel(const float4* __restrict__ x,
                                const float4* __restrict__ wq,
                                const float4* __restrict__ wk,
                                const float4* __restrict__ wv,
                                const float4* __restrict__ wo,
                                const float4* __restrict__ ck,
                                const float4* __restrict__ cv,
                                float4* __restrict__ Kout,
                                float4* __restrict__ Vout) {
    int id = blockIdx.x * blockDim.x + threadIdx.x;
    const int per = (int)(NMAT / 4);
    int mat = id / per;
    int rem = id - mat * per;
    const float4* srcs[7] = {x, wq, wk, wv, wo, ck, cv};
    float4 v = srcs[mat][rem];
    __half* base;
    if (mat == 0)      base = g_xh;
    else if (mat <= 4) base = g_w4 + (size_t)(mat - 1) * NMAT;
    else if (mat == 5) base = g_kc;
    else               base = g_vc;
    __half2* d = reinterpret_cast<__half2*>(base) + rem * 2;
    d[0] = __halves2half2(__float2half(v.x), __float2half(v.y));
    d[1] = __halves2half2(__float2half(v.z), __float2half(v.w));
    if (mat >= 5) {
        int pos = rem & 31;
        int row = rem >> 5;
        int s = row & (SC - 1);
        int bh = row >> 10;
        int dst = (((bh * SS) + s) << 5) + pos;
        ((mat == 5) ? Kout : Vout)[dst] = v;
    }
}

// ---------------------------------------------------------------------------
// HMMA fp16 GEMM (256 threads, 8 warps 4x2, CTA tile 128x64)
// mode 0: A=x, B=W[proj]; Q -> fp16 (scaled), K/V -> d_out fp32
// mode 1: A=attn, B=Wo; -> out fp32
// ---------------------------------------------------------------------------
__global__ __launch_bounds__(256, 2)
void mm_hmma_kernel(int mode, float* __restrict__ Kout, float* __restrict__ Vout,
                    float* __restrict__ out) {
    extern __shared__ char sm[];
    const uint32_t sbu = smem_u32(sm);
    const int tid = threadIdx.x;
    const int wid = tid >> 5, lane = tid & 31;
    const int warp_m = wid >> 1;
    const int warp_n = wid & 1;

    const int proj = blockIdx.z;
    const __half *As, *Bs;
    if (mode == 0) {
        As = g_xh;
        Bs = g_w4 + (size_t)proj * NMAT;
    } else {
        As = g_ah;
        Bs = g_w4 + (size_t)3 * NMAT;
    }
    const int m0 = blockIdx.x * 128, n0 = blockIdx.y * 64;

    const __half* gptr[3];
    uint32_t soff[3];
#pragma unroll
    for (int j = 0; j < 3; j++) {
        int c = j * 256 + tid;
        if (c < 512) {
            int r = c >> 2, c16 = c & 3;
            gptr[j] = As + (size_t)(m0 + r) * KDIM + c16 * 8;
            soff[j] = (uint32_t)(r * MM_LDS_B + c16 * 16);
        } else {
            int idx = c - 512;
            int r = idx >> 2, c16 = idx & 3;
            gptr[j] = Bs + (size_t)(n0 + r) * KDIM + c16 * 8;
            soff[j] = (uint32_t)(MM_MATA + r * MM_LDS_B + c16 * 16);
        }
    }

    const uint32_t a_row = (uint32_t)(warp_m * 32 + (lane & 15));
    const uint32_t a_kb  = (uint32_t)(((lane >> 4) << 3) * 2);
    const uint32_t b_row = (uint32_t)(warp_n * 32 + (lane & 7));
    const uint32_t b_kb  = (uint32_t)((((lane >> 3) & 1) << 3) * 2);

    float acc[2][4][4];
#pragma unroll
    for (int mi = 0; mi < 2; mi++)
#pragma unroll
        for (int ni = 0; ni < 4; ni++)
#pragma unroll
            for (int q = 0; q < 4; q++) acc[mi][ni][q] = 0.f;

#pragma unroll
    for (int j = 0; j < 3; j++) CP_ASYNC16(sbu + soff[j], gptr[j]);
    CP_COMMIT();

    for (int i = 0; i < MM_KSTEPS; i++) {
        const int s = i & 1;
        if (i + 1 < MM_KSTEPS) {
            const uint32_t sb2 = sbu + ((i + 1) & 1) * MM_STAGE;
            const int k0 = (i + 1) * MM_BK;
#pragma unroll
            for (int j = 0; j < 3; j++) CP_ASYNC16(sb2 + soff[j], gptr[j] + k0);
            CP_COMMIT();
            CP_WAIT(1);
        } else {
            CP_WAIT(0);
        }
        __syncthreads();

        const uint32_t stage = sbu + s * MM_STAGE;
#pragma unroll
        for (int kk = 0; kk < 2; kk++) {
            const uint32_t kb = (uint32_t)(kk * 32);
            uint32_t a_f[2][4], b_f[4][2];
#pragma unroll
            for (int ni = 0; ni < 4; ni++) {
                uint32_t baddr = stage + MM_MATA +
                                 (b_row + ni * 8) * MM_LDS_B + b_kb + kb;
                ldm_x2(baddr, b_f[ni]);
            }
#pragma unroll
            for (int mi = 0; mi < 2; mi++) {
                uint32_t aaddr = stage + (a_row + mi * 16) * MM_LDS_B + a_kb + kb;
                ldm_x4(aaddr, a_f[mi]);
            }
            mma_block(acc, a_f, b_f);
        }
        __syncthreads();
    }

    const int gid = lane >> 2, tc = lane & 3;
#pragma unroll
    for (int mi = 0; mi < 2; mi++) {
#pragma unroll
        for (int ni = 0; ni < 4; ni++) {
            int mrow0 = m0 + warp_m * 32 + mi * 16 + gid;
            int ncol  = n0 + warp_n * 32 + ni * 8 + tc * 2;
#pragma unroll
            for (int half = 0; half < 2; half++) {
                int m = mrow0 + half * 8;
                float v0 = acc[mi][ni][half * 2 + 0];
                float v1 = acc[mi][ni][half * 2 + 1];
                if (mode == 0) {
                    int b = m >> 10, t = m & (Tt - 1);
                    int h = ncol >> 7, d = ncol & (DK - 1);
                    if (proj == 0) {
                        size_t qi = (((size_t)(b * Hh + h) * Tt) + t) * DK + d;
                        *reinterpret_cast<__half2*>(g_qh + qi) =
                            __halves2half2(__float2half(v0 * RSQRT_DK),
                                           __float2half(v1 * RSQRT_DK));
                    } else {
                        float* base = (proj == 1) ? Kout : Vout;
                        float* dst = base + (((size_t)(b * Hh + h) * SS) + SC + t) * DK + d;
                        float2 vv; vv.x = v0; vv.y = v1;
                        *reinterpret_cast<float2*>(dst) = vv;
                    }
                } else {
                    float* dst = out + (size_t)m * Cc + ncol;
                    float2 vv; vv.x = v0; vv.y = v1;
                    *reinterpret_cast<float2*>(dst) = vv;
                }
            }
        }
    }
}

// ---------------------------------------------------------------------------
// Fused flash attention: per CTA (bh, 128-row m-tile).
// 8 warps, each owns 16 t-rows. Streams 64-row K/V s-tiles.
// S = Q.K^T (HMMA), online softmax in regs, O += P.V using the
// m16n8k16 C-fragment == A-fragment layout identity. Output fp16 -> g_ah.
// ---------------------------------------------------------------------------
__global__ __launch_bounds__(256, 1)
void fa_kernel() {
    extern __shared__ char sm[];
    const uint32_t sbu = smem_u32(sm);
    const int tid = threadIdx.x;
    const int wid = tid >> 5, lane = tid & 31;
    const int gid = lane >> 2, tc = lane & 3;

    const int mt = 7 - blockIdx.x;        // heavy tiles first
    const int bh = blockIdx.y;
    const int m0 = mt * 128;
    const int nst = (mt + 1) * 2;         // 64-row s-tiles (causal)

    const __half* Qg = g_qh + (size_t)bh * Tt * DK + (size_t)m0 * DK;
    const __half* Kg = g_kc + (size_t)bh * SC * DK;
    const __half* Vg = g_vc + (size_t)bh * SC * DK;

    const uint32_t qs  = sbu;
    const uint32_t kvs = sbu + FA_QBYTES;

    // Q load (once): 2048 16B chunks, 8 per thread
#pragma unroll
    for (int j = 0; j < 8; j++) {
        int c = j * 256 + tid;
        int row = c >> 4, col = c & 15;
        CP_ASYNC16(qs + row * FA_LDQ + col * 16, Qg + (size_t)row * DK + col * 8);
    }
    // K/V tile chunk mapping: 2048 chunks (K 1024, V 1024), 8 per thread
    const __half* kvg[8];
    uint32_t kvo[8];
#pragma unroll
    for (int j = 0; j < 8; j++) {
        int c = j * 256 + tid;
        int mat = c >> 10;
        int idx = c & 1023;
        int row = idx >> 4, col = idx & 15;
        kvg[j] = (mat ? Vg : Kg) + (size_t)row * DK + col * 8;
        kvo[j] = (uint32_t)(mat * FA_KBYTES + row * FA_LDK + col * 16);
    }
#pragma unroll
    for (int j = 0; j < 8; j++) CP_ASYNC16(kvs + kvo[j], kvg[j]);
    CP_COMMIT();

    float acc_o[16][4];
#pragma unroll
    for (int nd = 0; nd < 16; nd++)
#pragma unroll
        for (int q = 0; q < 4; q++) acc_o[nd][q] = 0.f;

    float m0r = -1e30f, m1r = -1e30f, l0r = 0.f, l1r = 0.f;
    const int t0 = m0 + wid * 16 + gid;   // row 0 of this thread (row 1 = t0+8)

    const uint32_t a_off   = (uint32_t)((wid * 16 + (lane & 15)) * FA_LDQ + ((lane >> 4) << 4));
    const uint32_t b_off   = (uint32_t)((lane & 7) * FA_LDK + (((lane >> 3) & 1) << 4));
    const uint32_t v_off   = (uint32_t)((lane & 15) * FA_LDK);

    for (int i = 0; i < nst; i++) {
        const int s = i & 1;
        if (i + 1 < nst) {
            const uint32_t kv2 = kvs + ((i + 1) & 1) * FA_KV_STAGE;
            const size_t off = (size_t)(i + 1) * 64 * DK;
#pragma unroll
            for (int j = 0; j < 8; j++) CP_ASYNC16(kv2 + kvo[j], kvg[j] + off);
            CP_COMMIT();
            CP_WAIT(1);
        } else {
            CP_WAIT(0);
        }
        __syncthreads();

        const uint32_t kb_ = kvs + s * FA_KV_STAGE;
        const uint32_t vb_ = kb_ + FA_KBYTES;

        // --- S = Q . K^T (16 rows x 64 s-cols per warp) ---
        float acc_s[8][4];
#pragma unroll
        for (int ni = 0; ni < 8; ni++)
#pragma unroll
            for (int q = 0; q < 4; q++) acc_s[ni][q] = 0.f;
#pragma unroll
        for (int kk = 0; kk < 8; kk++) {
            uint32_t a_f[4];
            ldm_x4(qs + a_off + kk * 32, a_f);
#pragma unroll
            for (int ni = 0; ni < 8; ni++) {
                uint32_t b_f[2];
                ldm_x2(kb_ + b_off + ni * 8 * FA_LDK + kk * 32, b_f);
                mma_f16(acc_s[ni], a_f, b_f);
            }
        }

        // --- causal mask (only the last two s-tiles can overlap the diagonal) ---
        if (i >= nst - 2) {
            const int sbase = i * 64;
#pragma unroll
            for (int ni = 0; ni < 8; ni++) {
#pragma unroll
                for (int q = 0; q < 4; q++) {
                    int sg = sbase + ni * 8 + tc * 2 + (q & 1);
                    int tt = t0 + ((q >> 1) << 3);
                    if (sg > tt) acc_s[ni][q] = -1e30f;
                }
            }
        }

        // --- online softmax ---
        float mx0 = -1e30f, mx1 = -1e30f;
#pragma unroll
        for (int ni = 0; ni < 8; ni++) {
            mx0 = fmaxf(mx0, fmaxf(acc_s[ni][0], acc_s[ni][1]));
            mx1 = fmaxf(mx1, fmaxf(acc_s[ni][2], acc_s[ni][3]));
        }
        mx0 = fmaxf(mx0, __shfl_xor_sync(0xffffffffu, mx0, 1));
        mx0 = fmaxf(mx0, __shfl_xor_sync(0xffffffffu, mx0, 2));
        mx1 = fmaxf(mx1, __shfl_xor_sync(0xffffffffu, mx1, 1));
        mx1 = fmaxf(mx1, __shfl_xor_sync(0xffffffffu, mx1, 2));
        float nm0 = fmaxf(m0r, mx0), nm1 = fmaxf(m1r, mx1);
        float sc0 = __expf(m0r - nm0), sc1 = __expf(m1r - nm1);
        m0r = nm0; m1r = nm1;

        float sum0 = 0.f, sum1 = 0.f;
#pragma unroll
        for (int ni = 0; ni < 8; ni++) {
            acc_s[ni][0] = __expf(acc_s[ni][0] - m0r);
            acc_s[ni][1] = __expf(acc_s[ni][1] - m0r);
            acc_s[ni][2] = __expf(acc_s[ni][2] - m1r);
            acc_s[ni][3] = __expf(acc_s[ni][3] - m1r);
            sum0 += acc_s[ni][0] + acc_s[ni][1];
            sum1 += acc_s[ni][2] + acc_s[ni][3];
        }
        sum0 += __shfl_xor_sync(0xffffffffu, sum0, 1);
        sum0 += __shfl_xor_sync(0xffffffffu, sum0, 2);
        sum1 += __shfl_xor_sync(0xffffffffu, sum1, 1);
        sum1 += __shfl_xor_sync(0xffffffffu, sum1, 2);
        l0r = l0r * sc0 + sum0;
        l1r = l1r * sc1 + sum1;

        // rescale running O
#pragma unroll
        for (int nd = 0; nd < 16; nd++) {
            acc_o[nd][0] *= sc0; acc_o[nd][1] *= sc0;
            acc_o[nd][2] *= sc1; acc_o[nd][3] *= sc1;
        }

        // pack P fragments (C-frag -> A-frag identity)
        uint32_t pf[4][4];
#pragma unroll
        for (int kk = 0; kk < 4; kk++) {
            pf[kk][0] = pack2h(acc_s[2 * kk][0],     acc_s[2 * kk][1]);
            pf[kk][1] = pack2h(acc_s[2 * kk][2],     acc_s[2 * kk][3]);
            pf[kk][2] = pack2h(acc_s[2 * kk + 1][0], acc_s[2 * kk + 1][1]);
            pf[kk][3] = pack2h(acc_s[2 * kk + 1][2], acc_s[2 * kk + 1][3]);
        }

        // --- O += P . V ---
#pragma unroll
        for (int kk = 0; kk < 4; kk++) {
#pragma unroll
            for (int nd = 0; nd < 16; nd++) {
                uint32_t b_f[2];
                ldm_x2_trans(vb_ + (kk * 16) * FA_LDK + v_off + nd * 16, b_f);
                mma_f16(acc_o[nd], pf[kk], b_f);
            }
        }
        __syncthreads();
    }

    // epilogue: normalize and store fp16 attn [b,t,h,d]
    const float inv0 = 1.f / l0r, inv1 = 1.f / l1r;
    const int b = bh >> 4, h = bh & (Hh - 1);
#pragma unroll
    for (int nd = 0; nd < 16; nd++) {
        int d = nd * 8 + tc * 2;
        size_t i0 = (((size_t)(b * Tt + t0) * Hh) + h) * DK + d;
        size_t i1 = (((size_t)(b * Tt + t0 + 8) * Hh) + h) * DK + d;
        *reinterpret_cast<__half2*>(g_ah + i0) =
            __halves2half2(__float2half(acc_o[nd][0] * inv0),
                           __float2half(acc_o[nd][1] * inv0));
        *reinterpret_cast<__half2*>(g_ah + i1) =
            __halves2half2(__float2half(acc_o[nd][2] * inv1),
                           __float2half(acc_o[nd][3] * inv1));
    }
}

// ---------------------------------------------------------------------------
extern "C" void kernel_launch(void* const* d_in, const int* in_sizes, int n_in,
                              void* d_out, int out_size) {
    const float* x  = (const float*)d_in[0];
    const float* ck = (const float*)d_in[1];
    const float* cv = (const float*)d_in[2];
    const float* Wq = (const float*)d_in[3];
    const float* Wk = (const float*)d_in[4];
    const float* Wv = (const float*)d_in[5];
    const float* Wo = (const float*)d_in[6];

    float* out  = (float*)d_out;
    float* Kout = out + (size_t)Bb * Tt * Cc;
    float* Vout = Kout + (size_t)Bb * Hh * SS * DK;

    cudaFuncSetAttribute(mm_hmma_kernel, cudaFuncAttributeMaxDynamicSharedMemorySize, MM_SMEM);
    cudaFuncSetAttribute(fa_kernel, cudaFuncAttributeMaxDynamicSharedMemorySize, FA_SMEM);

    convert7_kernel<<<28672, 256>>>((const float4*)x, (const float4*)Wq,
                                    (const float4*)Wk, (const float4*)Wv,
                                    (const float4*)Wo, (const float4*)ck,
                                    (const float4*)cv,
                                    (float4*)Kout, (float4*)Vout);
    mm_hmma_kernel<<<dim3(16, 32, 3), 256, MM_SMEM>>>(0, Kout, Vout, out);
    fa_kernel<<<dim3(8, 32), 256, FA_SMEM>>>();
    mm_hmma_kernel<<<dim3(16, 32, 1), 256, MM_SMEM>>>(1, Kout, Vout, out);
}

// round 12
// speedup vs baseline: 2.6683x; 1.1804x over previous
#include <cuda_runtime.h>
#include <cuda_fp16.h>
#include <math.h>
#include <stdint.h>

// Problem dims
#define Bb 2
#define Tt 1024
#define Cc 2048
#define Hh 16
#define DK 128
#define SC 1024
#define SS 2048
#define KDIM 2048
#define NMAT 4194304ull   // 2048*2048

#define RSQRT_DK 0.08838834764831845f

// HMMA GEMM tiling: CTA tile 128(M) x 128(N) x 32(K), 256 threads,
// 8 warps 2(m) x 4(n), warp tile 64x32. 2 CTAs/SM.
#define MM_BK 32
#define MM_LDS_B 80                        // bytes per smem row (32 fp16 + 16 pad)
#define MM_MATA 10240                      // 128 rows * 80
#define MM_MATB 10240                      // 128 rows * 80
#define MM_STAGE (MM_MATA + MM_MATB)       // 20480
#define MM_SMEM (2 * MM_STAGE)             // 40960
#define MM_KSTEPS (KDIM / MM_BK)           // 64

// Flash-attention tiling: m-tile 128, s-tile 64, d=128, 8 warps (16 rows each)
#define FA_LDQ 272                         // 128 fp16 = 256B + 16 pad
#define FA_LDK 272
#define FA_QBYTES (128 * FA_LDQ)           // 34816
#define FA_KBYTES (64 * FA_LDK)            // 17408
#define FA_KV_STAGE (2 * FA_KBYTES)        // 34816 (K then V)
#define FA_SMEM (FA_QBYTES + 2 * FA_KV_STAGE)  // 104448

// ---------------------------------------------------------------------------
// Scratch (device globals)
// ---------------------------------------------------------------------------
__device__ __half g_xh[NMAT];                             // x fp16
__device__ __half g_w4[4 * NMAT];                         // Wq,Wk,Wv,Wo fp16
__device__ __half g_kc[NMAT];                             // cache_k fp16
__device__ __half g_vc[NMAT];                             // cache_v fp16
__device__ __half g_qh[NMAT];                             // Q fp16 [bh,t,d] scaled
__device__ __half g_ah[NMAT];                             // attn fp16 [b,t,h,d]

// ---------------------------------------------------------------------------
// PTX helpers
// ---------------------------------------------------------------------------
__device__ __forceinline__ uint32_t smem_u32(const void* p) {
    uint32_t a;
    asm("{ .reg .u64 t; cvta.to.shared.u64 t, %1; cvt.u32.u64 %0, t; }" : "=r"(a) : "l"(p));
    return a;
}
#define CP_ASYNC16(saddr, gaddr) \
    asm volatile("cp.async.cg.shared.global [%0], [%1], 16;" :: "r"(saddr), "l"(gaddr))
#define CP_COMMIT() asm volatile("cp.async.commit_group;" ::: "memory")
#define CP_WAIT(n)  asm volatile("cp.async.wait_group %0;" :: "n"(n) : "memory")

__device__ __forceinline__ void ldm_x4(uint32_t addr, uint32_t* r) {
    asm volatile("ldmatrix.sync.aligned.m8n8.x4.shared.b16 {%0,%1,%2,%3}, [%4];"
        : "=r"(r[0]), "=r"(r[1]), "=r"(r[2]), "=r"(r[3]) : "r"(addr));
}
__device__ __forceinline__ void ldm_x2(uint32_t addr, uint32_t* r) {
    asm volatile("ldmatrix.sync.aligned.m8n8.x2.shared.b16 {%0,%1}, [%2];"
        : "=r"(r[0]), "=r"(r[1]) : "r"(addr));
}
__device__ __forceinline__ void ldm_x2_trans(uint32_t addr, uint32_t* r) {
    asm volatile("ldmatrix.sync.aligned.m8n8.x2.trans.shared.b16 {%0,%1}, [%2];"
        : "=r"(r[0]), "=r"(r[1]) : "r"(addr));
}
__device__ __forceinline__ void mma_f16(float* d, const uint32_t* a, const uint32_t* b) {
    asm volatile("mma.sync.aligned.m16n8k16.row.col.f32.f16.f16.f32 "
        "{%0,%1,%2,%3}, {%4,%5,%6,%7}, {%8,%9}, {%0,%1,%2,%3};"
        : "+f"(d[0]), "+f"(d[1]), "+f"(d[2]), "+f"(d[3])
        : "r"(a[0]), "r"(a[1]), "r"(a[2]), "r"(a[3]), "r"(b[0]), "r"(b[1]));
}
__device__ __forceinline__ uint32_t pack2h(float a, float b) {
    __half2 h = __floats2half2_rn(a, b);
    return *reinterpret_cast<uint32_t*>(&h);
}

// ---------------------------------------------------------------------------
// conversions (fused with cache copy): all 7 matrices -> fp16;
// ck/cv also copied fp32 into output K/V slots
// ---------------------------------------------------------------------------
__global__ void convert7_kernel(const float4* __restrict__ x,
                                const float4* __restrict__ wq,
                                const float4* __restrict__ wk,
                                const float4* __restrict__ wv,
                                const float4* __restrict__ wo,
                                const float4* __restrict__ ck,
                                const float4* __restrict__ cv,
                                float4* __restrict__ Kout,
                                float4* __restrict__ Vout) {
    int id = blockIdx.x * blockDim.x + threadIdx.x;
    const int per = (int)(NMAT / 4);
    int mat = id / per;
    int rem = id - mat * per;
    const float4* srcs[7] = {x, wq, wk, wv, wo, ck, cv};
    float4 v = srcs[mat][rem];
    __half* base;
    if (mat == 0)      base = g_xh;
    else if (mat <= 4) base = g_w4 + (size_t)(mat - 1) * NMAT;
    else if (mat == 5) base = g_kc;
    else               base = g_vc;
    __half2* d = reinterpret_cast<__half2*>(base) + rem * 2;
    d[0] = __halves2half2(__float2half(v.x), __float2half(v.y));
    d[1] = __halves2half2(__float2half(v.z), __float2half(v.w));
    if (mat >= 5) {
        int pos = rem & 31;
        int row = rem >> 5;
        int s = row & (SC - 1);
        int bh = row >> 10;
        int dst = (((bh * SS) + s) << 5) + pos;
        ((mat == 5) ? Kout : Vout)[dst] = v;
    }
}

// ---------------------------------------------------------------------------
// HMMA fp16 GEMM (256 threads, 8 warps 2x4, CTA tile 128x128, warp tile 64x32)
// mode 0: A=x, B=W[proj]; Q -> fp16 (scaled), K/V -> d_out fp32
// mode 1: A=attn, B=Wo; -> out fp32
// ---------------------------------------------------------------------------
__global__ __launch_bounds__(256, 2)
void mm_hmma_kernel(int mode, float* __restrict__ Kout, float* __restrict__ Vout,
                    float* __restrict__ out) {
    extern __shared__ char sm[];
    const uint32_t sbu = smem_u32(sm);
    const int tid = threadIdx.x;
    const int wid = tid >> 5, lane = tid & 31;
    const int warp_m = wid >> 2;          // 0..1
    const int warp_n = wid & 3;           // 0..3

    const int proj = blockIdx.z;
    const __half *As, *Bs;
    if (mode == 0) {
        As = g_xh;
        Bs = g_w4 + (size_t)proj * NMAT;
    } else {
        As = g_ah;
        Bs = g_w4 + (size_t)3 * NMAT;
    }
    const int m0 = blockIdx.x * 128, n0 = blockIdx.y * 128;

    // cp.async: 1024 16B chunks per stage, 4 per thread
    const __half* gptr[4];
    uint32_t soff[4];
#pragma unroll
    for (int j = 0; j < 4; j++) {
        int c = j * 256 + tid;
        int idx = c & 511;
        int r = idx >> 2, c16 = idx & 3;
        if (c < 512) {
            gptr[j] = As + (size_t)(m0 + r) * KDIM + c16 * 8;
            soff[j] = (uint32_t)(r * MM_LDS_B + c16 * 16);
        } else {
            gptr[j] = Bs + (size_t)(n0 + r) * KDIM + c16 * 8;
            soff[j] = (uint32_t)(MM_MATA + r * MM_LDS_B + c16 * 16);
        }
    }

    const uint32_t a_row = (uint32_t)(warp_m * 64 + (lane & 15));
    const uint32_t a_kb  = (uint32_t)(((lane >> 4) << 3) * 2);
    const uint32_t b_row = (uint32_t)(warp_n * 32 + (lane & 7));
    const uint32_t b_kb  = (uint32_t)((((lane >> 3) & 1) << 3) * 2);

    float acc[4][4][4];
#pragma unroll
    for (int mi = 0; mi < 4; mi++)
#pragma unroll
        for (int ni = 0; ni < 4; ni++)
#pragma unroll
            for (int q = 0; q < 4; q++) acc[mi][ni][q] = 0.f;

#pragma unroll
    for (int j = 0; j < 4; j++) CP_ASYNC16(sbu + soff[j], gptr[j]);
    CP_COMMIT();

    for (int i = 0; i < MM_KSTEPS; i++) {
        const int s = i & 1;
        if (i + 1 < MM_KSTEPS) {
            const uint32_t sb2 = sbu + ((i + 1) & 1) * MM_STAGE;
            const int k0 = (i + 1) * MM_BK;
#pragma unroll
            for (int j = 0; j < 4; j++) CP_ASYNC16(sb2 + soff[j], gptr[j] + k0);
            CP_COMMIT();
            CP_WAIT(1);
        } else {
            CP_WAIT(0);
        }
        __syncthreads();

        const uint32_t stage = sbu + s * MM_STAGE;
#pragma unroll
        for (int kk = 0; kk < 2; kk++) {
            const uint32_t kb = (uint32_t)(kk * 32);
            uint32_t a_f[4][4], b_f[4][2];
#pragma unroll
            for (int ni = 0; ni < 4; ni++) {
                uint32_t baddr = stage + MM_MATA +
                                 (b_row + ni * 8) * MM_LDS_B + b_kb + kb;
                ldm_x2(baddr, b_f[ni]);
            }
#pragma unroll
            for (int mi = 0; mi < 4; mi++) {
                uint32_t aaddr = stage + (a_row + mi * 16) * MM_LDS_B + a_kb + kb;
                ldm_x4(aaddr, a_f[mi]);
            }
#pragma unroll
            for (int mi = 0; mi < 4; mi++)
#pragma unroll
                for (int ni = 0; ni < 4; ni++)
                    mma_f16(acc[mi][ni], a_f[mi], b_f[ni]);
        }
        __syncthreads();
    }

    const int gid = lane >> 2, tc = lane & 3;
#pragma unroll
    for (int mi = 0; mi < 4; mi++) {
#pragma unroll
        for (int ni = 0; ni < 4; ni++) {
            int mrow0 = m0 + warp_m * 64 + mi * 16 + gid;
            int ncol  = n0 + warp_n * 32 + ni * 8 + tc * 2;
#pragma unroll
            for (int half = 0; half < 2; half++) {
                int m = mrow0 + half * 8;
                float v0 = acc[mi][ni][half * 2 + 0];
                float v1 = acc[mi][ni][half * 2 + 1];
                if (mode == 0) {
                    int b = m >> 10, t = m & (Tt - 1);
                    int h = ncol >> 7, d = ncol & (DK - 1);
                    if (proj == 0) {
                        size_t qi = (((size_t)(b * Hh + h) * Tt) + t) * DK + d;
                        *reinterpret_cast<__half2*>(g_qh + qi) =
                            __halves2half2(__float2half(v0 * RSQRT_DK),
                                           __float2half(v1 * RSQRT_DK));
                    } else {
                        float* base = (proj == 1) ? Kout : Vout;
                        float* dst = base + (((size_t)(b * Hh + h) * SS) + SC + t) * DK + d;
                        float2 vv; vv.x = v0; vv.y = v1;
                        *reinterpret_cast<float2*>(dst) = vv;
                    }
                } else {
                    float* dst = out + (size_t)m * Cc + ncol;
                    float2 vv; vv.x = v0; vv.y = v1;
                    *reinterpret_cast<float2*>(dst) = vv;
                }
            }
        }
    }
}

// ---------------------------------------------------------------------------
// Fused flash attention (unchanged from R11): per CTA (bh, 128-row m-tile).
// ---------------------------------------------------------------------------
__global__ __launch_bounds__(256, 1)
void fa_kernel() {
    extern __shared__ char sm[];
    const uint32_t sbu = smem_u32(sm);
    const int tid = threadIdx.x;
    const int wid = tid >> 5, lane = tid & 31;
    const int gid = lane >> 2, tc = lane & 3;

    const int mt = 7 - blockIdx.x;        // heavy tiles first
    const int bh = blockIdx.y;
    const int m0 = mt * 128;
    const int nst = (mt + 1) * 2;         // 64-row s-tiles (causal)

    const __half* Qg = g_qh + (size_t)bh * Tt * DK + (size_t)m0 * DK;
    const __half* Kg = g_kc + (size_t)bh * SC * DK;
    const __half* Vg = g_vc + (size_t)bh * SC * DK;

    const uint32_t qs  = sbu;
    const uint32_t kvs = sbu + FA_QBYTES;

#pragma unroll
    for (int j = 0; j < 8; j++) {
        int c = j * 256 + tid;
        int row = c >> 4, col = c & 15;
        CP_ASYNC16(qs + row * FA_LDQ + col * 16, Qg + (size_t)row * DK + col * 8);
    }
    const __half* kvg[8];
    uint32_t kvo[8];
#pragma unroll
    for (int j = 0; j < 8; j++) {
        int c = j * 256 + tid;
        int mat = c >> 10;
        int idx = c & 1023;
        int row = idx >> 4, col = idx & 15;
        kvg[j] = (mat ? Vg : Kg) + (size_t)row * DK + col * 8;
        kvo[j] = (uint32_t)(mat * FA_KBYTES + row * FA_LDK + col * 16);
    }
#pragma unroll
    for (int j = 0; j < 8; j++) CP_ASYNC16(kvs + kvo[j], kvg[j]);
    CP_COMMIT();

    float acc_o[16][4];
#pragma unroll
    for (int nd = 0; nd < 16; nd++)
#pragma unroll
        for (int q = 0; q < 4; q++) acc_o[nd][q] = 0.f;

    float m0r = -1e30f, m1r = -1e30f, l0r = 0.f, l1r = 0.f;
    const int t0 = m0 + wid * 16 + gid;

    const uint32_t a_off = (uint32_t)((wid * 16 + (lane & 15)) * FA_LDQ + ((lane >> 4) << 4));
    const uint32_t b_off = (uint32_t)((lane & 7) * FA_LDK + (((lane >> 3) & 1) << 4));
    const uint32_t v_off = (uint32_t)((lane & 15) * FA_LDK);

    for (int i = 0; i < nst; i++) {
        const int s = i & 1;
        if (i + 1 < nst) {
            const uint32_t kv2 = kvs + ((i + 1) & 1) * FA_KV_STAGE;
            const size_t off = (size_t)(i + 1) * 64 * DK;
#pragma unroll
            for (int j = 0; j < 8; j++) CP_ASYNC16(kv2 + kvo[j], kvg[j] + off);
            CP_COMMIT();
            CP_WAIT(1);
        } else {
            CP_WAIT(0);
        }
        __syncthreads();

        const uint32_t kb_ = kvs + s * FA_KV_STAGE;
        const uint32_t vb_ = kb_ + FA_KBYTES;

        float acc_s[8][4];
#pragma unroll
        for (int ni = 0; ni < 8; ni++)
#pragma unroll
            for (int q = 0; q < 4; q++) acc_s[ni][q] = 0.f;
#pragma unroll
        for (int kk = 0; kk < 8; kk++) {
            uint32_t a_f[4];
            ldm_x4(qs + a_off + kk * 32, a_f);
#pragma unroll
            for (int ni = 0; ni < 8; ni++) {
                uint32_t b_f[2];
                ldm_x2(kb_ + b_off + ni * 8 * FA_LDK + kk * 32, b_f);
                mma_f16(acc_s[ni], a_f, b_f);
            }
        }

        if (i >= nst - 2) {
            const int sbase = i * 64;
#pragma unroll
            for (int ni = 0; ni < 8; ni++) {
#pragma unroll
                for (int q = 0; q < 4; q++) {
                    int sg = sbase + ni * 8 + tc * 2 + (q & 1);
                    int tt = t0 + ((q >> 1) << 3);
                    if (sg > tt) acc_s[ni][q] = -1e30f;
                }
            }
        }

        float mx0 = -1e30f, mx1 = -1e30f;
#pragma unroll
        for (int ni = 0; ni < 8; ni++) {
            mx0 = fmaxf(mx0, fmaxf(acc_s[ni][0], acc_s[ni][1]));
            mx1 = fmaxf(mx1, fmaxf(acc_s[ni][2], acc_s[ni][3]));
        }
        mx0 = fmaxf(mx0, __shfl_xor_sync(0xffffffffu, mx0, 1));
        mx0 = fmaxf(mx0, __shfl_xor_sync(0xffffffffu, mx0, 2));
        mx1 = fmaxf(mx1, __shfl_xor_sync(0xffffffffu, mx1, 1));
        mx1 = fmaxf(mx1, __shfl_xor_sync(0xffffffffu, mx1, 2));
        float nm0 = fmaxf(m0r, mx0), nm1 = fmaxf(m1r, mx1);
        float sc0 = __expf(m0r - nm0), sc1 = __expf(m1r - nm1);
        m0r = nm0; m1r = nm1;

        float sum0 = 0.f, sum1 = 0.f;
#pragma unroll
        for (int ni = 0; ni < 8; ni++) {
            acc_s[ni][0] = __expf(acc_s[ni][0] - m0r);
            acc_s[ni][1] = __expf(acc_s[ni][1] - m0r);
            acc_s[ni][2] = __expf(acc_s[ni][2] - m1r);
            acc_s[ni][3] = __expf(acc_s[ni][3] - m1r);
            sum0 += acc_s[ni][0] + acc_s[ni][1];
            sum1 += acc_s[ni][2] + acc_s[ni][3];
        }
        sum0 += __shfl_xor_sync(0xffffffffu, sum0, 1);
        sum0 += __shfl_xor_sync(0xffffffffu, sum0, 2);
        sum1 += __shfl_xor_sync(0xffffffffu, sum1, 1);
        sum1 += __shfl_xor_sync(0xffffffffu, sum1, 2);
        l0r = l0r * sc0 + sum0;
        l1r = l1r * sc1 + sum1;

#pragma unroll
        for (int nd = 0; nd < 16; nd++) {
            acc_o[nd][0] *= sc0; acc_o[nd][1] *= sc0;
            acc_o[nd][2] *= sc1; acc_o[nd][3] *= sc1;
        }

        uint32_t pf[4][4];
#pragma unroll
        for (int kk = 0; kk < 4; kk++) {
            pf[kk][0] = pack2h(acc_s[2 * kk][0],     acc_s[2 * kk][1]);
            pf[kk][1] = pack2h(acc_s[2 * kk][2],     acc_s[2 * kk][3]);
            pf[kk][2] = pack2h(acc_s[2 * kk + 1][0], acc_s[2 * kk + 1][1]);
            pf[kk][3] = pack2h(acc_s[2 * kk + 1][2], acc_s[2 * kk + 1][3]);
        }

#pragma unroll
        for (int kk = 0; kk < 4; kk++) {
#pragma unroll
            for (int nd = 0; nd < 16; nd++) {
                uint32_t b_f[2];
                ldm_x2_trans(vb_ + (kk * 16) * FA_LDK + v_off + nd * 16, b_f);
                mma_f16(acc_o[nd], pf[kk], b_f);
            }
        }
        __syncthreads();
    }

    const float inv0 = 1.f / l0r, inv1 = 1.f / l1r;
    const int b = bh >> 4, h = bh & (Hh - 1);
#pragma unroll
    for (int nd = 0; nd < 16; nd++) {
        int d = nd * 8 + tc * 2;
        size_t i0 = (((size_t)(b * Tt + t0) * Hh) + h) * DK + d;
        size_t i1 = (((size_t)(b * Tt + t0 + 8) * Hh) + h) * DK + d;
        *reinterpret_cast<__half2*>(g_ah + i0) =
            __halves2half2(__float2half(acc_o[nd][0] * inv0),
                           __float2half(acc_o[nd][1] * inv0));
        *reinterpret_cast<__half2*>(g_ah + i1) =
            __halves2half2(__float2half(acc_o[nd][2] * inv1),
                           __float2half(acc_o[nd][3] * inv1));
    }
}

// ---------------------------------------------------------------------------
extern "C" void kernel_launch(void* const* d_in, const int* in_sizes, int n_in,
                              void* d_out, int out_size) {
    const float* x  = (const float*)d_in[0];
    const float* ck = (const float*)d_in[1];
    const float* cv = (const float*)d_in[2];
    const float* Wq = (const float*)d_in[3];
    const float* Wk = (const float*)d_in[4];
    const float* Wv = (const float*)d_in[5];
    const float* Wo = (const float*)d_in[6];

    float* out  = (float*)d_out;
    float* Kout = out + (size_t)Bb * Tt * Cc;
    float* Vout = Kout + (size_t)Bb * Hh * SS * DK;

    cudaFuncSetAttribute(mm_hmma_kernel, cudaFuncAttributeMaxDynamicSharedMemorySize, MM_SMEM);
    cudaFuncSetAttribute(fa_kernel, cudaFuncAttributeMaxDynamicSharedMemorySize, FA_SMEM);

    convert7_kernel<<<28672, 256>>>((const float4*)x, (const float4*)Wq,
                                    (const float4*)Wk, (const float4*)Wv,
                                    (const float4*)Wo, (const float4*)ck,
                                    (const float4*)cv,
                                    (float4*)Kout, (float4*)Vout);
    mm_hmma_kernel<<<dim3(16, 16, 3), 256, MM_SMEM>>>(0, Kout, Vout, out);
    fa_kernel<<<dim3(8, 32), 256, FA_SMEM>>>();
    mm_hmma_kernel<<<dim3(16, 16, 1), 256, MM_SMEM>>>(1, Kout, Vout, out);
}

// round 13
// speedup vs baseline: 2.9436x; 1.1032x over previous
#include <cuda_runtime.h>
#include <cuda_fp16.h>
#include <math.h>
#include <stdint.h>

// Problem dims
#define Bb 2
#define Tt 1024
#define Cc 2048
#define Hh 16
#define DK 128
#define SC 1024
#define SS 2048
#define KDIM 2048
#define NMAT 4194304ull   // 2048*2048

#define RSQRT_DK 0.08838834764831845f

// HMMA GEMM tiling: CTA tile 128(M) x 128(N) x 32(K), 256 threads,
// 8 warps 2(m) x 4(n), warp tile 64x32. 3-stage cp.async pipeline.
#define MM_BK 32
#define MM_LDS_B 80                        // bytes per smem row (32 fp16 + 16 pad)
#define MM_MATA 10240                      // 128 rows * 80
#define MM_STAGE (2 * MM_MATA)             // 20480 (A + B)
#define MM_NSTG 3
#define MM_SMEM (MM_NSTG * MM_STAGE)       // 61440
#define MM_KSTEPS (KDIM / MM_BK)           // 64

// Flash-attention tiling: m-tile 128, s-tile 64, d=128, 8 warps (16 rows each)
#define FA_LDQ 272
#define FA_LDK 272
#define FA_QBYTES (128 * FA_LDQ)           // 34816
#define FA_KBYTES (64 * FA_LDK)            // 17408
#define FA_KV_STAGE (2 * FA_KBYTES)        // 34816
#define FA_SMEM (FA_QBYTES + 2 * FA_KV_STAGE)  // 104448

// ---------------------------------------------------------------------------
// Scratch (device globals)
// ---------------------------------------------------------------------------
__device__ __half g_xh[NMAT];                             // x fp16
__device__ __half g_w4[4 * NMAT];                         // Wq,Wk,Wv,Wo fp16
__device__ __half g_kc[NMAT];                             // cache_k fp16
__device__ __half g_vc[NMAT];                             // cache_v fp16
__device__ __half g_qh[NMAT];                             // Q fp16 [bh,t,d] scaled
__device__ __half g_ah[NMAT];                             // attn fp16 [b,t,h,d]

// ---------------------------------------------------------------------------
// PTX helpers
// ---------------------------------------------------------------------------
__device__ __forceinline__ uint32_t smem_u32(const void* p) {
    uint32_t a;
    asm("{ .reg .u64 t; cvta.to.shared.u64 t, %1; cvt.u32.u64 %0, t; }" : "=r"(a) : "l"(p));
    return a;
}
#define CP_ASYNC16(saddr, gaddr) \
    asm volatile("cp.async.cg.shared.global [%0], [%1], 16;" :: "r"(saddr), "l"(gaddr))
#define CP_COMMIT() asm volatile("cp.async.commit_group;" ::: "memory")
#define CP_WAIT(n)  asm volatile("cp.async.wait_group %0;" :: "n"(n) : "memory")

__device__ __forceinline__ void ldm_x4(uint32_t addr, uint32_t* r) {
    asm volatile("ldmatrix.sync.aligned.m8n8.x4.shared.b16 {%0,%1,%2,%3}, [%4];"
        : "=r"(r[0]), "=r"(r[1]), "=r"(r[2]), "=r"(r[3]) : "r"(addr));
}
__device__ __forceinline__ void ldm_x2(uint32_t addr, uint32_t* r) {
    asm volatile("ldmatrix.sync.aligned.m8n8.x2.shared.b16 {%0,%1}, [%2];"
        : "=r"(r[0]), "=r"(r[1]) : "r"(addr));
}
__device__ __forceinline__ void ldm_x2_trans(uint32_t addr, uint32_t* r) {
    asm volatile("ldmatrix.sync.aligned.m8n8.x2.trans.shared.b16 {%0,%1}, [%2];"
        : "=r"(r[0]), "=r"(r[1]) : "r"(addr));
}
__device__ __forceinline__ void mma_f16(float* d, const uint32_t* a, const uint32_t* b) {
    asm volatile("mma.sync.aligned.m16n8k16.row.col.f32.f16.f16.f32 "
        "{%0,%1,%2,%3}, {%4,%5,%6,%7}, {%8,%9}, {%0,%1,%2,%3};"
        : "+f"(d[0]), "+f"(d[1]), "+f"(d[2]), "+f"(d[3])
        : "r"(a[0]), "r"(a[1]), "r"(a[2]), "r"(a[3]), "r"(b[0]), "r"(b[1]));
}
__device__ __forceinline__ uint32_t pack2h(float a, float b) {
    __half2 h = __floats2half2_rn(a, b);
    return *reinterpret_cast<uint32_t*>(&h);
}

// ---------------------------------------------------------------------------
// conversions (fused with cache copy)
// ---------------------------------------------------------------------------
__global__ void convert7_kernel(const float4* __restrict__ x,
                                const float4* __restrict__ wq,
                                const float4* __restrict__ wk,
                                const float4* __restrict__ wv,
                                const float4* __restrict__ wo,
                                const float4* __restrict__ ck,
                                const float4* __restrict__ cv,
                                float4* __restrict__ Kout,
                                float4* __restrict__ Vout) {
    int id = blockIdx.x * blockDim.x + threadIdx.x;
    const int per = (int)(NMAT / 4);
    int mat = id / per;
    int rem = id - mat * per;
    const float4* srcs[7] = {x, wq, wk, wv, wo, ck, cv};
    float4 v = srcs[mat][rem];
    __half* base;
    if (mat == 0)      base = g_xh;
    else if (mat <= 4) base = g_w4 + (size_t)(mat - 1) * NMAT;
    else if (mat == 5) base = g_kc;
    else               base = g_vc;
    __half2* d = reinterpret_cast<__half2*>(base) + rem * 2;
    d[0] = __halves2half2(__float2half(v.x), __float2half(v.y));
    d[1] = __halves2half2(__float2half(v.z), __float2half(v.w));
    if (mat >= 5) {
        int pos = rem & 31;
        int row = rem >> 5;
        int s = row & (SC - 1);
        int bh = row >> 10;
        int dst = (((bh * SS) + s) << 5) + pos;
        ((mat == 5) ? Kout : Vout)[dst] = v;
    }
}

// ---------------------------------------------------------------------------
// HMMA fp16 GEMM (256 threads, 8 warps 2x4, CTA 128x128, warp 64x32,
// 3-stage pipeline, one barrier per k-iter, x4 B loads)
// ---------------------------------------------------------------------------
__global__ __launch_bounds__(256, 2)
void mm_hmma_kernel(int mode, float* __restrict__ Kout, float* __restrict__ Vout,
                    float* __restrict__ out) {
    extern __shared__ char sm[];
    const uint32_t sbu = smem_u32(sm);
    const int tid = threadIdx.x;
    const int wid = tid >> 5, lane = tid & 31;
    const int warp_m = wid >> 2;          // 0..1
    const int warp_n = wid & 3;           // 0..3

    const int proj = blockIdx.z;
    const __half *As, *Bs;
    if (mode == 0) {
        As = g_xh;
        Bs = g_w4 + (size_t)proj * NMAT;
    } else {
        As = g_ah;
        Bs = g_w4 + (size_t)3 * NMAT;
    }
    const int m0 = blockIdx.x * 128, n0 = blockIdx.y * 128;

    // cp.async: 1024 16B chunks per stage, 4 per thread
    const __half* gptr[4];
    uint32_t soff[4];
#pragma unroll
    for (int j = 0; j < 4; j++) {
        int c = j * 256 + tid;
        int idx = c & 511;
        int r = idx >> 2, c16 = idx & 3;
        if (c < 512) {
            gptr[j] = As + (size_t)(m0 + r) * KDIM + c16 * 8;
            soff[j] = (uint32_t)(r * MM_LDS_B + c16 * 16);
        } else {
            gptr[j] = Bs + (size_t)(n0 + r) * KDIM + c16 * 8;
            soff[j] = (uint32_t)(MM_MATA + r * MM_LDS_B + c16 * 16);
        }
    }

    const uint32_t a_row  = (uint32_t)(warp_m * 64 + (lane & 15));
    const uint32_t a_kb   = (uint32_t)(((lane >> 4) << 3) * 2);
    // x4 B: lanes 0-7 row n+(l&7) kcol0, 8-15 same rows kcol16, 16-23 rows+8 kcol0, 24-31 rows+8 kcol16
    const uint32_t b_row4 = (uint32_t)(warp_n * 32 + (lane & 7) + ((lane >> 4) << 3));
    const uint32_t b_kb4  = (uint32_t)(((lane >> 3) & 1) << 4);

    float acc[4][4][4];
#pragma unroll
    for (int mi = 0; mi < 4; mi++)
#pragma unroll
        for (int ni = 0; ni < 4; ni++)
#pragma unroll
            for (int q = 0; q < 4; q++) acc[mi][ni][q] = 0.f;

    // prologue: stages 0 and 1
#pragma unroll
    for (int p = 0; p < 2; p++) {
        const uint32_t sb = sbu + p * MM_STAGE;
#pragma unroll
        for (int j = 0; j < 4; j++) CP_ASYNC16(sb + soff[j], gptr[j] + p * MM_BK);
        CP_COMMIT();
    }

    int stage_i = 0;   // i % 3
    for (int i = 0; i < MM_KSTEPS; i++) {
        CP_WAIT(1);
        __syncthreads();

        // refill stage (i+2)%3 (its previous contents finished computing pre-barrier)
        if (i + 2 < MM_KSTEPS) {
            int sw = stage_i + 2; if (sw >= MM_NSTG) sw -= MM_NSTG;
            const uint32_t sb2 = sbu + sw * MM_STAGE;
            const int k0 = (i + 2) * MM_BK;
#pragma unroll
            for (int j = 0; j < 4; j++) CP_ASYNC16(sb2 + soff[j], gptr[j] + k0);
        }
        CP_COMMIT();   // commit even when empty to keep group accounting uniform

        const uint32_t stage = sbu + stage_i * MM_STAGE;
#pragma unroll
        for (int kk = 0; kk < 2; kk++) {
            const uint32_t kb = (uint32_t)(kk * 32);
            uint32_t a_f[4][4], b4[2][4];
#pragma unroll
            for (int nj = 0; nj < 2; nj++) {
                uint32_t baddr = stage + MM_MATA +
                                 (b_row4 + nj * 16) * MM_LDS_B + b_kb4 + kb;
                ldm_x4(baddr, b4[nj]);
            }
#pragma unroll
            for (int mi = 0; mi < 4; mi++) {
                uint32_t aaddr = stage + (a_row + mi * 16) * MM_LDS_B + a_kb + kb;
                ldm_x4(aaddr, a_f[mi]);
            }
#pragma unroll
            for (int mi = 0; mi < 4; mi++)
#pragma unroll
                for (int ni = 0; ni < 4; ni++)
                    mma_f16(acc[mi][ni], a_f[mi], &b4[ni >> 1][(ni & 1) * 2]);
        }
        if (++stage_i == MM_NSTG) stage_i = 0;
    }

    const int gid = lane >> 2, tc = lane & 3;
#pragma unroll
    for (int mi = 0; mi < 4; mi++) {
#pragma unroll
        for (int ni = 0; ni < 4; ni++) {
            int mrow0 = m0 + warp_m * 64 + mi * 16 + gid;
            int ncol  = n0 + warp_n * 32 + ni * 8 + tc * 2;
#pragma unroll
            for (int half = 0; half < 2; half++) {
                int m = mrow0 + half * 8;
                float v0 = acc[mi][ni][half * 2 + 0];
                float v1 = acc[mi][ni][half * 2 + 1];
                if (mode == 0) {
                    int b = m >> 10, t = m & (Tt - 1);
                    int h = ncol >> 7, d = ncol & (DK - 1);
                    if (proj == 0) {
                        size_t qi = (((size_t)(b * Hh + h) * Tt) + t) * DK + d;
                        *reinterpret_cast<__half2*>(g_qh + qi) =
                            __halves2half2(__float2half(v0 * RSQRT_DK),
                                           __float2half(v1 * RSQRT_DK));
                    } else {
                        float* base = (proj == 1) ? Kout : Vout;
                        float* dst = base + (((size_t)(b * Hh + h) * SS) + SC + t) * DK + d;
                        float2 vv; vv.x = v0; vv.y = v1;
                        *reinterpret_cast<float2*>(dst) = vv;
                    }
                } else {
                    float* dst = out + (size_t)m * Cc + ncol;
                    float2 vv; vv.x = v0; vv.y = v1;
                    *reinterpret_cast<float2*>(dst) = vv;
                }
            }
        }
    }
}

// ---------------------------------------------------------------------------
// Fused flash attention (unchanged from R11/R12)
// ---------------------------------------------------------------------------
__global__ __launch_bounds__(256, 1)
void fa_kernel() {
    extern __shared__ char sm[];
    const uint32_t sbu = smem_u32(sm);
    const int tid = threadIdx.x;
    const int wid = tid >> 5, lane = tid & 31;
    const int gid = lane >> 2, tc = lane & 3;

    const int mt = 7 - blockIdx.x;
    const int bh = blockIdx.y;
    const int m0 = mt * 128;
    const int nst = (mt + 1) * 2;

    const __half* Qg = g_qh + (size_t)bh * Tt * DK + (size_t)m0 * DK;
    const __half* Kg = g_kc + (size_t)bh * SC * DK;
    const __half* Vg = g_vc + (size_t)bh * SC * DK;

    const uint32_t qs  = sbu;
    const uint32_t kvs = sbu + FA_QBYTES;

#pragma unroll
    for (int j = 0; j < 8; j++) {
        int c = j * 256 + tid;
        int row = c >> 4, col = c & 15;
        CP_ASYNC16(qs + row * FA_LDQ + col * 16, Qg + (size_t)row * DK + col * 8);
    }
    const __half* kvg[8];
    uint32_t kvo[8];
#pragma unroll
    for (int j = 0; j < 8; j++) {
        int c = j * 256 + tid;
        int mat = c >> 10;
        int idx = c & 1023;
        int row = idx >> 4, col = idx & 15;
        kvg[j] = (mat ? Vg : Kg) + (size_t)row * DK + col * 8;
        kvo[j] = (uint32_t)(mat * FA_KBYTES + row * FA_LDK + col * 16);
    }
#pragma unroll
    for (int j = 0; j < 8; j++) CP_ASYNC16(kvs + kvo[j], kvg[j]);
    CP_COMMIT();

    float acc_o[16][4];
#pragma unroll
    for (int nd = 0; nd < 16; nd++)
#pragma unroll
        for (int q = 0; q < 4; q++) acc_o[nd][q] = 0.f;

    float m0r = -1e30f, m1r = -1e30f, l0r = 0.f, l1r = 0.f;
    const int t0 = m0 + wid * 16 + gid;

    const uint32_t a_off = (uint32_t)((wid * 16 + (lane & 15)) * FA_LDQ + ((lane >> 4) << 4));
    const uint32_t b_off = (uint32_t)((lane & 7) * FA_LDK + (((lane >> 3) & 1) << 4));
    const uint32_t v_off = (uint32_t)((lane & 15) * FA_LDK);

    for (int i = 0; i < nst; i++) {
        const int s = i & 1;
        if (i + 1 < nst) {
            const uint32_t kv2 = kvs + ((i + 1) & 1) * FA_KV_STAGE;
            const size_t off = (size_t)(i + 1) * 64 * DK;
#pragma unroll
            for (int j = 0; j < 8; j++) CP_ASYNC16(kv2 + kvo[j], kvg[j] + off);
            CP_COMMIT();
            CP_WAIT(1);
        } else {
            CP_WAIT(0);
        }
        __syncthreads();

        const uint32_t kb_ = kvs + s * FA_KV_STAGE;
        const uint32_t vb_ = kb_ + FA_KBYTES;

        float acc_s[8][4];
#pragma unroll
        for (int ni = 0; ni < 8; ni++)
#pragma unroll
            for (int q = 0; q < 4; q++) acc_s[ni][q] = 0.f;
#pragma unroll
        for (int kk = 0; kk < 8; kk++) {
            uint32_t a_f[4];
            ldm_x4(qs + a_off + kk * 32, a_f);
#pragma unroll
            for (int ni = 0; ni < 8; ni++) {
                uint32_t b_f[2];
                ldm_x2(kb_ + b_off + ni * 8 * FA_LDK + kk * 32, b_f);
                mma_f16(acc_s[ni], a_f, b_f);
            }
        }

        if (i >= nst - 2) {
            const int sbase = i * 64;
#pragma unroll
            for (int ni = 0; ni < 8; ni++) {
#pragma unroll
                for (int q = 0; q < 4; q++) {
                    int sg = sbase + ni * 8 + tc * 2 + (q & 1);
                    int tt = t0 + ((q >> 1) << 3);
                    if (sg > tt) acc_s[ni][q] = -1e30f;
                }
            }
        }

        float mx0 = -1e30f, mx1 = -1e30f;
#pragma unroll
        for (int ni = 0; ni < 8; ni++) {
            mx0 = fmaxf(mx0, fmaxf(acc_s[ni][0], acc_s[ni][1]));
            mx1 = fmaxf(mx1, fmaxf(acc_s[ni][2], acc_s[ni][3]));
        }
        mx0 = fmaxf(mx0, __shfl_xor_sync(0xffffffffu, mx0, 1));
        mx0 = fmaxf(mx0, __shfl_xor_sync(0xffffffffu, mx0, 2));
        mx1 = fmaxf(mx1, __shfl_xor_sync(0xffffffffu, mx1, 1));
        mx1 = fmaxf(mx1, __shfl_xor_sync(0xffffffffu, mx1, 2));
        float nm0 = fmaxf(m0r, mx0), nm1 = fmaxf(m1r, mx1);
        float sc0 = __expf(m0r - nm0), sc1 = __expf(m1r - nm1);
        m0r = nm0; m1r = nm1;

        float sum0 = 0.f, sum1 = 0.f;
#pragma unroll
        for (int ni = 0; ni < 8; ni++) {
            acc_s[ni][0] = __expf(acc_s[ni][0] - m0r);
            acc_s[ni][1] = __expf(acc_s[ni][1] - m0r);
            acc_s[ni][2] = __expf(acc_s[ni][2] - m1r);
            acc_s[ni][3] = __expf(acc_s[ni][3] - m1r);
            sum0 += acc_s[ni][0] + acc_s[ni][1];
            sum1 += acc_s[ni][2] + acc_s[ni][3];
        }
        sum0 += __shfl_xor_sync(0xffffffffu, sum0, 1);
        sum0 += __shfl_xor_sync(0xffffffffu, sum0, 2);
        sum1 += __shfl_xor_sync(0xffffffffu, sum1, 1);
        sum1 += __shfl_xor_sync(0xffffffffu, sum1, 2);
        l0r = l0r * sc0 + sum0;
        l1r = l1r * sc1 + sum1;

#pragma unroll
        for (int nd = 0; nd < 16; nd++) {
            acc_o[nd][0] *= sc0; acc_o[nd][1] *= sc0;
            acc_o[nd][2] *= sc1; acc_o[nd][3] *= sc1;
        }

        uint32_t pf[4][4];
#pragma unroll
        for (int kk = 0; kk < 4; kk++) {
            pf[kk][0] = pack2h(acc_s[2 * kk][0],     acc_s[2 * kk][1]);
            pf[kk][1] = pack2h(acc_s[2 * kk][2],     acc_s[2 * kk][3]);
            pf[kk][2] = pack2h(acc_s[2 * kk + 1][0], acc_s[2 * kk + 1][1]);
            pf[kk][3] = pack2h(acc_s[2 * kk + 1][2], acc_s[2 * kk + 1][3]);
        }

#pragma unroll
        for (int kk = 0; kk < 4; kk++) {
#pragma unroll
            for (int nd = 0; nd < 16; nd++) {
                uint32_t b_f[2];
                ldm_x2_trans(vb_ + (kk * 16) * FA_LDK + v_off + nd * 16, b_f);
                mma_f16(acc_o[nd], pf[kk], b_f);
            }
        }
        __syncthreads();
    }

    const float inv0 = 1.f / l0r, inv1 = 1.f / l1r;
    const int b = bh >> 4, h = bh & (Hh - 1);
#pragma unroll
    for (int nd = 0; nd < 16; nd++) {
        int d = nd * 8 + tc * 2;
        size_t i0 = (((size_t)(b * Tt + t0) * Hh) + h) * DK + d;
        size_t i1 = (((size_t)(b * Tt + t0 + 8) * Hh) + h) * DK + d;
        *reinterpret_cast<__half2*>(g_ah + i0) =
            __halves2half2(__float2half(acc_o[nd][0] * inv0),
                           __float2half(acc_o[nd][1] * inv0));
        *reinterpret_cast<__half2*>(g_ah + i1) =
            __halves2half2(__float2half(acc_o[nd][2] * inv1),
                           __float2half(acc_o[nd][3] * inv1));
    }
}

// ---------------------------------------------------------------------------
extern "C" void kernel_launch(void* const* d_in, const int* in_sizes, int n_in,
                              void* d_out, int out_size) {
    const float* x  = (const float*)d_in[0];
    const float* ck = (const float*)d_in[1];
    const float* cv = (const float*)d_in[2];
    const float* Wq = (const float*)d_in[3];
    const float* Wk = (const float*)d_in[4];
    const float* Wv = (const float*)d_in[5];
    const float* Wo = (const float*)d_in[6];

    float* out  = (float*)d_out;
    float* Kout = out + (size_t)Bb * Tt * Cc;
    float* Vout = Kout + (size_t)Bb * Hh * SS * DK;

    cudaFuncSetAttribute(mm_hmma_kernel, cudaFuncAttributeMaxDynamicSharedMemorySize, MM_SMEM);
    cudaFuncSetAttribute(fa_kernel, cudaFuncAttributeMaxDynamicSharedMemorySize, FA_SMEM);

    convert7_kernel<<<28672, 256>>>((const float4*)x, (const float4*)Wq,
                                    (const float4*)Wk, (const float4*)Wv,
                                    (const float4*)Wo, (const float4*)ck,
                                    (const float4*)cv,
                                    (float4*)Kout, (float4*)Vout);
    mm_hmma_kernel<<<dim3(16, 16, 3), 256, MM_SMEM>>>(0, Kout, Vout, out);
    fa_kernel<<<dim3(8, 32), 256, FA_SMEM>>>();
    mm_hmma_kernel<<<dim3(16, 16, 1), 256, MM_SMEM>>>(1, Kout, Vout, out);
}